// round 8
// baseline (speedup 1.0000x reference)
#include <cuda_runtime.h>
#include <math.h>
#include <stdint.h>

#define BB   4
#define CC   384
#define HH   56
#define WW   56
#define HWW  3136
#define NTOK 12544
#define GG   12
#define GCH  32
#define KK2  9
#define OMC  324
#define HID  1536
#define EPSV 1e-5f

// ---------------- scratch (device globals; no allocation) ----------------
__device__ float g_xp [NTOK * CC];
__device__ float g_tn [NTOK * CC];
__device__ float g_val[NTOK * CC];
__device__ float g_om [NTOK * OMC];
__device__ float g_dcn[NTOK * CC];
__device__ float g_res[NTOK * CC];
__device__ float g_ln2[NTOK * CC];
__device__ float g_hid[NTOK * HID];
__device__ float g_fin[NTOK * CC];
__device__ float g_wm [CC * CC];   // om_w zero-padded to [384][384]

// ===================== helpers =====================
__device__ __forceinline__ uint32_t smem_u32(const void* p) {
    uint32_t a;
    asm("{ .reg .u64 t; cvta.to.shared.u64 t, %1; cvt.u32.u64 %0, t; }"
        : "=r"(a) : "l"(p));
    return a;
}
#define CP16(dst, src) \
    asm volatile("cp.async.ca.shared.global [%0], [%1], 16;" \
                 :: "r"(dst), "l"(src))
#define CP_COMMIT() asm volatile("cp.async.commit_group;")
#define CP_WAIT1()  asm volatile("cp.async.wait_group 1;")
#define CP_WAIT0()  asm volatile("cp.async.wait_group 0;")

#define MMA_TF32(d, a, b) \
    asm volatile("mma.sync.aligned.m16n8k8.row.col.f32.tf32.tf32.f32 " \
        "{%0,%1,%2,%3}, {%4,%5,%6,%7}, {%8,%9}, {%0,%1,%2,%3};" \
        : "+f"((d)[0]), "+f"((d)[1]), "+f"((d)[2]), "+f"((d)[3]) \
        : "r"((a)[0]), "r"((a)[1]), "r"((a)[2]), "r"((a)[3]), \
          "r"((b)[0]), "r"((b)[1]))

// ===================== mma.sync tf32 GEMM =====================
// Out[M,Nn] = A[M,K] @ W[K,Nw] (+epilogue). W consumed in native [K,Nw] layout.
// CTA tile 256x128, 8 warps (warp tile 64x64, 4m x 2n), K chunk 16,
// 3-stage cp.async pipeline. EPI: 0=+bias ; 1=+bias+GELU ; 2=+bias+Add
#define ASTR 20    // A smem row stride (words): read bank 20*g4+tg -> all 32
#define BSTR 136   // B smem row stride (words): read bank 8*tg+g4 -> all 32
#define A_FLOATS (256 * ASTR)
#define B_FLOATS (16 * BSTR)
#define GEMM_SMEM_BYTES ((3 * (A_FLOATS + B_FLOATS)) * 4)

template <int EPI>
__global__ __launch_bounds__(256, 1) void gemm_mma(
    const float* __restrict__ A, const float* __restrict__ W,
    const float* __restrict__ bias, const float* __restrict__ Add,
    float* __restrict__ Out, int Nn, int Nw, int K)
{
    extern __shared__ float dyn[];
    float* Asb = dyn;                       // [3][256][ASTR]
    float* Bsb = dyn + 3 * A_FLOATS;        // [3][16][BSTR]

    const int tid  = threadIdx.x;           // 256 threads
    const int lane = tid & 31, warp = tid >> 5;
    const int wm = (warp & 3) * 64, wn = (warp >> 2) * 64;
    const int g4 = lane >> 2, tg = lane & 3;
    const int m0 = blockIdx.x * 256, n0 = blockIdx.y * 128;

    const int brow = tid >> 4;              // 0..15  (B k-row)
    const int bcol = (tid & 15) * 8;        // B col base (8 floats per thread)

    float acc[4][8][4];
#pragma unroll
    for (int a = 0; a < 4; a++)
#pragma unroll
        for (int b = 0; b < 8; b++)
#pragma unroll
            for (int c = 0; c < 4; c++) acc[a][b][c] = 0.f;

    const int nkc = K >> 4;
    const float* srcA = A + (size_t)(m0 + tid) * K;
    const float* srcB = W + (size_t)brow * Nw + n0 + bcol;

#define ISSUE(kc, buf) do {                                                   \
        int _k0 = (kc) << 4;                                                  \
        float* _As = Asb + (buf) * A_FLOATS + tid * ASTR;                     \
        float* _Bs = Bsb + (buf) * B_FLOATS + brow * BSTR + bcol;             \
        CP16(smem_u32(_As),      srcA + _k0);                                 \
        CP16(smem_u32(_As + 4),  srcA + _k0 + 4);                             \
        CP16(smem_u32(_As + 8),  srcA + _k0 + 8);                             \
        CP16(smem_u32(_As + 12), srcA + _k0 + 12);                            \
        CP16(smem_u32(_Bs),      srcB + (size_t)_k0 * Nw);                    \
        CP16(smem_u32(_Bs + 4),  srcB + (size_t)_k0 * Nw + 4);                \
        CP_COMMIT();                                                          \
    } while (0)

    ISSUE(0, 0);
    ISSUE(1, 1);

    int buf = 0;
    for (int kc = 0; kc < nkc; kc++) {
        if (kc + 2 < nkc) CP_WAIT1(); else CP_WAIT0();
        __syncthreads();
        if (kc + 2 < nkc) {
            int nb = kc + 2 - ((kc + 2) / 3) * 3;
            ISSUE(kc + 2, nb);
        }
        const float* As = Asb + buf * A_FLOATS;
        const float* Bs = Bsb + buf * B_FLOATS;

#pragma unroll
        for (int s = 0; s < 2; s++) {
            const int ka = s * 8 + tg, kb = ka + 4;
            uint32_t af[4][4], bf[8][2];
#pragma unroll
            for (int mt = 0; mt < 4; mt++) {
                int m = wm + mt * 16 + g4;
                af[mt][0] = __float_as_uint(As[m * ASTR + ka]);
                af[mt][1] = __float_as_uint(As[(m + 8) * ASTR + ka]);
                af[mt][2] = __float_as_uint(As[m * ASTR + kb]);
                af[mt][3] = __float_as_uint(As[(m + 8) * ASTR + kb]);
            }
#pragma unroll
            for (int nt = 0; nt < 8; nt++) {
                int n = wn + nt * 8 + g4;
                bf[nt][0] = __float_as_uint(Bs[ka * BSTR + n]);
                bf[nt][1] = __float_as_uint(Bs[kb * BSTR + n]);
            }
#pragma unroll
            for (int mt = 0; mt < 4; mt++)
#pragma unroll
                for (int nt = 0; nt < 8; nt++)
                    MMA_TF32(acc[mt][nt], af[mt], bf[nt]);
        }
        buf++; if (buf == 3) buf = 0;
    }
#undef ISSUE

    // epilogue
#pragma unroll
    for (int mt = 0; mt < 4; mt++) {
        int row = m0 + wm + mt * 16 + g4;
#pragma unroll
        for (int nt = 0; nt < 8; nt++) {
            int col = n0 + wn + nt * 8 + tg * 2;
            if (col < Nn) {
                float b0 = __ldg(&bias[col]), b1 = __ldg(&bias[col + 1]);
                float v0 = acc[mt][nt][0] + b0;
                float v1 = acc[mt][nt][1] + b1;
                float v2 = acc[mt][nt][2] + b0;
                float v3 = acc[mt][nt][3] + b1;
                if (EPI == 1) {
                    v0 = 0.5f * v0 * (1.f + erff(v0 * 0.70710678118654752f));
                    v1 = 0.5f * v1 * (1.f + erff(v1 * 0.70710678118654752f));
                    v2 = 0.5f * v2 * (1.f + erff(v2 * 0.70710678118654752f));
                    v3 = 0.5f * v3 * (1.f + erff(v3 * 0.70710678118654752f));
                }
                if (EPI == 2) {
                    v0 += Add[(size_t)row * Nn + col];
                    v1 += Add[(size_t)row * Nn + col + 1];
                    v2 += Add[(size_t)(row + 8) * Nn + col];
                    v3 += Add[(size_t)(row + 8) * Nn + col + 1];
                }
                *reinterpret_cast<float2*>(Out + (size_t)row * Nn + col)       = make_float2(v0, v1);
                *reinterpret_cast<float2*>(Out + (size_t)(row + 8) * Nn + col) = make_float2(v2, v3);
            }
        }
    }
}

// ---------------- pad om_w [384][324] -> [384][384] (zeros) ---------------
__global__ void pad_om(const float* __restrict__ src, float* __restrict__ dst)
{
    int k = blockIdx.x, n = threadIdx.x;     // 384 x 384
    dst[k * CC + n] = (n < OMC) ? src[k * OMC + n] : 0.f;
}

// ---------------- LN1: transpose x + layernorm ----------------
__global__ void ln1_kernel(const float* __restrict__ x,
                           const float* __restrict__ gam,
                           const float* __restrict__ bet,
                           float* __restrict__ xp, float* __restrict__ tn)
{
    int warp = (blockIdx.x * blockDim.x + threadIdx.x) >> 5;
    if (warp >= NTOK) return;
    int lane = threadIdx.x & 31;
    int b  = warp / HWW;
    int hw = warp - b * HWW;
    const float* xb = x + (size_t)b * CC * HWW + hw;

    float v[12];
#pragma unroll
    for (int i = 0; i < 12; i++) v[i] = xb[(size_t)(lane + 32 * i) * HWW];
    float s = 0.f;
#pragma unroll
    for (int i = 0; i < 12; i++) s += v[i];
#pragma unroll
    for (int o = 16; o; o >>= 1) s += __shfl_xor_sync(0xffffffffu, s, o);
    float mu = s * (1.0f / CC);
    float q = 0.f;
#pragma unroll
    for (int i = 0; i < 12; i++) { float d = v[i] - mu; q += d * d; }
#pragma unroll
    for (int o = 16; o; o >>= 1) q += __shfl_xor_sync(0xffffffffu, q, o);
    float rs = rsqrtf(q * (1.0f / CC) + EPSV);
    size_t base = (size_t)warp * CC;
#pragma unroll
    for (int i = 0; i < 12; i++) {
        int c = lane + 32 * i;
        xp[base + c] = v[i];
        tn[base + c] = (v[i] - mu) * rs * gam[c] + bet[c];
    }
}

__global__ void ln2_kernel(const float* __restrict__ res,
                           const float* __restrict__ gam,
                           const float* __restrict__ bet,
                           float* __restrict__ outp)
{
    int warp = (blockIdx.x * blockDim.x + threadIdx.x) >> 5;
    if (warp >= NTOK) return;
    int lane = threadIdx.x & 31;
    size_t base = (size_t)warp * CC;
    float v[12];
#pragma unroll
    for (int i = 0; i < 12; i++) v[i] = res[base + lane + 32 * i];
    float s = 0.f;
#pragma unroll
    for (int i = 0; i < 12; i++) s += v[i];
#pragma unroll
    for (int o = 16; o; o >>= 1) s += __shfl_xor_sync(0xffffffffu, s, o);
    float mu = s * (1.0f / CC);
    float q = 0.f;
#pragma unroll
    for (int i = 0; i < 12; i++) { float d = v[i] - mu; q += d * d; }
#pragma unroll
    for (int o = 16; o; o >>= 1) q += __shfl_xor_sync(0xffffffffu, q, o);
    float rs = rsqrtf(q * (1.0f / CC) + EPSV);
#pragma unroll
    for (int i = 0; i < 12; i++) {
        int c = lane + 32 * i;
        outp[base + c] = (v[i] - mu) * rs * gam[c] + bet[c];
    }
}

// ---------------- DCNv4 sampling: one block per token, warp = group -------
__global__ __launch_bounds__(384) void dcn_kernel(
    const float* __restrict__ val,
    const float* __restrict__ om,
    float* __restrict__ outp)
{
    __shared__ float s_om[OMC];
    const int n = blockIdx.x;
    const int tid = threadIdx.x;
    if (tid < OMC) s_om[tid] = om[(size_t)n * OMC + tid];
    __syncthreads();

    const int g = tid >> 5, lane = tid & 31;
    const int b = n / HWW;
    const int hw = n - b * HWW;
    const int ii = hw / WW;
    const int jj = hw - ii * WW;

    const float* omb = s_om + g * 27;
    const float* vb  = val + b * (HWW * CC) + g * GCH + lane;

    float acc = 0.f;
#pragma unroll
    for (int k = 0; k < KK2; k++) {
        float dx = omb[2 * k];
        float dy = omb[2 * k + 1];
        float mk = omb[18 + k];
        float px = (float)jj + (float)(k % 3 - 1) + dx;
        float py = (float)ii + (float)(k / 3 - 1) + dy;
        float x0f = floorf(px), y0f = floorf(py);
        float tx = px - x0f, ty = py - y0f;
        int x0 = (int)x0f, y0 = (int)y0f;
        int x1 = x0 + 1,   y1 = y0 + 1;
        bool vx0 = (x0 >= 0) & (x0 < WW);
        bool vx1 = (x1 >= 0) & (x1 < WW);
        bool vy0 = (y0 >= 0) & (y0 < HH);
        bool vy1 = (y1 >= 0) & (y1 < HH);
        int row0 = y0 * (WW * CC), row1 = row0 + WW * CC;
        float v00 = (vy0 && vx0) ? __ldg(vb + row0 + x0 * CC) : 0.f;
        float v01 = (vy0 && vx1) ? __ldg(vb + row0 + x1 * CC) : 0.f;
        float v10 = (vy1 && vx0) ? __ldg(vb + row1 + x0 * CC) : 0.f;
        float v11 = (vy1 && vx1) ? __ldg(vb + row1 + x1 * CC) : 0.f;
        float top = v00 * (1.f - tx) + v01 * tx;
        float bot = v10 * (1.f - tx) + v11 * tx;
        acc += mk * (top * (1.f - ty) + bot * ty);
    }
    outp[n * CC + g * GCH + lane] = acc;
}

// ---------------- final transpose ----------------
__global__ void transpose_out(const float* __restrict__ fin,
                              float* __restrict__ outp)
{
    __shared__ float s[32][33];
    int b   = blockIdx.z;
    int hw0 = blockIdx.x * 32;
    int c0  = blockIdx.y * 32;
    int tx = threadIdx.x, ty = threadIdx.y;
#pragma unroll
    for (int r = 0; r < 4; r++) {
        int hw = hw0 + ty + 8 * r;
        s[ty + 8 * r][tx] = fin[(size_t)(b * HWW + hw) * CC + c0 + tx];
    }
    __syncthreads();
#pragma unroll
    for (int r = 0; r < 4; r++) {
        int c = c0 + ty + 8 * r;
        outp[(size_t)(b * CC + c) * HWW + hw0 + tx] = s[tx][ty + 8 * r];
    }
}

// --------------------------------------------------------------------------
extern "C" void kernel_launch(void* const* d_in, const int* in_sizes, int n_in,
                              void* d_out, int out_size)
{
    const float* x       = (const float*)d_in[0];
    const float* ln1_g   = (const float*)d_in[1];
    const float* ln1_b   = (const float*)d_in[2];
    const float* vproj_w = (const float*)d_in[3];
    const float* vproj_b = (const float*)d_in[4];
    const float* om_w    = (const float*)d_in[5];
    const float* om_b    = (const float*)d_in[6];
    const float* oproj_w = (const float*)d_in[7];
    const float* oproj_b = (const float*)d_in[8];
    const float* ln2_g   = (const float*)d_in[9];
    const float* ln2_b   = (const float*)d_in[10];
    const float* fc1_w   = (const float*)d_in[11];
    const float* fc1_b   = (const float*)d_in[12];
    const float* fc2_w   = (const float*)d_in[13];
    const float* fc2_b   = (const float*)d_in[14];
    float* outp = (float*)d_out;

    float *xp, *tn, *val, *om, *dcn, *res, *ln2o, *hid, *fin, *wm;
    cudaGetSymbolAddress((void**)&xp,  g_xp);
    cudaGetSymbolAddress((void**)&tn,  g_tn);
    cudaGetSymbolAddress((void**)&val, g_val);
    cudaGetSymbolAddress((void**)&om,  g_om);
    cudaGetSymbolAddress((void**)&dcn, g_dcn);
    cudaGetSymbolAddress((void**)&res, g_res);
    cudaGetSymbolAddress((void**)&ln2o, g_ln2);
    cudaGetSymbolAddress((void**)&hid, g_hid);
    cudaGetSymbolAddress((void**)&fin, g_fin);
    cudaGetSymbolAddress((void**)&wm,  g_wm);

    static int attr_done = 0;
    if (!attr_done) {
        cudaFuncSetAttribute(gemm_mma<0>, cudaFuncAttributeMaxDynamicSharedMemorySize, GEMM_SMEM_BYTES);
        cudaFuncSetAttribute(gemm_mma<1>, cudaFuncAttributeMaxDynamicSharedMemorySize, GEMM_SMEM_BYTES);
        cudaFuncSetAttribute(gemm_mma<2>, cudaFuncAttributeMaxDynamicSharedMemorySize, GEMM_SMEM_BYTES);
        attr_done = 1;
    }

    // pad om_w to [384][384]
    pad_om<<<CC, CC>>>(om_w, wm);
    // 1. transpose + LN1
    ln1_kernel<<<NTOK / 8, 256>>>(x, ln1_g, ln1_b, xp, tn);
    // 2. val = tn @ vproj_w + b
    gemm_mma<0><<<dim3(NTOK / 256, 3), 256, GEMM_SMEM_BYTES>>>(tn, vproj_w, vproj_b, nullptr, val, CC, CC, CC);
    // 3. om = tn @ om_w + b (padded W, Nn=324)
    gemm_mma<0><<<dim3(NTOK / 256, 3), 256, GEMM_SMEM_BYTES>>>(tn, wm, om_b, nullptr, om, OMC, CC, CC);
    // 4. DCN sampling
    dcn_kernel<<<NTOK, 384>>>(val, om, dcn);
    // 5. res = xp + dcn @ oproj_w + b
    gemm_mma<2><<<dim3(NTOK / 256, 3), 256, GEMM_SMEM_BYTES>>>(dcn, oproj_w, oproj_b, xp, res, CC, CC, CC);
    // 6. LN2
    ln2_kernel<<<NTOK / 8, 256>>>(res, ln2_g, ln2_b, ln2o);
    // 7. hid = gelu(ln2o @ fc1_w + b)
    gemm_mma<1><<<dim3(NTOK / 256, HID / 128), 256, GEMM_SMEM_BYTES>>>(ln2o, fc1_w, fc1_b, nullptr, hid, HID, HID, CC);
    // 8. fin = res + hid @ fc2_w + b
    gemm_mma<2><<<dim3(NTOK / 256, 3), 256, GEMM_SMEM_BYTES>>>(hid, fc2_w, fc2_b, res, fin, CC, CC, HID);
    // 9. transpose back
    transpose_out<<<dim3(HWW / 32, CC / 32, BB), dim3(32, 8)>>>(fin, outp);
}

// round 9
// speedup vs baseline: 1.2336x; 1.2336x over previous
#include <cuda_runtime.h>
#include <math.h>
#include <stdint.h>

#define BB   4
#define CC   384
#define HH   56
#define WW   56
#define HWW  3136
#define NTOK 12544
#define GG   12
#define GCH  32
#define KK2  9
#define OMC  324
#define HID  1536
#define EPSV 1e-5f

// ---------------- scratch (device globals; no allocation) ----------------
__device__ float g_xp [NTOK * CC];
__device__ float g_tn [NTOK * CC];
__device__ float g_val[NTOK * CC];
__device__ float g_om [NTOK * OMC];
__device__ float g_dcn[NTOK * CC];
__device__ float g_res[NTOK * CC];
__device__ float g_ln2[NTOK * CC];
__device__ float g_hid[NTOK * HID];
__device__ float g_fin[NTOK * CC];
// transposed weights [N,K] row-major
__device__ float g_wv [CC * CC];
__device__ float g_wo [CC * CC];
__device__ float g_w1 [HID * CC];
__device__ float g_w2 [CC * HID];
__device__ float g_wm [CC * CC];   // om_w^T; rows >= 324 stay zero (never written)

// ===================== helpers =====================
__device__ __forceinline__ uint32_t smem_u32(const void* p) {
    uint32_t a;
    asm("{ .reg .u64 t; cvta.to.shared.u64 t, %1; cvt.u32.u64 %0, t; }"
        : "=r"(a) : "l"(p));
    return a;
}
#define CP16(dst, src) \
    asm volatile("cp.async.ca.shared.global [%0], [%1], 16;" \
                 :: "r"(dst), "l"(src))
#define CP_COMMIT() asm volatile("cp.async.commit_group;")
#define CP_WAIT1()  asm volatile("cp.async.wait_group 1;")
#define CP_WAIT0()  asm volatile("cp.async.wait_group 0;")

#define MMA_TF32(d, a, b) \
    asm volatile("mma.sync.aligned.m16n8k8.row.col.f32.tf32.tf32.f32 " \
        "{%0,%1,%2,%3}, {%4,%5,%6,%7}, {%8,%9}, {%0,%1,%2,%3};" \
        : "+f"((d)[0]), "+f"((d)[1]), "+f"((d)[2]), "+f"((d)[3]) \
        : "r"((a)[0]), "r"((a)[1]), "r"((a)[2]), "r"((a)[3]), \
          "r"((b)[0]), "r"((b)[1]))

// ===================== mma.sync tf32 GEMM =====================
// Out[M,Nn] = A[M,K] @ Wt[Nt,K]^T.  Both A and B tiles in [row][k] smem layout,
// stride 20 words (conflict-free). CTA tile 128x128, 8 warps (64x32 warp tile),
// K chunk 16, 3-stage cp.async pipeline in dynamic smem.
// EPI: 0 = +bias ; 1 = +bias+GELU ; 2 = +bias+Add
#define TSTR 20
#define T_FLOATS (128 * TSTR)                      // one A or B tile
#define GEMM_SMEM_BYTES ((6 * T_FLOATS) * 4)       // 3 stages x (A+B) = 61440

template <int EPI>
__global__ __launch_bounds__(256, 2) void gemm_mma(
    const float* __restrict__ A, const float* __restrict__ Wt,
    const float* __restrict__ bias, const float* __restrict__ Add,
    float* __restrict__ Out, int Nn, int K)
{
    extern __shared__ float dyn[];
    float* Asb = dyn;                   // [3][128][TSTR]
    float* Bsb = dyn + 3 * T_FLOATS;    // [3][128][TSTR]

    const int tid  = threadIdx.x;       // 256 threads
    const int lane = tid & 31, warp = tid >> 5;
    const int wm = (warp >> 2) * 64, wn = (warp & 3) * 32;
    const int g4 = lane >> 2, tg = lane & 3;
    const int m0 = blockIdx.x * 128, n0 = blockIdx.y * 128;

    const int r  = tid >> 2;            // 0..63 (row pair index)
    const int kq = tid & 3;             // 16B slot within 16-wide k chunk

    float acc[4][4][4];
#pragma unroll
    for (int a = 0; a < 4; a++)
#pragma unroll
        for (int b = 0; b < 4; b++)
#pragma unroll
            for (int c = 0; c < 4; c++) acc[a][b][c] = 0.f;

    const int nkc = K >> 4;
    const float* srcA0 = A  + (size_t)(m0 + r) * K + kq * 4;
    const float* srcA1 = A  + (size_t)(m0 + r + 64) * K + kq * 4;
    const float* srcB0 = Wt + (size_t)(n0 + r) * K + kq * 4;
    const float* srcB1 = Wt + (size_t)(n0 + r + 64) * K + kq * 4;

#define ISSUE(kc, bufi) do {                                                  \
        int _k0 = (kc) << 4;                                                  \
        float* _As = Asb + (bufi) * T_FLOATS;                                 \
        float* _Bs = Bsb + (bufi) * T_FLOATS;                                 \
        CP16(smem_u32(_As + r * TSTR + kq * 4),        srcA0 + _k0);          \
        CP16(smem_u32(_As + (r + 64) * TSTR + kq * 4), srcA1 + _k0);          \
        CP16(smem_u32(_Bs + r * TSTR + kq * 4),        srcB0 + _k0);          \
        CP16(smem_u32(_Bs + (r + 64) * TSTR + kq * 4), srcB1 + _k0);          \
        CP_COMMIT();                                                          \
    } while (0)

    ISSUE(0, 0);
    ISSUE(1, 1);

    int buf = 0;
    for (int kc = 0; kc < nkc; kc++) {
        if (kc + 2 < nkc) CP_WAIT1(); else CP_WAIT0();
        __syncthreads();
        if (kc + 2 < nkc) {
            int nb = kc + 2 - ((kc + 2) / 3) * 3;
            ISSUE(kc + 2, nb);
        }
        const float* As = Asb + buf * T_FLOATS;
        const float* Bs = Bsb + buf * T_FLOATS;

#pragma unroll
        for (int s = 0; s < 2; s++) {
            const int ka = s * 8 + tg, kb = ka + 4;
            uint32_t af[4][4], bf[4][2];
#pragma unroll
            for (int mt = 0; mt < 4; mt++) {
                int m = wm + mt * 16 + g4;
                af[mt][0] = __float_as_uint(As[m * TSTR + ka]);
                af[mt][1] = __float_as_uint(As[(m + 8) * TSTR + ka]);
                af[mt][2] = __float_as_uint(As[m * TSTR + kb]);
                af[mt][3] = __float_as_uint(As[(m + 8) * TSTR + kb]);
            }
#pragma unroll
            for (int nt = 0; nt < 4; nt++) {
                int n = wn + nt * 8 + g4;
                bf[nt][0] = __float_as_uint(Bs[n * TSTR + ka]);
                bf[nt][1] = __float_as_uint(Bs[n * TSTR + kb]);
            }
#pragma unroll
            for (int mt = 0; mt < 4; mt++)
#pragma unroll
                for (int nt = 0; nt < 4; nt++)
                    MMA_TF32(acc[mt][nt], af[mt], bf[nt]);
        }
        buf++; if (buf == 3) buf = 0;
    }
#undef ISSUE

    // epilogue
#pragma unroll
    for (int mt = 0; mt < 4; mt++) {
        int row = m0 + wm + mt * 16 + g4;
#pragma unroll
        for (int nt = 0; nt < 4; nt++) {
            int col = n0 + wn + nt * 8 + tg * 2;
            if (col < Nn) {
                float b0 = __ldg(&bias[col]), b1 = __ldg(&bias[col + 1]);
                float v0 = acc[mt][nt][0] + b0;
                float v1 = acc[mt][nt][1] + b1;
                float v2 = acc[mt][nt][2] + b0;
                float v3 = acc[mt][nt][3] + b1;
                if (EPI == 1) {
                    v0 = 0.5f * v0 * (1.f + erff(v0 * 0.70710678118654752f));
                    v1 = 0.5f * v1 * (1.f + erff(v1 * 0.70710678118654752f));
                    v2 = 0.5f * v2 * (1.f + erff(v2 * 0.70710678118654752f));
                    v3 = 0.5f * v3 * (1.f + erff(v3 * 0.70710678118654752f));
                }
                if (EPI == 2) {
                    v0 += Add[(size_t)row * Nn + col];
                    v1 += Add[(size_t)row * Nn + col + 1];
                    v2 += Add[(size_t)(row + 8) * Nn + col];
                    v3 += Add[(size_t)(row + 8) * Nn + col + 1];
                }
                *reinterpret_cast<float2*>(Out + (size_t)row * Nn + col)       = make_float2(v0, v1);
                *reinterpret_cast<float2*>(Out + (size_t)(row + 8) * Nn + col) = make_float2(v2, v3);
            }
        }
    }
}

// ---------------- guarded weight transpose: src[K,N] -> dst[N,K] ----------
__global__ void transpose_w(const float* __restrict__ src, float* __restrict__ dst,
                            int Kdim, int Ndim)
{
    __shared__ float s[32][33];
    int n0 = blockIdx.x * 32, k0 = blockIdx.y * 32;
    int tx = threadIdx.x, ty = threadIdx.y;
#pragma unroll
    for (int r = 0; r < 4; r++) {
        int k = k0 + ty + 8 * r, n = n0 + tx;
        s[ty + 8 * r][tx] = (k < Kdim && n < Ndim) ? src[(size_t)k * Ndim + n] : 0.f;
    }
    __syncthreads();
#pragma unroll
    for (int r = 0; r < 4; r++) {
        int n = n0 + ty + 8 * r, k = k0 + tx;
        if (n < Ndim && k < Kdim)
            dst[(size_t)n * Kdim + k] = s[tx][ty + 8 * r];
    }
}

// ---------------- LN1: transpose x + layernorm ----------------
__global__ void ln1_kernel(const float* __restrict__ x,
                           const float* __restrict__ gam,
                           const float* __restrict__ bet,
                           float* __restrict__ xp, float* __restrict__ tn)
{
    int warp = (blockIdx.x * blockDim.x + threadIdx.x) >> 5;
    if (warp >= NTOK) return;
    int lane = threadIdx.x & 31;
    int b  = warp / HWW;
    int hw = warp - b * HWW;
    const float* xb = x + (size_t)b * CC * HWW + hw;

    float v[12];
#pragma unroll
    for (int i = 0; i < 12; i++) v[i] = xb[(size_t)(lane + 32 * i) * HWW];
    float s = 0.f;
#pragma unroll
    for (int i = 0; i < 12; i++) s += v[i];
#pragma unroll
    for (int o = 16; o; o >>= 1) s += __shfl_xor_sync(0xffffffffu, s, o);
    float mu = s * (1.0f / CC);
    float q = 0.f;
#pragma unroll
    for (int i = 0; i < 12; i++) { float d = v[i] - mu; q += d * d; }
#pragma unroll
    for (int o = 16; o; o >>= 1) q += __shfl_xor_sync(0xffffffffu, q, o);
    float rs = rsqrtf(q * (1.0f / CC) + EPSV);
    size_t base = (size_t)warp * CC;
#pragma unroll
    for (int i = 0; i < 12; i++) {
        int c = lane + 32 * i;
        xp[base + c] = v[i];
        tn[base + c] = (v[i] - mu) * rs * gam[c] + bet[c];
    }
}

__global__ void ln2_kernel(const float* __restrict__ res,
                           const float* __restrict__ gam,
                           const float* __restrict__ bet,
                           float* __restrict__ outp)
{
    int warp = (blockIdx.x * blockDim.x + threadIdx.x) >> 5;
    if (warp >= NTOK) return;
    int lane = threadIdx.x & 31;
    size_t base = (size_t)warp * CC;
    float v[12];
#pragma unroll
    for (int i = 0; i < 12; i++) v[i] = res[base + lane + 32 * i];
    float s = 0.f;
#pragma unroll
    for (int i = 0; i < 12; i++) s += v[i];
#pragma unroll
    for (int o = 16; o; o >>= 1) s += __shfl_xor_sync(0xffffffffu, s, o);
    float mu = s * (1.0f / CC);
    float q = 0.f;
#pragma unroll
    for (int i = 0; i < 12; i++) { float d = v[i] - mu; q += d * d; }
#pragma unroll
    for (int o = 16; o; o >>= 1) q += __shfl_xor_sync(0xffffffffu, q, o);
    float rs = rsqrtf(q * (1.0f / CC) + EPSV);
#pragma unroll
    for (int i = 0; i < 12; i++) {
        int c = lane + 32 * i;
        outp[base + c] = (v[i] - mu) * rs * gam[c] + bet[c];
    }
}

// ---------------- DCNv4 sampling: one block per token, warp = group -------
__global__ __launch_bounds__(384) void dcn_kernel(
    const float* __restrict__ val,
    const float* __restrict__ om,
    float* __restrict__ outp)
{
    __shared__ float s_om[OMC];
    const int n = blockIdx.x;
    const int tid = threadIdx.x;
    if (tid < OMC) s_om[tid] = om[(size_t)n * OMC + tid];
    __syncthreads();

    const int g = tid >> 5, lane = tid & 31;
    const int b = n / HWW;
    const int hw = n - b * HWW;
    const int ii = hw / WW;
    const int jj = hw - ii * WW;

    const float* omb = s_om + g * 27;
    const float* vb  = val + b * (HWW * CC) + g * GCH + lane;

    float acc = 0.f;
#pragma unroll
    for (int k = 0; k < KK2; k++) {
        float dx = omb[2 * k];
        float dy = omb[2 * k + 1];
        float mk = omb[18 + k];
        float px = (float)jj + (float)(k % 3 - 1) + dx;
        float py = (float)ii + (float)(k / 3 - 1) + dy;
        float x0f = floorf(px), y0f = floorf(py);
        float tx = px - x0f, ty = py - y0f;
        int x0 = (int)x0f, y0 = (int)y0f;
        int x1 = x0 + 1,   y1 = y0 + 1;
        bool vx0 = (x0 >= 0) & (x0 < WW);
        bool vx1 = (x1 >= 0) & (x1 < WW);
        bool vy0 = (y0 >= 0) & (y0 < HH);
        bool vy1 = (y1 >= 0) & (y1 < HH);
        int row0 = y0 * (WW * CC), row1 = row0 + WW * CC;
        float v00 = (vy0 && vx0) ? __ldg(vb + row0 + x0 * CC) : 0.f;
        float v01 = (vy0 && vx1) ? __ldg(vb + row0 + x1 * CC) : 0.f;
        float v10 = (vy1 && vx0) ? __ldg(vb + row1 + x0 * CC) : 0.f;
        float v11 = (vy1 && vx1) ? __ldg(vb + row1 + x1 * CC) : 0.f;
        float top = v00 * (1.f - tx) + v01 * tx;
        float bot = v10 * (1.f - tx) + v11 * tx;
        acc += mk * (top * (1.f - ty) + bot * ty);
    }
    outp[n * CC + g * GCH + lane] = acc;
}

// ---------------- final transpose ----------------
__global__ void transpose_out(const float* __restrict__ fin,
                              float* __restrict__ outp)
{
    __shared__ float s[32][33];
    int b   = blockIdx.z;
    int hw0 = blockIdx.x * 32;
    int c0  = blockIdx.y * 32;
    int tx = threadIdx.x, ty = threadIdx.y;
#pragma unroll
    for (int r = 0; r < 4; r++) {
        int hw = hw0 + ty + 8 * r;
        s[ty + 8 * r][tx] = fin[(size_t)(b * HWW + hw) * CC + c0 + tx];
    }
    __syncthreads();
#pragma unroll
    for (int r = 0; r < 4; r++) {
        int c = c0 + ty + 8 * r;
        outp[(size_t)(b * CC + c) * HWW + hw0 + tx] = s[tx][ty + 8 * r];
    }
}

// --------------------------------------------------------------------------
extern "C" void kernel_launch(void* const* d_in, const int* in_sizes, int n_in,
                              void* d_out, int out_size)
{
    const float* x       = (const float*)d_in[0];
    const float* ln1_g   = (const float*)d_in[1];
    const float* ln1_b   = (const float*)d_in[2];
    const float* vproj_w = (const float*)d_in[3];
    const float* vproj_b = (const float*)d_in[4];
    const float* om_w    = (const float*)d_in[5];
    const float* om_b    = (const float*)d_in[6];
    const float* oproj_w = (const float*)d_in[7];
    const float* oproj_b = (const float*)d_in[8];
    const float* ln2_g   = (const float*)d_in[9];
    const float* ln2_b   = (const float*)d_in[10];
    const float* fc1_w   = (const float*)d_in[11];
    const float* fc1_b   = (const float*)d_in[12];
    const float* fc2_w   = (const float*)d_in[13];
    const float* fc2_b   = (const float*)d_in[14];
    float* outp = (float*)d_out;

    float *xp, *tn, *val, *om, *dcn, *res, *ln2o, *hid, *fin;
    float *wv, *wo, *w1, *w2, *wm;
    cudaGetSymbolAddress((void**)&xp,  g_xp);
    cudaGetSymbolAddress((void**)&tn,  g_tn);
    cudaGetSymbolAddress((void**)&val, g_val);
    cudaGetSymbolAddress((void**)&om,  g_om);
    cudaGetSymbolAddress((void**)&dcn, g_dcn);
    cudaGetSymbolAddress((void**)&res, g_res);
    cudaGetSymbolAddress((void**)&ln2o, g_ln2);
    cudaGetSymbolAddress((void**)&hid, g_hid);
    cudaGetSymbolAddress((void**)&fin, g_fin);
    cudaGetSymbolAddress((void**)&wv,  g_wv);
    cudaGetSymbolAddress((void**)&wo,  g_wo);
    cudaGetSymbolAddress((void**)&w1,  g_w1);
    cudaGetSymbolAddress((void**)&w2,  g_w2);
    cudaGetSymbolAddress((void**)&wm,  g_wm);

    static int attr_done = 0;
    if (!attr_done) {
        cudaFuncSetAttribute(gemm_mma<0>, cudaFuncAttributeMaxDynamicSharedMemorySize, GEMM_SMEM_BYTES);
        cudaFuncSetAttribute(gemm_mma<1>, cudaFuncAttributeMaxDynamicSharedMemorySize, GEMM_SMEM_BYTES);
        cudaFuncSetAttribute(gemm_mma<2>, cudaFuncAttributeMaxDynamicSharedMemorySize, GEMM_SMEM_BYTES);
        attr_done = 1;
    }

    dim3 tb(32, 8);
    // weight transposes: [K,N] -> [N,K]  (wm rows >= 324 remain zero)
    transpose_w<<<dim3(CC / 32, CC / 32), tb>>>(vproj_w, wv, CC, CC);
    transpose_w<<<dim3(HID / 32, CC / 32), tb>>>(fc1_w, w1, CC, HID);
    transpose_w<<<dim3(CC / 32, CC / 32), tb>>>(oproj_w, wo, CC, CC);
    transpose_w<<<dim3(CC / 32, HID / 32), tb>>>(fc2_w, w2, HID, CC);
    transpose_w<<<dim3((OMC + 31) / 32, CC / 32), tb>>>(om_w, wm, CC, OMC);

    // 1. transpose + LN1
    ln1_kernel<<<NTOK / 8, 256>>>(x, ln1_g, ln1_b, xp, tn);
    // 2. val = tn @ vproj_w + b
    gemm_mma<0><<<dim3(NTOK / 128, 3), 256, GEMM_SMEM_BYTES>>>(tn, wv, vproj_b, nullptr, val, CC, CC);
    // 3. om = tn @ om_w + b (Nn=324; padded Wt rows are zero)
    gemm_mma<0><<<dim3(NTOK / 128, 3), 256, GEMM_SMEM_BYTES>>>(tn, wm, om_b, nullptr, om, OMC, CC);
    // 4. DCN sampling
    dcn_kernel<<<NTOK, 384>>>(val, om, dcn);
    // 5. res = xp + dcn @ oproj_w + b
    gemm_mma<2><<<dim3(NTOK / 128, 3), 256, GEMM_SMEM_BYTES>>>(dcn, wo, oproj_b, xp, res, CC, CC);
    // 6. LN2
    ln2_kernel<<<NTOK / 8, 256>>>(res, ln2_g, ln2_b, ln2o);
    // 7. hid = gelu(ln2o @ fc1_w + b)
    gemm_mma<1><<<dim3(NTOK / 128, HID / 128), 256, GEMM_SMEM_BYTES>>>(ln2o, w1, fc1_b, nullptr, hid, HID, CC);
    // 8. fin = res + hid @ fc2_w + b
    gemm_mma<2><<<dim3(NTOK / 128, 3), 256, GEMM_SMEM_BYTES>>>(hid, w2, fc2_b, res, fin, CC, HID);
    // 9. transpose back
    transpose_out<<<dim3(HWW / 32, CC / 32, BB), tb>>>(fin, outp);
}

// round 10
// speedup vs baseline: 1.2893x; 1.0451x over previous
#include <cuda_runtime.h>
#include <cuda_fp16.h>
#include <math.h>
#include <stdint.h>

#define BB   4
#define CC   384
#define HH   56
#define WW   56
#define HWW  3136
#define NTOK 12544
#define GG   12
#define GCH  32
#define KK2  9
#define OMC  324
#define HID  1536
#define EPSV 1e-5f

// ---------------- scratch (device globals; no allocation) ----------------
__device__ float  g_xp [NTOK * CC];
__device__ __half g_tn [NTOK * CC];
__device__ float  g_val[NTOK * CC];
__device__ float  g_om [NTOK * OMC];
__device__ __half g_dcn[NTOK * CC];
__device__ float  g_res[NTOK * CC];
__device__ __half g_ln2[NTOK * CC];
__device__ __half g_hid[NTOK * HID];
__device__ float  g_fin[NTOK * CC];
// transposed weights [N,K] row-major, fp16
__device__ __half g_wv [CC * CC];
__device__ __half g_wo [CC * CC];
__device__ __half g_w1 [HID * CC];
__device__ __half g_w2 [CC * HID];
__device__ __half g_wm [CC * CC];   // om_w^T; rows >= 324 stay zero (never written)

// ===================== helpers =====================
__device__ __forceinline__ uint32_t smem_u32(const void* p) {
    uint32_t a;
    asm("{ .reg .u64 t; cvta.to.shared.u64 t, %1; cvt.u32.u64 %0, t; }"
        : "=r"(a) : "l"(p));
    return a;
}
#define CP16(dst, src) \
    asm volatile("cp.async.ca.shared.global [%0], [%1], 16;" \
                 :: "r"(dst), "l"(src))
#define CP_COMMIT() asm volatile("cp.async.commit_group;")
#define CP_WAIT1()  asm volatile("cp.async.wait_group 1;")
#define CP_WAIT0()  asm volatile("cp.async.wait_group 0;")

#define MMA_F16(d, a, b) \
    asm volatile("mma.sync.aligned.m16n8k16.row.col.f32.f16.f16.f32 " \
        "{%0,%1,%2,%3}, {%4,%5,%6,%7}, {%8,%9}, {%0,%1,%2,%3};" \
        : "+f"((d)[0]), "+f"((d)[1]), "+f"((d)[2]), "+f"((d)[3]) \
        : "r"((a)[0]), "r"((a)[1]), "r"((a)[2]), "r"((a)[3]), \
          "r"((b)[0]), "r"((b)[1]))

// ===================== mma.sync fp16 GEMM (fp32 accum) =====================
// Out[M,Nn] = A[M,K] @ Wt[Nt,K]^T. A, Wt fp16; accumulate fp32.
// Tiles [row][k] in smem, 40-half row stride (word bank 20*g4+tg: all 32).
// CTA tile 128x128, 8 warps (64x32 warp tile), K chunk 32, 3-stage cp.async.
// EPI: 0 = +bias ; 1 = +bias+GELU ; 2 = +bias+Add.  OUTH: write half output.
#define TSTRH 40
#define T_HALFS (128 * TSTRH)                       // one A or B tile (5120 halfs)
#define GEMM_SMEM_BYTES ((6 * T_HALFS) * 2)         // 3 stages x (A+B) = 61440 B

template <int EPI, int OUTH>
__global__ __launch_bounds__(256, 2) void gemm_mma(
    const __half* __restrict__ A, const __half* __restrict__ Wt,
    const float* __restrict__ bias, const float* __restrict__ Add,
    void* __restrict__ OutV, int Nn, int K)
{
    extern __shared__ __half dynh[];
    __half* Asb = dynh;                  // [3][128][TSTRH]
    __half* Bsb = dynh + 3 * T_HALFS;    // [3][128][TSTRH]
    float*  OutF = (float*)OutV;
    __half* OutH = (__half*)OutV;

    const int tid  = threadIdx.x;        // 256 threads
    const int lane = tid & 31, warp = tid >> 5;
    const int wm = (warp >> 2) * 64, wn = (warp & 3) * 32;
    const int g4 = lane >> 2, tg = lane & 3;
    const int m0 = blockIdx.x * 128, n0 = blockIdx.y * 128;

    const int r = tid & 127;             // tile row
    const int q = tid >> 7;              // 0/1: handles 16B slots q and q+2

    float acc[4][4][4];
#pragma unroll
    for (int a = 0; a < 4; a++)
#pragma unroll
        for (int b = 0; b < 4; b++)
#pragma unroll
            for (int c = 0; c < 4; c++) acc[a][b][c] = 0.f;

    const int nkc = K >> 5;
    const __half* srcA = A  + (size_t)(m0 + r) * K + q * 8;
    const __half* srcB = Wt + (size_t)(n0 + r) * K + q * 8;

#define ISSUE(kc, bufi) do {                                                  \
        int _k0 = (kc) << 5;                                                  \
        __half* _As = Asb + (bufi) * T_HALFS + r * TSTRH + q * 8;             \
        __half* _Bs = Bsb + (bufi) * T_HALFS + r * TSTRH + q * 8;             \
        CP16(smem_u32(_As),      srcA + _k0);                                 \
        CP16(smem_u32(_As + 16), srcA + _k0 + 16);                            \
        CP16(smem_u32(_Bs),      srcB + _k0);                                 \
        CP16(smem_u32(_Bs + 16), srcB + _k0 + 16);                            \
        CP_COMMIT();                                                          \
    } while (0)

    ISSUE(0, 0);
    ISSUE(1, 1);

    int buf = 0;
    for (int kc = 0; kc < nkc; kc++) {
        if (kc + 2 < nkc) CP_WAIT1(); else CP_WAIT0();
        __syncthreads();
        if (kc + 2 < nkc) {
            int nb = kc + 2 - ((kc + 2) / 3) * 3;
            ISSUE(kc + 2, nb);
        }
        const __half* As = Asb + buf * T_HALFS;
        const __half* Bs = Bsb + buf * T_HALFS;

#pragma unroll
        for (int s = 0; s < 2; s++) {
            const int k2 = s * 16 + 2 * tg;
            uint32_t af[4][4], bf[4][2];
#pragma unroll
            for (int mt = 0; mt < 4; mt++) {
                int m = wm + mt * 16 + g4;
                af[mt][0] = *reinterpret_cast<const uint32_t*>(As + m * TSTRH + k2);
                af[mt][1] = *reinterpret_cast<const uint32_t*>(As + (m + 8) * TSTRH + k2);
                af[mt][2] = *reinterpret_cast<const uint32_t*>(As + m * TSTRH + k2 + 8);
                af[mt][3] = *reinterpret_cast<const uint32_t*>(As + (m + 8) * TSTRH + k2 + 8);
            }
#pragma unroll
            for (int nt = 0; nt < 4; nt++) {
                int n = wn + nt * 8 + g4;
                bf[nt][0] = *reinterpret_cast<const uint32_t*>(Bs + n * TSTRH + k2);
                bf[nt][1] = *reinterpret_cast<const uint32_t*>(Bs + n * TSTRH + k2 + 8);
            }
#pragma unroll
            for (int mt = 0; mt < 4; mt++)
#pragma unroll
                for (int nt = 0; nt < 4; nt++)
                    MMA_F16(acc[mt][nt], af[mt], bf[nt]);
        }
        buf++; if (buf == 3) buf = 0;
    }
#undef ISSUE

    // epilogue
#pragma unroll
    for (int mt = 0; mt < 4; mt++) {
        int row = m0 + wm + mt * 16 + g4;
#pragma unroll
        for (int nt = 0; nt < 4; nt++) {
            int col = n0 + wn + nt * 8 + tg * 2;
            if (col < Nn) {
                float b0 = __ldg(&bias[col]), b1 = __ldg(&bias[col + 1]);
                float v0 = acc[mt][nt][0] + b0;
                float v1 = acc[mt][nt][1] + b1;
                float v2 = acc[mt][nt][2] + b0;
                float v3 = acc[mt][nt][3] + b1;
                if (EPI == 1) {
                    v0 = 0.5f * v0 * (1.f + erff(v0 * 0.70710678118654752f));
                    v1 = 0.5f * v1 * (1.f + erff(v1 * 0.70710678118654752f));
                    v2 = 0.5f * v2 * (1.f + erff(v2 * 0.70710678118654752f));
                    v3 = 0.5f * v3 * (1.f + erff(v3 * 0.70710678118654752f));
                }
                if (EPI == 2) {
                    v0 += Add[(size_t)row * Nn + col];
                    v1 += Add[(size_t)row * Nn + col + 1];
                    v2 += Add[(size_t)(row + 8) * Nn + col];
                    v3 += Add[(size_t)(row + 8) * Nn + col + 1];
                }
                if (OUTH) {
                    *reinterpret_cast<__half2*>(OutH + (size_t)row * Nn + col)       = __floats2half2_rn(v0, v1);
                    *reinterpret_cast<__half2*>(OutH + (size_t)(row + 8) * Nn + col) = __floats2half2_rn(v2, v3);
                } else {
                    *reinterpret_cast<float2*>(OutF + (size_t)row * Nn + col)       = make_float2(v0, v1);
                    *reinterpret_cast<float2*>(OutF + (size_t)(row + 8) * Nn + col) = make_float2(v2, v3);
                }
            }
        }
    }
}

// ---------------- guarded weight transpose: src[K,N] f32 -> dst[N,K] f16 --
__global__ void transpose_w(const float* __restrict__ src, __half* __restrict__ dst,
                            int Kdim, int Ndim)
{
    __shared__ float s[32][33];
    int n0 = blockIdx.x * 32, k0 = blockIdx.y * 32;
    int tx = threadIdx.x, ty = threadIdx.y;
#pragma unroll
    for (int r = 0; r < 4; r++) {
        int k = k0 + ty + 8 * r, n = n0 + tx;
        s[ty + 8 * r][tx] = (k < Kdim && n < Ndim) ? src[(size_t)k * Ndim + n] : 0.f;
    }
    __syncthreads();
#pragma unroll
    for (int r = 0; r < 4; r++) {
        int n = n0 + ty + 8 * r, k = k0 + tx;
        if (n < Ndim && k < Kdim)
            dst[(size_t)n * Kdim + k] = __float2half(s[tx][ty + 8 * r]);
    }
}

// ---------------- LN1: transpose x + layernorm (tn -> fp16) ----------------
__global__ void ln1_kernel(const float* __restrict__ x,
                           const float* __restrict__ gam,
                           const float* __restrict__ bet,
                           float* __restrict__ xp, __half* __restrict__ tn)
{
    int warp = (blockIdx.x * blockDim.x + threadIdx.x) >> 5;
    if (warp >= NTOK) return;
    int lane = threadIdx.x & 31;
    int b  = warp / HWW;
    int hw = warp - b * HWW;
    const float* xb = x + (size_t)b * CC * HWW + hw;

    float v[12];
#pragma unroll
    for (int i = 0; i < 12; i++) v[i] = xb[(size_t)(lane + 32 * i) * HWW];
    float s = 0.f;
#pragma unroll
    for (int i = 0; i < 12; i++) s += v[i];
#pragma unroll
    for (int o = 16; o; o >>= 1) s += __shfl_xor_sync(0xffffffffu, s, o);
    float mu = s * (1.0f / CC);
    float q = 0.f;
#pragma unroll
    for (int i = 0; i < 12; i++) { float d = v[i] - mu; q += d * d; }
#pragma unroll
    for (int o = 16; o; o >>= 1) q += __shfl_xor_sync(0xffffffffu, q, o);
    float rs = rsqrtf(q * (1.0f / CC) + EPSV);
    size_t base = (size_t)warp * CC;
#pragma unroll
    for (int i = 0; i < 12; i++) {
        int c = lane + 32 * i;
        xp[base + c] = v[i];
        tn[base + c] = __float2half((v[i] - mu) * rs * gam[c] + bet[c]);
    }
}

// ---------------- LN2 (out -> fp16) ----------------
__global__ void ln2_kernel(const float* __restrict__ res,
                           const float* __restrict__ gam,
                           const float* __restrict__ bet,
                           __half* __restrict__ outp)
{
    int warp = (blockIdx.x * blockDim.x + threadIdx.x) >> 5;
    if (warp >= NTOK) return;
    int lane = threadIdx.x & 31;
    size_t base = (size_t)warp * CC;
    float v[12];
#pragma unroll
    for (int i = 0; i < 12; i++) v[i] = res[base + lane + 32 * i];
    float s = 0.f;
#pragma unroll
    for (int i = 0; i < 12; i++) s += v[i];
#pragma unroll
    for (int o = 16; o; o >>= 1) s += __shfl_xor_sync(0xffffffffu, s, o);
    float mu = s * (1.0f / CC);
    float q = 0.f;
#pragma unroll
    for (int i = 0; i < 12; i++) { float d = v[i] - mu; q += d * d; }
#pragma unroll
    for (int o = 16; o; o >>= 1) q += __shfl_xor_sync(0xffffffffu, q, o);
    float rs = rsqrtf(q * (1.0f / CC) + EPSV);
#pragma unroll
    for (int i = 0; i < 12; i++) {
        int c = lane + 32 * i;
        outp[base + c] = __float2half((v[i] - mu) * rs * gam[c] + bet[c]);
    }
}

// ---------------- DCNv4 sampling (out -> fp16) ----------------
__global__ __launch_bounds__(384) void dcn_kernel(
    const float* __restrict__ val,
    const float* __restrict__ om,
    __half* __restrict__ outp)
{
    __shared__ float s_om[OMC];
    const int n = blockIdx.x;
    const int tid = threadIdx.x;
    if (tid < OMC) s_om[tid] = om[(size_t)n * OMC + tid];
    __syncthreads();

    const int g = tid >> 5, lane = tid & 31;
    const int b = n / HWW;
    const int hw = n - b * HWW;
    const int ii = hw / WW;
    const int jj = hw - ii * WW;

    const float* omb = s_om + g * 27;
    const float* vb  = val + b * (HWW * CC) + g * GCH + lane;

    float acc = 0.f;
#pragma unroll
    for (int k = 0; k < KK2; k++) {
        float dx = omb[2 * k];
        float dy = omb[2 * k + 1];
        float mk = omb[18 + k];
        float px = (float)jj + (float)(k % 3 - 1) + dx;
        float py = (float)ii + (float)(k / 3 - 1) + dy;
        float x0f = floorf(px), y0f = floorf(py);
        float tx = px - x0f, ty = py - y0f;
        int x0 = (int)x0f, y0 = (int)y0f;
        int x1 = x0 + 1,   y1 = y0 + 1;
        bool vx0 = (x0 >= 0) & (x0 < WW);
        bool vx1 = (x1 >= 0) & (x1 < WW);
        bool vy0 = (y0 >= 0) & (y0 < HH);
        bool vy1 = (y1 >= 0) & (y1 < HH);
        int row0 = y0 * (WW * CC), row1 = row0 + WW * CC;
        float v00 = (vy0 && vx0) ? __ldg(vb + row0 + x0 * CC) : 0.f;
        float v01 = (vy0 && vx1) ? __ldg(vb + row0 + x1 * CC) : 0.f;
        float v10 = (vy1 && vx0) ? __ldg(vb + row1 + x0 * CC) : 0.f;
        float v11 = (vy1 && vx1) ? __ldg(vb + row1 + x1 * CC) : 0.f;
        float top = v00 * (1.f - tx) + v01 * tx;
        float bot = v10 * (1.f - tx) + v11 * tx;
        acc += mk * (top * (1.f - ty) + bot * ty);
    }
    outp[n * CC + g * GCH + lane] = __float2half(acc);
}

// ---------------- final transpose ----------------
__global__ void transpose_out(const float* __restrict__ fin,
                              float* __restrict__ outp)
{
    __shared__ float s[32][33];
    int b   = blockIdx.z;
    int hw0 = blockIdx.x * 32;
    int c0  = blockIdx.y * 32;
    int tx = threadIdx.x, ty = threadIdx.y;
#pragma unroll
    for (int r = 0; r < 4; r++) {
        int hw = hw0 + ty + 8 * r;
        s[ty + 8 * r][tx] = fin[(size_t)(b * HWW + hw) * CC + c0 + tx];
    }
    __syncthreads();
#pragma unroll
    for (int r = 0; r < 4; r++) {
        int c = c0 + ty + 8 * r;
        outp[(size_t)(b * CC + c) * HWW + hw0 + tx] = s[tx][ty + 8 * r];
    }
}

// --------------------------------------------------------------------------
extern "C" void kernel_launch(void* const* d_in, const int* in_sizes, int n_in,
                              void* d_out, int out_size)
{
    const float* x       = (const float*)d_in[0];
    const float* ln1_g   = (const float*)d_in[1];
    const float* ln1_b   = (const float*)d_in[2];
    const float* vproj_w = (const float*)d_in[3];
    const float* vproj_b = (const float*)d_in[4];
    const float* om_w    = (const float*)d_in[5];
    const float* om_b    = (const float*)d_in[6];
    const float* oproj_w = (const float*)d_in[7];
    const float* oproj_b = (const float*)d_in[8];
    const float* ln2_g   = (const float*)d_in[9];
    const float* ln2_b   = (const float*)d_in[10];
    const float* fc1_w   = (const float*)d_in[11];
    const float* fc1_b   = (const float*)d_in[12];
    const float* fc2_w   = (const float*)d_in[13];
    const float* fc2_b   = (const float*)d_in[14];
    float* outp = (float*)d_out;

    float *xp, *val, *om, *res, *fin;
    __half *tn, *dcn, *ln2o, *hid, *wv, *wo, *w1, *w2, *wm;
    cudaGetSymbolAddress((void**)&xp,  g_xp);
    cudaGetSymbolAddress((void**)&tn,  g_tn);
    cudaGetSymbolAddress((void**)&val, g_val);
    cudaGetSymbolAddress((void**)&om,  g_om);
    cudaGetSymbolAddress((void**)&dcn, g_dcn);
    cudaGetSymbolAddress((void**)&res, g_res);
    cudaGetSymbolAddress((void**)&ln2o, g_ln2);
    cudaGetSymbolAddress((void**)&hid, g_hid);
    cudaGetSymbolAddress((void**)&fin, g_fin);
    cudaGetSymbolAddress((void**)&wv,  g_wv);
    cudaGetSymbolAddress((void**)&wo,  g_wo);
    cudaGetSymbolAddress((void**)&w1,  g_w1);
    cudaGetSymbolAddress((void**)&w2,  g_w2);
    cudaGetSymbolAddress((void**)&wm,  g_wm);

    static int attr_done = 0;
    if (!attr_done) {
        cudaFuncSetAttribute(gemm_mma<0, 0>, cudaFuncAttributeMaxDynamicSharedMemorySize, GEMM_SMEM_BYTES);
        cudaFuncSetAttribute(gemm_mma<1, 1>, cudaFuncAttributeMaxDynamicSharedMemorySize, GEMM_SMEM_BYTES);
        cudaFuncSetAttribute(gemm_mma<2, 0>, cudaFuncAttributeMaxDynamicSharedMemorySize, GEMM_SMEM_BYTES);
        attr_done = 1;
    }

    dim3 tb(32, 8);
    // weight transposes: [K,N] f32 -> [N,K] f16 (wm rows >= 324 remain zero)
    transpose_w<<<dim3(CC / 32, CC / 32), tb>>>(vproj_w, wv, CC, CC);
    transpose_w<<<dim3(HID / 32, CC / 32), tb>>>(fc1_w, w1, CC, HID);
    transpose_w<<<dim3(CC / 32, CC / 32), tb>>>(oproj_w, wo, CC, CC);
    transpose_w<<<dim3(CC / 32, HID / 32), tb>>>(fc2_w, w2, HID, CC);
    transpose_w<<<dim3((OMC + 31) / 32, CC / 32), tb>>>(om_w, wm, CC, OMC);

    // 1. transpose + LN1
    ln1_kernel<<<NTOK / 8, 256>>>(x, ln1_g, ln1_b, xp, tn);
    // 2. val = tn @ vproj_w + b   (fp32 out)
    gemm_mma<0, 0><<<dim3(NTOK / 128, 3), 256, GEMM_SMEM_BYTES>>>(tn, wv, vproj_b, nullptr, val, CC, CC);
    // 3. om = tn @ om_w + b       (Nn=324, fp32 out)
    gemm_mma<0, 0><<<dim3(NTOK / 128, 3), 256, GEMM_SMEM_BYTES>>>(tn, wm, om_b, nullptr, om, OMC, CC);
    // 4. DCN sampling (fp16 out)
    dcn_kernel<<<NTOK, 384>>>(val, om, dcn);
    // 5. res = xp + dcn @ oproj_w + b  (fp32 out)
    gemm_mma<2, 0><<<dim3(NTOK / 128, 3), 256, GEMM_SMEM_BYTES>>>(dcn, wo, oproj_b, xp, res, CC, CC);
    // 6. LN2 (fp16 out)
    ln2_kernel<<<NTOK / 8, 256>>>(res, ln2_g, ln2_b, ln2o);
    // 7. hid = gelu(ln2o @ fc1_w + b)  (fp16 out)
    gemm_mma<1, 1><<<dim3(NTOK / 128, HID / 128), 256, GEMM_SMEM_BYTES>>>(ln2o, w1, fc1_b, nullptr, hid, HID, CC);
    // 8. fin = res + hid @ fc2_w + b   (fp32 out)
    gemm_mma<2, 0><<<dim3(NTOK / 128, 3), 256, GEMM_SMEM_BYTES>>>(hid, w2, fc2_b, res, fin, CC, HID);
    // 9. transpose back
    transpose_out<<<dim3(HWW / 32, CC / 32, BB), tb>>>(fin, outp);
}

// round 11
// speedup vs baseline: 1.4095x; 1.0933x over previous
#include <cuda_runtime.h>
#include <cuda_fp16.h>
#include <math.h>
#include <stdint.h>

#define BB   4
#define CC   384
#define HH   56
#define WW   56
#define HWW  3136
#define NTOK 12544
#define GG   12
#define GCH  32
#define KK2  9
#define OMC  324
#define HID  1536
#define EPSV 1e-5f

// ---------------- scratch (device globals; no allocation) ----------------
__device__ float  g_xp [NTOK * CC];
__device__ __half g_tn [NTOK * CC];
__device__ __half g_val[NTOK * CC];
__device__ float  g_om [NTOK * OMC];
__device__ __half g_dcn[NTOK * CC];
__device__ float  g_res[NTOK * CC];
__device__ __half g_ln2[NTOK * CC];
__device__ __half g_hid[NTOK * HID];
__device__ float  g_fin[NTOK * CC];
// transposed weights [N,K] row-major, fp16
__device__ __half g_wv [CC * CC];
__device__ __half g_wo [CC * CC];
__device__ __half g_w1 [HID * CC];
__device__ __half g_w2 [CC * HID];
__device__ __half g_wm [CC * CC];   // om_w^T; rows >= 324 stay zero (never written)

// ===================== helpers =====================
__device__ __forceinline__ uint32_t smem_u32(const void* p) {
    uint32_t a;
    asm("{ .reg .u64 t; cvta.to.shared.u64 t, %1; cvt.u32.u64 %0, t; }"
        : "=r"(a) : "l"(p));
    return a;
}
#define CP16(dst, src) \
    asm volatile("cp.async.ca.shared.global [%0], [%1], 16;" \
                 :: "r"(dst), "l"(src))
#define CP_COMMIT() asm volatile("cp.async.commit_group;")
#define CP_WAIT1()  asm volatile("cp.async.wait_group 1;")
#define CP_WAIT0()  asm volatile("cp.async.wait_group 0;")

#define MMA_F16(d, a, b) \
    asm volatile("mma.sync.aligned.m16n8k16.row.col.f32.f16.f16.f32 " \
        "{%0,%1,%2,%3}, {%4,%5,%6,%7}, {%8,%9}, {%0,%1,%2,%3};" \
        : "+f"((d)[0]), "+f"((d)[1]), "+f"((d)[2]), "+f"((d)[3]) \
        : "r"((a)[0]), "r"((a)[1]), "r"((a)[2]), "r"((a)[3]), \
          "r"((b)[0]), "r"((b)[1]))

#define LDSM4(r0, r1, r2, r3, addr) \
    asm volatile("ldmatrix.sync.aligned.m8n8.x4.shared.b16 {%0,%1,%2,%3}, [%4];" \
        : "=r"(r0), "=r"(r1), "=r"(r2), "=r"(r3) : "r"(addr))

// ===================== mma.sync fp16 GEMM (fp32 accum) =====================
// Out[M,Nn] = A[M,K] @ Wt[Nt,K]^T. A, Wt fp16; accumulate fp32.
// Tiles [row][k] smem, 40-half stride. Fragments via ldmatrix.x4.
// CTA tile 128x128, 8 warps (64x32), K chunk 32, 3-stage cp.async.
// EPI: 0 = +bias ; 1 = +bias+GELU ; 2 = +bias+Add.  OUTH: write half output.
#define TSTRH 40
#define T_HALFS (128 * TSTRH)
#define GEMM_SMEM_BYTES ((6 * T_HALFS) * 2)         // 61440 B

template <int EPI, int OUTH>
__global__ __launch_bounds__(256, 2) void gemm_mma(
    const __half* __restrict__ A, const __half* __restrict__ Wt,
    const float* __restrict__ bias, const float* __restrict__ Add,
    void* __restrict__ OutV, int Nn, int K)
{
    extern __shared__ __half dynh[];
    __half* Asb = dynh;                  // [3][128][TSTRH]
    __half* Bsb = dynh + 3 * T_HALFS;    // [3][128][TSTRH]
    float*  OutF = (float*)OutV;
    __half* OutH = (__half*)OutV;

    const int tid  = threadIdx.x;        // 256 threads
    const int lane = tid & 31, warp = tid >> 5;
    const int wm = (warp >> 2) * 64, wn = (warp & 3) * 32;
    const int g4 = lane >> 2, tg = lane & 3;
    const int m0 = blockIdx.x * 128, n0 = blockIdx.y * 128;

    // ldmatrix per-lane source coords
    const int lrow = lane & 15;              // A row within 16-tile
    const int lkof = (lane >> 4) * 8;        // A k offset (0 or 8)
    const int bnof = (lane >> 4) * 8 + (lane & 7);   // B n within 16-pair
    const int bkof = ((lane >> 3) & 1) * 8;          // B k offset

    const int r = tid & 127;             // cp.async tile row
    const int q = tid >> 7;              // 0/1

    float acc[4][4][4];
#pragma unroll
    for (int a = 0; a < 4; a++)
#pragma unroll
        for (int b = 0; b < 4; b++)
#pragma unroll
            for (int c = 0; c < 4; c++) acc[a][b][c] = 0.f;

    const int nkc = K >> 5;
    const __half* srcA = A  + (size_t)(m0 + r) * K + q * 8;
    const __half* srcB = Wt + (size_t)(n0 + r) * K + q * 8;

#define ISSUE(kc, bufi) do {                                                  \
        int _k0 = (kc) << 5;                                                  \
        __half* _As = Asb + (bufi) * T_HALFS + r * TSTRH + q * 8;             \
        __half* _Bs = Bsb + (bufi) * T_HALFS + r * TSTRH + q * 8;             \
        CP16(smem_u32(_As),      srcA + _k0);                                 \
        CP16(smem_u32(_As + 16), srcA + _k0 + 16);                            \
        CP16(smem_u32(_Bs),      srcB + _k0);                                 \
        CP16(smem_u32(_Bs + 16), srcB + _k0 + 16);                            \
        CP_COMMIT();                                                          \
    } while (0)

    ISSUE(0, 0);
    ISSUE(1, 1);

    int buf = 0;
    for (int kc = 0; kc < nkc; kc++) {
        if (kc + 2 < nkc) CP_WAIT1(); else CP_WAIT0();
        __syncthreads();
        if (kc + 2 < nkc) {
            int nb = kc + 2 - ((kc + 2) / 3) * 3;
            ISSUE(kc + 2, nb);
        }
        const __half* As = Asb + buf * T_HALFS;
        const __half* Bs = Bsb + buf * T_HALFS;

#pragma unroll
        for (int s = 0; s < 2; s++) {
            uint32_t af[4][4], bf[4][2];
#pragma unroll
            for (int mt = 0; mt < 4; mt++) {
                uint32_t ad = smem_u32(As + (wm + mt * 16 + lrow) * TSTRH + s * 16 + lkof);
                LDSM4(af[mt][0], af[mt][1], af[mt][2], af[mt][3], ad);
            }
#pragma unroll
            for (int p = 0; p < 2; p++) {
                uint32_t ad = smem_u32(Bs + (wn + p * 16 + bnof) * TSTRH + s * 16 + bkof);
                LDSM4(bf[2 * p][0], bf[2 * p][1], bf[2 * p + 1][0], bf[2 * p + 1][1], ad);
            }
#pragma unroll
            for (int mt = 0; mt < 4; mt++)
#pragma unroll
                for (int nt = 0; nt < 4; nt++)
                    MMA_F16(acc[mt][nt], af[mt], bf[nt]);
        }
        buf++; if (buf == 3) buf = 0;
    }
#undef ISSUE

    // epilogue
#pragma unroll
    for (int mt = 0; mt < 4; mt++) {
        int row = m0 + wm + mt * 16 + g4;
#pragma unroll
        for (int nt = 0; nt < 4; nt++) {
            int col = n0 + wn + nt * 8 + tg * 2;
            if (col < Nn) {
                float b0 = __ldg(&bias[col]), b1 = __ldg(&bias[col + 1]);
                float v0 = acc[mt][nt][0] + b0;
                float v1 = acc[mt][nt][1] + b1;
                float v2 = acc[mt][nt][2] + b0;
                float v3 = acc[mt][nt][3] + b1;
                if (EPI == 1) {
                    v0 = 0.5f * v0 * (1.f + erff(v0 * 0.70710678118654752f));
                    v1 = 0.5f * v1 * (1.f + erff(v1 * 0.70710678118654752f));
                    v2 = 0.5f * v2 * (1.f + erff(v2 * 0.70710678118654752f));
                    v3 = 0.5f * v3 * (1.f + erff(v3 * 0.70710678118654752f));
                }
                if (EPI == 2) {
                    v0 += Add[(size_t)row * Nn + col];
                    v1 += Add[(size_t)row * Nn + col + 1];
                    v2 += Add[(size_t)(row + 8) * Nn + col];
                    v3 += Add[(size_t)(row + 8) * Nn + col + 1];
                }
                if (OUTH) {
                    *reinterpret_cast<__half2*>(OutH + (size_t)row * Nn + col)       = __floats2half2_rn(v0, v1);
                    *reinterpret_cast<__half2*>(OutH + (size_t)(row + 8) * Nn + col) = __floats2half2_rn(v2, v3);
                } else {
                    *reinterpret_cast<float2*>(OutF + (size_t)row * Nn + col)       = make_float2(v0, v1);
                    *reinterpret_cast<float2*>(OutF + (size_t)(row + 8) * Nn + col) = make_float2(v2, v3);
                }
            }
        }
    }
}

// ---------------- guarded weight transpose: src[K,N] f32 -> dst[N,K] f16 --
__global__ void transpose_w(const float* __restrict__ src, __half* __restrict__ dst,
                            int Kdim, int Ndim)
{
    __shared__ float s[32][33];
    int n0 = blockIdx.x * 32, k0 = blockIdx.y * 32;
    int tx = threadIdx.x, ty = threadIdx.y;
#pragma unroll
    for (int r = 0; r < 4; r++) {
        int k = k0 + ty + 8 * r, n = n0 + tx;
        s[ty + 8 * r][tx] = (k < Kdim && n < Ndim) ? src[(size_t)k * Ndim + n] : 0.f;
    }
    __syncthreads();
#pragma unroll
    for (int r = 0; r < 4; r++) {
        int n = n0 + ty + 8 * r, k = k0 + tx;
        if (n < Ndim && k < Kdim)
            dst[(size_t)n * Kdim + k] = __float2half(s[tx][ty + 8 * r]);
    }
}

// ---------------- LN1: transpose x + layernorm (tn -> fp16) ----------------
__global__ void ln1_kernel(const float* __restrict__ x,
                           const float* __restrict__ gam,
                           const float* __restrict__ bet,
                           float* __restrict__ xp, __half* __restrict__ tn)
{
    int warp = (blockIdx.x * blockDim.x + threadIdx.x) >> 5;
    if (warp >= NTOK) return;
    int lane = threadIdx.x & 31;
    int b  = warp / HWW;
    int hw = warp - b * HWW;
    const float* xb = x + (size_t)b * CC * HWW + hw;

    float v[12];
#pragma unroll
    for (int i = 0; i < 12; i++) v[i] = xb[(size_t)(lane + 32 * i) * HWW];
    float s = 0.f;
#pragma unroll
    for (int i = 0; i < 12; i++) s += v[i];
#pragma unroll
    for (int o = 16; o; o >>= 1) s += __shfl_xor_sync(0xffffffffu, s, o);
    float mu = s * (1.0f / CC);
    float q = 0.f;
#pragma unroll
    for (int i = 0; i < 12; i++) { float d = v[i] - mu; q += d * d; }
#pragma unroll
    for (int o = 16; o; o >>= 1) q += __shfl_xor_sync(0xffffffffu, q, o);
    float rs = rsqrtf(q * (1.0f / CC) + EPSV);
    size_t base = (size_t)warp * CC;
#pragma unroll
    for (int i = 0; i < 12; i++) {
        int c = lane + 32 * i;
        xp[base + c] = v[i];
        tn[base + c] = __float2half((v[i] - mu) * rs * gam[c] + bet[c]);
    }
}

// ---------------- LN2 (out -> fp16) ----------------
__global__ void ln2_kernel(const float* __restrict__ res,
                           const float* __restrict__ gam,
                           const float* __restrict__ bet,
                           __half* __restrict__ outp)
{
    int warp = (blockIdx.x * blockDim.x + threadIdx.x) >> 5;
    if (warp >= NTOK) return;
    int lane = threadIdx.x & 31;
    size_t base = (size_t)warp * CC;
    float v[12];
#pragma unroll
    for (int i = 0; i < 12; i++) v[i] = res[base + lane + 32 * i];
    float s = 0.f;
#pragma unroll
    for (int i = 0; i < 12; i++) s += v[i];
#pragma unroll
    for (int o = 16; o; o >>= 1) s += __shfl_xor_sync(0xffffffffu, s, o);
    float mu = s * (1.0f / CC);
    float q = 0.f;
#pragma unroll
    for (int i = 0; i < 12; i++) { float d = v[i] - mu; q += d * d; }
#pragma unroll
    for (int o = 16; o; o >>= 1) q += __shfl_xor_sync(0xffffffffu, q, o);
    float rs = rsqrtf(q * (1.0f / CC) + EPSV);
#pragma unroll
    for (int i = 0; i < 12; i++) {
        int c = lane + 32 * i;
        outp[base + c] = __float2half((v[i] - mu) * rs * gam[c] + bet[c]);
    }
}

// ---------------- DCNv4 sampling (val fp16 in, fp16 out) ----------------
__global__ __launch_bounds__(384) void dcn_kernel(
    const __half* __restrict__ val,
    const float* __restrict__ om,
    __half* __restrict__ outp)
{
    __shared__ float s_om[OMC];
    const int n = blockIdx.x;
    const int tid = threadIdx.x;
    if (tid < OMC) s_om[tid] = om[(size_t)n * OMC + tid];
    __syncthreads();

    const int g = tid >> 5, lane = tid & 31;
    const int b = n / HWW;
    const int hw = n - b * HWW;
    const int ii = hw / WW;
    const int jj = hw - ii * WW;

    const float* omb = s_om + g * 27;
    const __half* vb = val + b * (HWW * CC) + g * GCH + lane;

    float acc = 0.f;
#pragma unroll
    for (int k = 0; k < KK2; k++) {
        float dx = omb[2 * k];
        float dy = omb[2 * k + 1];
        float mk = omb[18 + k];
        float px = (float)jj + (float)(k % 3 - 1) + dx;
        float py = (float)ii + (float)(k / 3 - 1) + dy;
        float x0f = floorf(px), y0f = floorf(py);
        float tx = px - x0f, ty = py - y0f;
        int x0 = (int)x0f, y0 = (int)y0f;
        int x1 = x0 + 1,   y1 = y0 + 1;
        bool vx0 = (x0 >= 0) & (x0 < WW);
        bool vx1 = (x1 >= 0) & (x1 < WW);
        bool vy0 = (y0 >= 0) & (y0 < HH);
        bool vy1 = (y1 >= 0) & (y1 < HH);
        int row0 = y0 * (WW * CC), row1 = row0 + WW * CC;
        float v00 = (vy0 && vx0) ? __half2float(__ldg(vb + row0 + x0 * CC)) : 0.f;
        float v01 = (vy0 && vx1) ? __half2float(__ldg(vb + row0 + x1 * CC)) : 0.f;
        float v10 = (vy1 && vx0) ? __half2float(__ldg(vb + row1 + x0 * CC)) : 0.f;
        float v11 = (vy1 && vx1) ? __half2float(__ldg(vb + row1 + x1 * CC)) : 0.f;
        float top = v00 * (1.f - tx) + v01 * tx;
        float bot = v10 * (1.f - tx) + v11 * tx;
        acc += mk * (top * (1.f - ty) + bot * ty);
    }
    outp[n * CC + g * GCH + lane] = __float2half(acc);
}

// ---------------- final transpose ----------------
__global__ void transpose_out(const float* __restrict__ fin,
                              float* __restrict__ outp)
{
    __shared__ float s[32][33];
    int b   = blockIdx.z;
    int hw0 = blockIdx.x * 32;
    int c0  = blockIdx.y * 32;
    int tx = threadIdx.x, ty = threadIdx.y;
#pragma unroll
    for (int r = 0; r < 4; r++) {
        int hw = hw0 + ty + 8 * r;
        s[ty + 8 * r][tx] = fin[(size_t)(b * HWW + hw) * CC + c0 + tx];
    }
    __syncthreads();
#pragma unroll
    for (int r = 0; r < 4; r++) {
        int c = c0 + ty + 8 * r;
        outp[(size_t)(b * CC + c) * HWW + hw0 + tx] = s[tx][ty + 8 * r];
    }
}

// --------------------------------------------------------------------------
extern "C" void kernel_launch(void* const* d_in, const int* in_sizes, int n_in,
                              void* d_out, int out_size)
{
    const float* x       = (const float*)d_in[0];
    const float* ln1_g   = (const float*)d_in[1];
    const float* ln1_b   = (const float*)d_in[2];
    const float* vproj_w = (const float*)d_in[3];
    const float* vproj_b = (const float*)d_in[4];
    const float* om_w    = (const float*)d_in[5];
    const float* om_b    = (const float*)d_in[6];
    const float* oproj_w = (const float*)d_in[7];
    const float* oproj_b = (const float*)d_in[8];
    const float* ln2_g   = (const float*)d_in[9];
    const float* ln2_b   = (const float*)d_in[10];
    const float* fc1_w   = (const float*)d_in[11];
    const float* fc1_b   = (const float*)d_in[12];
    const float* fc2_w   = (const float*)d_in[13];
    const float* fc2_b   = (const float*)d_in[14];
    float* outp = (float*)d_out;

    float *xp, *om, *res, *fin;
    __half *tn, *val, *dcn, *ln2o, *hid, *wv, *wo, *w1, *w2, *wm;
    cudaGetSymbolAddress((void**)&xp,  g_xp);
    cudaGetSymbolAddress((void**)&tn,  g_tn);
    cudaGetSymbolAddress((void**)&val, g_val);
    cudaGetSymbolAddress((void**)&om,  g_om);
    cudaGetSymbolAddress((void**)&dcn, g_dcn);
    cudaGetSymbolAddress((void**)&res, g_res);
    cudaGetSymbolAddress((void**)&ln2o, g_ln2);
    cudaGetSymbolAddress((void**)&hid, g_hid);
    cudaGetSymbolAddress((void**)&fin, g_fin);
    cudaGetSymbolAddress((void**)&wv,  g_wv);
    cudaGetSymbolAddress((void**)&wo,  g_wo);
    cudaGetSymbolAddress((void**)&w1,  g_w1);
    cudaGetSymbolAddress((void**)&w2,  g_w2);
    cudaGetSymbolAddress((void**)&wm,  g_wm);

    static int attr_done = 0;
    if (!attr_done) {
        cudaFuncSetAttribute(gemm_mma<0, 1>, cudaFuncAttributeMaxDynamicSharedMemorySize, GEMM_SMEM_BYTES);
        cudaFuncSetAttribute(gemm_mma<0, 0>, cudaFuncAttributeMaxDynamicSharedMemorySize, GEMM_SMEM_BYTES);
        cudaFuncSetAttribute(gemm_mma<1, 1>, cudaFuncAttributeMaxDynamicSharedMemorySize, GEMM_SMEM_BYTES);
        cudaFuncSetAttribute(gemm_mma<2, 0>, cudaFuncAttributeMaxDynamicSharedMemorySize, GEMM_SMEM_BYTES);
        attr_done = 1;
    }

    dim3 tb(32, 8);
    // weight transposes: [K,N] f32 -> [N,K] f16 (wm rows >= 324 remain zero)
    transpose_w<<<dim3(CC / 32, CC / 32), tb>>>(vproj_w, wv, CC, CC);
    transpose_w<<<dim3(HID / 32, CC / 32), tb>>>(fc1_w, w1, CC, HID);
    transpose_w<<<dim3(CC / 32, CC / 32), tb>>>(oproj_w, wo, CC, CC);
    transpose_w<<<dim3(CC / 32, HID / 32), tb>>>(fc2_w, w2, HID, CC);
    transpose_w<<<dim3((OMC + 31) / 32, CC / 32), tb>>>(om_w, wm, CC, OMC);

    // 1. transpose + LN1
    ln1_kernel<<<NTOK / 8, 256>>>(x, ln1_g, ln1_b, xp, tn);
    // 2. val = tn @ vproj_w + b   (fp16 out)
    gemm_mma<0, 1><<<dim3(NTOK / 128, 3), 256, GEMM_SMEM_BYTES>>>(tn, wv, vproj_b, nullptr, val, CC, CC);
    // 3. om = tn @ om_w + b       (Nn=324, fp32 out)
    gemm_mma<0, 0><<<dim3(NTOK / 128, 3), 256, GEMM_SMEM_BYTES>>>(tn, wm, om_b, nullptr, om, OMC, CC);
    // 4. DCN sampling (fp16 in/out)
    dcn_kernel<<<NTOK, 384>>>(val, om, dcn);
    // 5. res = xp + dcn @ oproj_w + b  (fp32 out)
    gemm_mma<2, 0><<<dim3(NTOK / 128, 3), 256, GEMM_SMEM_BYTES>>>(dcn, wo, oproj_b, xp, res, CC, CC);
    // 6. LN2 (fp16 out)
    ln2_kernel<<<NTOK / 8, 256>>>(res, ln2_g, ln2_b, ln2o);
    // 7. hid = gelu(ln2o @ fc1_w + b)  (fp16 out)
    gemm_mma<1, 1><<<dim3(NTOK / 128, HID / 128), 256, GEMM_SMEM_BYTES>>>(ln2o, w1, fc1_b, nullptr, hid, HID, CC);
    // 8. fin = res + hid @ fc2_w + b   (fp32 out)
    gemm_mma<2, 0><<<dim3(NTOK / 128, 3), 256, GEMM_SMEM_BYTES>>>(hid, w2, fc2_b, res, fin, CC, HID);
    // 9. transpose back
    transpose_out<<<dim3(HWW / 32, CC / 32, BB), tb>>>(fin, outp);
}

// round 12
// speedup vs baseline: 1.4418x; 1.0229x over previous
#include <cuda_runtime.h>
#include <cuda_fp16.h>
#include <math.h>
#include <stdint.h>

#define BB   4
#define CC   384
#define HH   56
#define WW   56
#define HWW  3136
#define NTOK 12544
#define GG   12
#define GCH  32
#define KK2  9
#define OMC  324
#define HID  1536
#define EPSV 1e-5f
#define VOC  708          // combined val(384) + om(324) row width

// ---------------- scratch (device globals; no allocation) ----------------
__device__ float  g_xp [NTOK * CC];
__device__ __half g_tn [NTOK * CC];
__device__ __half g_vo [NTOK * VOC];     // val | om combined, fp16
__device__ __half g_dcn[NTOK * CC];
__device__ float  g_res[NTOK * CC];
__device__ __half g_ln2[NTOK * CC];
__device__ __half g_hid[NTOK * HID];
__device__ float  g_fin[NTOK * CC];
// transposed weights [N,K] row-major, fp16 (zero-init where never written)
__device__ __half g_wvm[768 * CC];       // vproj^T rows 0..383, om^T rows 384..707
__device__ float  g_bvm[768];            // combined bias
__device__ __half g_wo [CC * CC];
__device__ __half g_w1 [HID * CC];
__device__ __half g_w2 [CC * HID];

// ===================== helpers =====================
__device__ __forceinline__ uint32_t smem_u32(const void* p) {
    uint32_t a;
    asm("{ .reg .u64 t; cvta.to.shared.u64 t, %1; cvt.u32.u64 %0, t; }"
        : "=r"(a) : "l"(p));
    return a;
}
#define CP16(dst, src) \
    asm volatile("cp.async.ca.shared.global [%0], [%1], 16;" \
                 :: "r"(dst), "l"(src))
#define CP_COMMIT() asm volatile("cp.async.commit_group;")
#define CP_WAIT1()  asm volatile("cp.async.wait_group 1;")
#define CP_WAIT0()  asm volatile("cp.async.wait_group 0;")

#define MMA_F16(d, a, b) \
    asm volatile("mma.sync.aligned.m16n8k16.row.col.f32.f16.f16.f32 " \
        "{%0,%1,%2,%3}, {%4,%5,%6,%7}, {%8,%9}, {%0,%1,%2,%3};" \
        : "+f"((d)[0]), "+f"((d)[1]), "+f"((d)[2]), "+f"((d)[3]) \
        : "r"((a)[0]), "r"((a)[1]), "r"((a)[2]), "r"((a)[3]), \
          "r"((b)[0]), "r"((b)[1]))

#define LDSM4(r0, r1, r2, r3, addr) \
    asm volatile("ldmatrix.sync.aligned.m8n8.x4.shared.b16 {%0,%1,%2,%3}, [%4];" \
        : "=r"(r0), "=r"(r1), "=r"(r2), "=r"(r3) : "r"(addr))

// ===================== mma.sync fp16 GEMM (fp32 accum) =====================
#define TSTRH 40
#define T_HALFS (128 * TSTRH)
#define GEMM_SMEM_BYTES ((6 * T_HALFS) * 2)         // 61440 B

template <int EPI, int OUTH>
__global__ __launch_bounds__(256, 2) void gemm_mma(
    const __half* __restrict__ A, const __half* __restrict__ Wt,
    const float* __restrict__ bias, const float* __restrict__ Add,
    void* __restrict__ OutV, int Nn, int K)
{
    extern __shared__ __half dynh[];
    __half* Asb = dynh;
    __half* Bsb = dynh + 3 * T_HALFS;
    float*  OutF = (float*)OutV;
    __half* OutH = (__half*)OutV;

    const int tid  = threadIdx.x;
    const int lane = tid & 31, warp = tid >> 5;
    const int wm = (warp >> 2) * 64, wn = (warp & 3) * 32;
    const int g4 = lane >> 2, tg = lane & 3;
    const int m0 = blockIdx.x * 128, n0 = blockIdx.y * 128;

    const int lrow = lane & 15;
    const int lkof = (lane >> 4) * 8;
    const int bnof = (lane >> 4) * 8 + (lane & 7);
    const int bkof = ((lane >> 3) & 1) * 8;

    const int r = tid & 127;
    const int q = tid >> 7;

    float acc[4][4][4];
#pragma unroll
    for (int a = 0; a < 4; a++)
#pragma unroll
        for (int b = 0; b < 4; b++)
#pragma unroll
            for (int c = 0; c < 4; c++) acc[a][b][c] = 0.f;

    const int nkc = K >> 5;
    const __half* srcA = A  + (size_t)(m0 + r) * K + q * 8;
    const __half* srcB = Wt + (size_t)(n0 + r) * K + q * 8;

#define ISSUE(kc, bufi) do {                                                  \
        int _k0 = (kc) << 5;                                                  \
        __half* _As = Asb + (bufi) * T_HALFS + r * TSTRH + q * 8;             \
        __half* _Bs = Bsb + (bufi) * T_HALFS + r * TSTRH + q * 8;             \
        CP16(smem_u32(_As),      srcA + _k0);                                 \
        CP16(smem_u32(_As + 16), srcA + _k0 + 16);                            \
        CP16(smem_u32(_Bs),      srcB + _k0);                                 \
        CP16(smem_u32(_Bs + 16), srcB + _k0 + 16);                            \
        CP_COMMIT();                                                          \
    } while (0)

    ISSUE(0, 0);
    ISSUE(1, 1);

    int buf = 0;
    for (int kc = 0; kc < nkc; kc++) {
        if (kc + 2 < nkc) CP_WAIT1(); else CP_WAIT0();
        __syncthreads();
        if (kc + 2 < nkc) {
            int nb = kc + 2 - ((kc + 2) / 3) * 3;
            ISSUE(kc + 2, nb);
        }
        const __half* As = Asb + buf * T_HALFS;
        const __half* Bs = Bsb + buf * T_HALFS;

#pragma unroll
        for (int s = 0; s < 2; s++) {
            uint32_t af[4][4], bf[4][2];
#pragma unroll
            for (int mt = 0; mt < 4; mt++) {
                uint32_t ad = smem_u32(As + (wm + mt * 16 + lrow) * TSTRH + s * 16 + lkof);
                LDSM4(af[mt][0], af[mt][1], af[mt][2], af[mt][3], ad);
            }
#pragma unroll
            for (int p = 0; p < 2; p++) {
                uint32_t ad = smem_u32(Bs + (wn + p * 16 + bnof) * TSTRH + s * 16 + bkof);
                LDSM4(bf[2 * p][0], bf[2 * p][1], bf[2 * p + 1][0], bf[2 * p + 1][1], ad);
            }
#pragma unroll
            for (int mt = 0; mt < 4; mt++)
#pragma unroll
                for (int nt = 0; nt < 4; nt++)
                    MMA_F16(acc[mt][nt], af[mt], bf[nt]);
        }
        buf++; if (buf == 3) buf = 0;
    }
#undef ISSUE

#pragma unroll
    for (int mt = 0; mt < 4; mt++) {
        int row = m0 + wm + mt * 16 + g4;
#pragma unroll
        for (int nt = 0; nt < 4; nt++) {
            int col = n0 + wn + nt * 8 + tg * 2;
            if (col < Nn) {
                float b0 = __ldg(&bias[col]), b1 = __ldg(&bias[col + 1]);
                float v0 = acc[mt][nt][0] + b0;
                float v1 = acc[mt][nt][1] + b1;
                float v2 = acc[mt][nt][2] + b0;
                float v3 = acc[mt][nt][3] + b1;
                if (EPI == 1) {
                    v0 = 0.5f * v0 * (1.f + erff(v0 * 0.70710678118654752f));
                    v1 = 0.5f * v1 * (1.f + erff(v1 * 0.70710678118654752f));
                    v2 = 0.5f * v2 * (1.f + erff(v2 * 0.70710678118654752f));
                    v3 = 0.5f * v3 * (1.f + erff(v3 * 0.70710678118654752f));
                }
                if (EPI == 2) {
                    v0 += Add[(size_t)row * Nn + col];
                    v1 += Add[(size_t)row * Nn + col + 1];
                    v2 += Add[(size_t)(row + 8) * Nn + col];
                    v3 += Add[(size_t)(row + 8) * Nn + col + 1];
                }
                if (OUTH) {
                    *reinterpret_cast<__half2*>(OutH + (size_t)row * Nn + col)       = __floats2half2_rn(v0, v1);
                    *reinterpret_cast<__half2*>(OutH + (size_t)(row + 8) * Nn + col) = __floats2half2_rn(v2, v3);
                } else {
                    *reinterpret_cast<float2*>(OutF + (size_t)row * Nn + col)       = make_float2(v0, v1);
                    *reinterpret_cast<float2*>(OutF + (size_t)(row + 8) * Nn + col) = make_float2(v2, v3);
                }
            }
        }
    }
}

// ---------------- one-shot weight prep: all transposes + bias ------------
// segments (32x32 tiles, dim3(32,8) blocks):
//   [0,144)      vproj_w[384,384]  -> wvm rows 0..383
//   [144,276)    om_w[384,324]     -> wvm rows 384..707   (11x12 tiles)
//   [276,420)    oproj_w[384,384]  -> wo
//   [420,996)    fc1_w[384,1536]   -> w1                  (48x12)
//   [996,1572)   fc2_w[1536,384]   -> w2                  (12x48)
//   1572         bias combine -> bvm
__global__ void transpose_all(
    const float* __restrict__ vproj_w, const float* __restrict__ om_w,
    const float* __restrict__ oproj_w, const float* __restrict__ fc1_w,
    const float* __restrict__ fc2_w,
    const float* __restrict__ vproj_b, const float* __restrict__ om_b,
    __half* __restrict__ wvm, __half* __restrict__ wo,
    __half* __restrict__ w1, __half* __restrict__ w2,
    float* __restrict__ bvm)
{
    __shared__ float s[32][33];
    int t = blockIdx.x;
    int tx = threadIdx.x, ty = threadIdx.y;
    int tid = ty * 32 + tx;

    if (t == 1572) {
        for (int i = tid; i < 768; i += 256)
            bvm[i] = (i < CC) ? vproj_b[i] : ((i < VOC) ? om_b[i - CC] : 0.f);
        return;
    }

    const float* src; __half* dst;
    int Kdim, Ndim, ntiles_n, rowoff, dstK;
    if (t < 144)       { src = vproj_w; dst = wvm; Kdim = CC;  Ndim = CC;  ntiles_n = 12; rowoff = 0;   dstK = CC;  }
    else if (t < 276)  { t -= 144;  src = om_w;   dst = wvm; Kdim = CC;  Ndim = OMC; ntiles_n = 11; rowoff = CC;  dstK = CC;  }
    else if (t < 420)  { t -= 276;  src = oproj_w; dst = wo;  Kdim = CC;  Ndim = CC;  ntiles_n = 12; rowoff = 0;   dstK = CC;  }
    else if (t < 996)  { t -= 420;  src = fc1_w;  dst = w1;  Kdim = CC;  Ndim = HID; ntiles_n = 48; rowoff = 0;   dstK = CC;  }
    else               { t -= 996;  src = fc2_w;  dst = w2;  Kdim = HID; Ndim = CC;  ntiles_n = 12; rowoff = 0;   dstK = HID; }

    int n0 = (t % ntiles_n) * 32;
    int k0 = (t / ntiles_n) * 32;

#pragma unroll
    for (int r = 0; r < 4; r++) {
        int k = k0 + ty + 8 * r, n = n0 + tx;
        s[ty + 8 * r][tx] = (k < Kdim && n < Ndim) ? src[(size_t)k * Ndim + n] : 0.f;
    }
    __syncthreads();
#pragma unroll
    for (int r = 0; r < 4; r++) {
        int n = n0 + ty + 8 * r, k = k0 + tx;
        if (n < Ndim && k < Kdim)
            dst[(size_t)(n + rowoff) * dstK + k] = __float2half(s[tx][ty + 8 * r]);
    }
}

// ---------------- LN1: transpose x + layernorm (tn -> fp16) ----------------
__global__ void ln1_kernel(const float* __restrict__ x,
                           const float* __restrict__ gam,
                           const float* __restrict__ bet,
                           float* __restrict__ xp, __half* __restrict__ tn)
{
    int warp = (blockIdx.x * blockDim.x + threadIdx.x) >> 5;
    if (warp >= NTOK) return;
    int lane = threadIdx.x & 31;
    int b  = warp / HWW;
    int hw = warp - b * HWW;
    const float* xb = x + (size_t)b * CC * HWW + hw;

    float v[12];
#pragma unroll
    for (int i = 0; i < 12; i++) v[i] = xb[(size_t)(lane + 32 * i) * HWW];
    float s = 0.f;
#pragma unroll
    for (int i = 0; i < 12; i++) s += v[i];
#pragma unroll
    for (int o = 16; o; o >>= 1) s += __shfl_xor_sync(0xffffffffu, s, o);
    float mu = s * (1.0f / CC);
    float q = 0.f;
#pragma unroll
    for (int i = 0; i < 12; i++) { float d = v[i] - mu; q += d * d; }
#pragma unroll
    for (int o = 16; o; o >>= 1) q += __shfl_xor_sync(0xffffffffu, q, o);
    float rs = rsqrtf(q * (1.0f / CC) + EPSV);
    size_t base = (size_t)warp * CC;
#pragma unroll
    for (int i = 0; i < 12; i++) {
        int c = lane + 32 * i;
        xp[base + c] = v[i];
        tn[base + c] = __float2half((v[i] - mu) * rs * gam[c] + bet[c]);
    }
}

// ---------------- LN2 (out -> fp16) ----------------
__global__ void ln2_kernel(const float* __restrict__ res,
                           const float* __restrict__ gam,
                           const float* __restrict__ bet,
                           __half* __restrict__ outp)
{
    int warp = (blockIdx.x * blockDim.x + threadIdx.x) >> 5;
    if (warp >= NTOK) return;
    int lane = threadIdx.x & 31;
    size_t base = (size_t)warp * CC;
    float v[12];
#pragma unroll
    for (int i = 0; i < 12; i++) v[i] = res[base + lane + 32 * i];
    float s = 0.f;
#pragma unroll
    for (int i = 0; i < 12; i++) s += v[i];
#pragma unroll
    for (int o = 16; o; o >>= 1) s += __shfl_xor_sync(0xffffffffu, s, o);
    float mu = s * (1.0f / CC);
    float q = 0.f;
#pragma unroll
    for (int i = 0; i < 12; i++) { float d = v[i] - mu; q += d * d; }
#pragma unroll
    for (int o = 16; o; o >>= 1) q += __shfl_xor_sync(0xffffffffu, q, o);
    float rs = rsqrtf(q * (1.0f / CC) + EPSV);
#pragma unroll
    for (int i = 0; i < 12; i++) {
        int c = lane + 32 * i;
        outp[base + c] = __float2half((v[i] - mu) * rs * gam[c] + bet[c]);
    }
}

// ---------------- DCNv4 sampling from combined vo buffer -----------------
__global__ __launch_bounds__(384) void dcn_kernel(
    const __half* __restrict__ vo,
    __half* __restrict__ outp)
{
    __shared__ float s_om[OMC];
    const int n = blockIdx.x;
    const int tid = threadIdx.x;
    if (tid < OMC) s_om[tid] = __half2float(vo[(size_t)n * VOC + CC + tid]);
    __syncthreads();

    const int g = tid >> 5, lane = tid & 31;
    const int b = n / HWW;
    const int hw = n - b * HWW;
    const int ii = hw / WW;
    const int jj = hw - ii * WW;

    const float* omb = s_om + g * 27;
    const __half* vb = vo + (size_t)b * HWW * VOC + g * GCH + lane;

    float acc = 0.f;
#pragma unroll
    for (int k = 0; k < KK2; k++) {
        float dx = omb[2 * k];
        float dy = omb[2 * k + 1];
        float mk = omb[18 + k];
        float px = (float)jj + (float)(k % 3 - 1) + dx;
        float py = (float)ii + (float)(k / 3 - 1) + dy;
        float x0f = floorf(px), y0f = floorf(py);
        float tx = px - x0f, ty = py - y0f;
        int x0 = (int)x0f, y0 = (int)y0f;
        int x1 = x0 + 1,   y1 = y0 + 1;
        bool vx0 = (x0 >= 0) & (x0 < WW);
        bool vx1 = (x1 >= 0) & (x1 < WW);
        bool vy0 = (y0 >= 0) & (y0 < HH);
        bool vy1 = (y1 >= 0) & (y1 < HH);
        int row0 = y0 * (WW * VOC), row1 = row0 + WW * VOC;
        float v00 = (vy0 && vx0) ? __half2float(__ldg(vb + row0 + x0 * VOC)) : 0.f;
        float v01 = (vy0 && vx1) ? __half2float(__ldg(vb + row0 + x1 * VOC)) : 0.f;
        float v10 = (vy1 && vx0) ? __half2float(__ldg(vb + row1 + x0 * VOC)) : 0.f;
        float v11 = (vy1 && vx1) ? __half2float(__ldg(vb + row1 + x1 * VOC)) : 0.f;
        float top = v00 * (1.f - tx) + v01 * tx;
        float bot = v10 * (1.f - tx) + v11 * tx;
        acc += mk * (top * (1.f - ty) + bot * ty);
    }
    outp[(size_t)n * CC + g * GCH + lane] = __float2half(acc);
}

// ---------------- final transpose ----------------
__global__ void transpose_out(const float* __restrict__ fin,
                              float* __restrict__ outp)
{
    __shared__ float s[32][33];
    int b   = blockIdx.z;
    int hw0 = blockIdx.x * 32;
    int c0  = blockIdx.y * 32;
    int tx = threadIdx.x, ty = threadIdx.y;
#pragma unroll
    for (int r = 0; r < 4; r++) {
        int hw = hw0 + ty + 8 * r;
        s[ty + 8 * r][tx] = fin[(size_t)(b * HWW + hw) * CC + c0 + tx];
    }
    __syncthreads();
#pragma unroll
    for (int r = 0; r < 4; r++) {
        int c = c0 + ty + 8 * r;
        outp[(size_t)(b * CC + c) * HWW + hw0 + tx] = s[tx][ty + 8 * r];
    }
}

// --------------------------------------------------------------------------
extern "C" void kernel_launch(void* const* d_in, const int* in_sizes, int n_in,
                              void* d_out, int out_size)
{
    const float* x       = (const float*)d_in[0];
    const float* ln1_g   = (const float*)d_in[1];
    const float* ln1_b   = (const float*)d_in[2];
    const float* vproj_w = (const float*)d_in[3];
    const float* vproj_b = (const float*)d_in[4];
    const float* om_w    = (const float*)d_in[5];
    const float* om_b    = (const float*)d_in[6];
    const float* oproj_w = (const float*)d_in[7];
    const float* oproj_b = (const float*)d_in[8];
    const float* ln2_g   = (const float*)d_in[9];
    const float* ln2_b   = (const float*)d_in[10];
    const float* fc1_w   = (const float*)d_in[11];
    const float* fc1_b   = (const float*)d_in[12];
    const float* fc2_w   = (const float*)d_in[13];
    const float* fc2_b   = (const float*)d_in[14];
    float* outp = (float*)d_out;

    float *xp, *res, *fin, *bvm;
    __half *tn, *vo, *dcn, *ln2o, *hid, *wvm, *wo, *w1, *w2;
    cudaGetSymbolAddress((void**)&xp,  g_xp);
    cudaGetSymbolAddress((void**)&tn,  g_tn);
    cudaGetSymbolAddress((void**)&vo,  g_vo);
    cudaGetSymbolAddress((void**)&dcn, g_dcn);
    cudaGetSymbolAddress((void**)&res, g_res);
    cudaGetSymbolAddress((void**)&ln2o, g_ln2);
    cudaGetSymbolAddress((void**)&hid, g_hid);
    cudaGetSymbolAddress((void**)&fin, g_fin);
    cudaGetSymbolAddress((void**)&wvm, g_wvm);
    cudaGetSymbolAddress((void**)&bvm, g_bvm);
    cudaGetSymbolAddress((void**)&wo,  g_wo);
    cudaGetSymbolAddress((void**)&w1,  g_w1);
    cudaGetSymbolAddress((void**)&w2,  g_w2);

    static int attr_done = 0;
    if (!attr_done) {
        cudaFuncSetAttribute(gemm_mma<0, 1>, cudaFuncAttributeMaxDynamicSharedMemorySize, GEMM_SMEM_BYTES);
        cudaFuncSetAttribute(gemm_mma<1, 1>, cudaFuncAttributeMaxDynamicSharedMemorySize, GEMM_SMEM_BYTES);
        cudaFuncSetAttribute(gemm_mma<2, 0>, cudaFuncAttributeMaxDynamicSharedMemorySize, GEMM_SMEM_BYTES);
        attr_done = 1;
    }

    dim3 tb(32, 8);
    // 0. all weight transposes + bias combine, one launch
    transpose_all<<<1573, tb>>>(vproj_w, om_w, oproj_w, fc1_w, fc2_w,
                                vproj_b, om_b, wvm, wo, w1, w2, bvm);
    // 1. transpose + LN1
    ln1_kernel<<<NTOK / 8, 256>>>(x, ln1_g, ln1_b, xp, tn);
    // 2. vo = tn @ [vproj|om] + b   (fp16 out, N=708 of 768-padded)
    gemm_mma<0, 1><<<dim3(NTOK / 128, 6), 256, GEMM_SMEM_BYTES>>>(tn, wvm, bvm, nullptr, vo, VOC, CC);
    // 3. DCN sampling (combined vo in, fp16 out)
    dcn_kernel<<<NTOK, 384>>>(vo, dcn);
    // 4. res = xp + dcn @ oproj_w + b  (fp32 out)
    gemm_mma<2, 0><<<dim3(NTOK / 128, 3), 256, GEMM_SMEM_BYTES>>>(dcn, wo, oproj_b, xp, res, CC, CC);
    // 5. LN2 (fp16 out)
    ln2_kernel<<<NTOK / 8, 256>>>(res, ln2_g, ln2_b, ln2o);
    // 6. hid = gelu(ln2o @ fc1_w + b)  (fp16 out)
    gemm_mma<1, 1><<<dim3(NTOK / 128, HID / 128), 256, GEMM_SMEM_BYTES>>>(ln2o, w1, fc1_b, nullptr, hid, HID, CC);
    // 7. fin = res + hid @ fc2_w + b   (fp32 out)
    gemm_mma<2, 0><<<dim3(NTOK / 128, 3), 256, GEMM_SMEM_BYTES>>>(hid, w2, fc2_b, res, fin, CC, HID);
    // 8. transpose back
    transpose_out<<<dim3(HWW / 32, CC / 32, BB), tb>>>(fin, outp);
}

// round 13
// speedup vs baseline: 1.5726x; 1.0907x over previous
#include <cuda_runtime.h>
#include <cuda_fp16.h>
#include <math.h>
#include <stdint.h>

#define BB   4
#define CC   384
#define HH   56
#define WW   56
#define HWW  3136
#define NTOK 12544
#define GG   12
#define GCH  32
#define KK2  9
#define OMC  324
#define HID  1536
#define EPSV 1e-5f
#define VOC  708          // combined val(384) + om(324) row width

// ---------------- scratch (device globals; no allocation) ----------------
__device__ float  g_xp [NTOK * CC];
__device__ __half g_tn [NTOK * CC];
__device__ __half g_vo [NTOK * VOC];     // val | om combined, fp16
__device__ __half g_dcn[NTOK * CC];
__device__ float  g_res[NTOK * CC];
__device__ __half g_ln2[NTOK * CC];
__device__ __half g_hid[NTOK * HID];
__device__ float  g_fin[NTOK * CC];
// transposed weights [N,K] row-major, fp16 (zero-init where never written)
__device__ __half g_wvm[768 * CC];       // vproj^T rows 0..383, om^T rows 384..707
__device__ float  g_bvm[768];            // combined bias
__device__ __half g_wo [CC * CC];
__device__ __half g_w1 [HID * CC];
__device__ __half g_w2 [CC * HID];

// ===================== helpers =====================
__device__ __forceinline__ uint32_t smem_u32(const void* p) {
    uint32_t a;
    asm("{ .reg .u64 t; cvta.to.shared.u64 t, %1; cvt.u32.u64 %0, t; }"
        : "=r"(a) : "l"(p));
    return a;
}
#define CP16(dst, src) \
    asm volatile("cp.async.ca.shared.global [%0], [%1], 16;" \
                 :: "r"(dst), "l"(src))
#define CP_COMMIT() asm volatile("cp.async.commit_group;")
#define CP_WAIT1()  asm volatile("cp.async.wait_group 1;")
#define CP_WAIT0()  asm volatile("cp.async.wait_group 0;")

#define MMA_F16(d, a, b) \
    asm volatile("mma.sync.aligned.m16n8k16.row.col.f32.f16.f16.f32 " \
        "{%0,%1,%2,%3}, {%4,%5,%6,%7}, {%8,%9}, {%0,%1,%2,%3};" \
        : "+f"((d)[0]), "+f"((d)[1]), "+f"((d)[2]), "+f"((d)[3]) \
        : "r"((a)[0]), "r"((a)[1]), "r"((a)[2]), "r"((a)[3]), \
          "r"((b)[0]), "r"((b)[1]))

#define LDSM4(r0, r1, r2, r3, addr) \
    asm volatile("ldmatrix.sync.aligned.m8n8.x4.shared.b16 {%0,%1,%2,%3}, [%4];" \
        : "=r"(r0), "=r"(r1), "=r"(r2), "=r"(r3) : "r"(addr))

// ===================== mma.sync fp16 GEMM (fp32 accum) =====================
#define TSTRH 40
#define T_HALFS (128 * TSTRH)
#define GEMM_SMEM_BYTES ((6 * T_HALFS) * 2)         // 61440 B

template <int EPI, int OUTH>
__global__ __launch_bounds__(256, 2) void gemm_mma(
    const __half* __restrict__ A, const __half* __restrict__ Wt,
    const float* __restrict__ bias, const float* __restrict__ Add,
    void* __restrict__ OutV, int Nn, int K)
{
    extern __shared__ __half dynh[];
    __half* Asb = dynh;
    __half* Bsb = dynh + 3 * T_HALFS;
    float*  OutF = (float*)OutV;
    __half* OutH = (__half*)OutV;

    const int tid  = threadIdx.x;
    const int lane = tid & 31, warp = tid >> 5;
    const int wm = (warp >> 2) * 64, wn = (warp & 3) * 32;
    const int g4 = lane >> 2, tg = lane & 3;
    const int m0 = blockIdx.x * 128, n0 = blockIdx.y * 128;

    const int lrow = lane & 15;
    const int lkof = (lane >> 4) * 8;
    const int bnof = (lane >> 4) * 8 + (lane & 7);
    const int bkof = ((lane >> 3) & 1) * 8;

    const int r = tid & 127;
    const int q = tid >> 7;

    float acc[4][4][4];
#pragma unroll
    for (int a = 0; a < 4; a++)
#pragma unroll
        for (int b = 0; b < 4; b++)
#pragma unroll
            for (int c = 0; c < 4; c++) acc[a][b][c] = 0.f;

    const int nkc = K >> 5;
    const __half* srcA = A  + (size_t)(m0 + r) * K + q * 8;
    const __half* srcB = Wt + (size_t)(n0 + r) * K + q * 8;

#define ISSUE(kc, bufi) do {                                                  \
        int _k0 = (kc) << 5;                                                  \
        __half* _As = Asb + (bufi) * T_HALFS + r * TSTRH + q * 8;             \
        __half* _Bs = Bsb + (bufi) * T_HALFS + r * TSTRH + q * 8;             \
        CP16(smem_u32(_As),      srcA + _k0);                                 \
        CP16(smem_u32(_As + 16), srcA + _k0 + 16);                            \
        CP16(smem_u32(_Bs),      srcB + _k0);                                 \
        CP16(smem_u32(_Bs + 16), srcB + _k0 + 16);                            \
        CP_COMMIT();                                                          \
    } while (0)

    ISSUE(0, 0);
    ISSUE(1, 1);

    int buf = 0;
    for (int kc = 0; kc < nkc; kc++) {
        if (kc + 2 < nkc) CP_WAIT1(); else CP_WAIT0();
        __syncthreads();
        if (kc + 2 < nkc) {
            int nb = kc + 2 - ((kc + 2) / 3) * 3;
            ISSUE(kc + 2, nb);
        }
        const __half* As = Asb + buf * T_HALFS;
        const __half* Bs = Bsb + buf * T_HALFS;

#pragma unroll
        for (int s = 0; s < 2; s++) {
            uint32_t af[4][4], bf[4][2];
#pragma unroll
            for (int mt = 0; mt < 4; mt++) {
                uint32_t ad = smem_u32(As + (wm + mt * 16 + lrow) * TSTRH + s * 16 + lkof);
                LDSM4(af[mt][0], af[mt][1], af[mt][2], af[mt][3], ad);
            }
#pragma unroll
            for (int p = 0; p < 2; p++) {
                uint32_t ad = smem_u32(Bs + (wn + p * 16 + bnof) * TSTRH + s * 16 + bkof);
                LDSM4(bf[2 * p][0], bf[2 * p][1], bf[2 * p + 1][0], bf[2 * p + 1][1], ad);
            }
#pragma unroll
            for (int mt = 0; mt < 4; mt++)
#pragma unroll
                for (int nt = 0; nt < 4; nt++)
                    MMA_F16(acc[mt][nt], af[mt], bf[nt]);
        }
        buf++; if (buf == 3) buf = 0;
    }
#undef ISSUE

#pragma unroll
    for (int mt = 0; mt < 4; mt++) {
        int row = m0 + wm + mt * 16 + g4;
#pragma unroll
        for (int nt = 0; nt < 4; nt++) {
            int col = n0 + wn + nt * 8 + tg * 2;
            if (col < Nn) {
                float b0 = __ldg(&bias[col]), b1 = __ldg(&bias[col + 1]);
                float v0 = acc[mt][nt][0] + b0;
                float v1 = acc[mt][nt][1] + b1;
                float v2 = acc[mt][nt][2] + b0;
                float v3 = acc[mt][nt][3] + b1;
                if (EPI == 1) {
                    v0 = 0.5f * v0 * (1.f + erff(v0 * 0.70710678118654752f));
                    v1 = 0.5f * v1 * (1.f + erff(v1 * 0.70710678118654752f));
                    v2 = 0.5f * v2 * (1.f + erff(v2 * 0.70710678118654752f));
                    v3 = 0.5f * v3 * (1.f + erff(v3 * 0.70710678118654752f));
                }
                if (EPI == 2) {
                    v0 += Add[(size_t)row * Nn + col];
                    v1 += Add[(size_t)row * Nn + col + 1];
                    v2 += Add[(size_t)(row + 8) * Nn + col];
                    v3 += Add[(size_t)(row + 8) * Nn + col + 1];
                }
                if (OUTH) {
                    *reinterpret_cast<__half2*>(OutH + (size_t)row * Nn + col)       = __floats2half2_rn(v0, v1);
                    *reinterpret_cast<__half2*>(OutH + (size_t)(row + 8) * Nn + col) = __floats2half2_rn(v2, v3);
                } else {
                    *reinterpret_cast<float2*>(OutF + (size_t)row * Nn + col)       = make_float2(v0, v1);
                    *reinterpret_cast<float2*>(OutF + (size_t)(row + 8) * Nn + col) = make_float2(v2, v3);
                }
            }
        }
    }
}

// ---------------- one-shot weight prep: all transposes + bias ------------
__global__ void transpose_all(
    const float* __restrict__ vproj_w, const float* __restrict__ om_w,
    const float* __restrict__ oproj_w, const float* __restrict__ fc1_w,
    const float* __restrict__ fc2_w,
    const float* __restrict__ vproj_b, const float* __restrict__ om_b,
    __half* __restrict__ wvm, __half* __restrict__ wo,
    __half* __restrict__ w1, __half* __restrict__ w2,
    float* __restrict__ bvm)
{
    __shared__ float s[32][33];
    int t = blockIdx.x;
    int tx = threadIdx.x, ty = threadIdx.y;
    int tid = ty * 32 + tx;

    if (t == 1572) {
        for (int i = tid; i < 768; i += 256)
            bvm[i] = (i < CC) ? vproj_b[i] : ((i < VOC) ? om_b[i - CC] : 0.f);
        return;
    }

    const float* src; __half* dst;
    int Kdim, Ndim, ntiles_n, rowoff, dstK;
    if (t < 144)       { src = vproj_w; dst = wvm; Kdim = CC;  Ndim = CC;  ntiles_n = 12; rowoff = 0;   dstK = CC;  }
    else if (t < 276)  { t -= 144;  src = om_w;   dst = wvm; Kdim = CC;  Ndim = OMC; ntiles_n = 11; rowoff = CC;  dstK = CC;  }
    else if (t < 420)  { t -= 276;  src = oproj_w; dst = wo;  Kdim = CC;  Ndim = CC;  ntiles_n = 12; rowoff = 0;   dstK = CC;  }
    else if (t < 996)  { t -= 420;  src = fc1_w;  dst = w1;  Kdim = CC;  Ndim = HID; ntiles_n = 48; rowoff = 0;   dstK = CC;  }
    else               { t -= 996;  src = fc2_w;  dst = w2;  Kdim = HID; Ndim = CC;  ntiles_n = 12; rowoff = 0;   dstK = HID; }

    int n0 = (t % ntiles_n) * 32;
    int k0 = (t / ntiles_n) * 32;

#pragma unroll
    for (int r = 0; r < 4; r++) {
        int k = k0 + ty + 8 * r, n = n0 + tx;
        s[ty + 8 * r][tx] = (k < Kdim && n < Ndim) ? src[(size_t)k * Ndim + n] : 0.f;
    }
    __syncthreads();
#pragma unroll
    for (int r = 0; r < 4; r++) {
        int n = n0 + ty + 8 * r, k = k0 + tx;
        if (n < Ndim && k < Kdim)
            dst[(size_t)(n + rowoff) * dstK + k] = __float2half(s[tx][ty + 8 * r]);
    }
}

// ---------------- LN1: transpose x + layernorm (tn -> fp16) ----------------
__global__ void ln1_kernel(const float* __restrict__ x,
                           const float* __restrict__ gam,
                           const float* __restrict__ bet,
                           float* __restrict__ xp, __half* __restrict__ tn)
{
    int warp = (blockIdx.x * blockDim.x + threadIdx.x) >> 5;
    if (warp >= NTOK) return;
    int lane = threadIdx.x & 31;
    int b  = warp / HWW;
    int hw = warp - b * HWW;
    const float* xb = x + (size_t)b * CC * HWW + hw;

    float v[12];
#pragma unroll
    for (int i = 0; i < 12; i++) v[i] = xb[(size_t)(lane + 32 * i) * HWW];
    float s = 0.f;
#pragma unroll
    for (int i = 0; i < 12; i++) s += v[i];
#pragma unroll
    for (int o = 16; o; o >>= 1) s += __shfl_xor_sync(0xffffffffu, s, o);
    float mu = s * (1.0f / CC);
    float q = 0.f;
#pragma unroll
    for (int i = 0; i < 12; i++) { float d = v[i] - mu; q += d * d; }
#pragma unroll
    for (int o = 16; o; o >>= 1) q += __shfl_xor_sync(0xffffffffu, q, o);
    float rs = rsqrtf(q * (1.0f / CC) + EPSV);
    size_t base = (size_t)warp * CC;
#pragma unroll
    for (int i = 0; i < 12; i++) {
        int c = lane + 32 * i;
        xp[base + c] = v[i];
        tn[base + c] = __float2half((v[i] - mu) * rs * gam[c] + bet[c]);
    }
}

// ---------------- LN2 (out -> fp16) ----------------
__global__ void ln2_kernel(const float* __restrict__ res,
                           const float* __restrict__ gam,
                           const float* __restrict__ bet,
                           __half* __restrict__ outp)
{
    int warp = (blockIdx.x * blockDim.x + threadIdx.x) >> 5;
    if (warp >= NTOK) return;
    int lane = threadIdx.x & 31;
    size_t base = (size_t)warp * CC;
    float v[12];
#pragma unroll
    for (int i = 0; i < 12; i++) v[i] = res[base + lane + 32 * i];
    float s = 0.f;
#pragma unroll
    for (int i = 0; i < 12; i++) s += v[i];
#pragma unroll
    for (int o = 16; o; o >>= 1) s += __shfl_xor_sync(0xffffffffu, s, o);
    float mu = s * (1.0f / CC);
    float q = 0.f;
#pragma unroll
    for (int i = 0; i < 12; i++) { float d = v[i] - mu; q += d * d; }
#pragma unroll
    for (int o = 16; o; o >>= 1) q += __shfl_xor_sync(0xffffffffu, q, o);
    float rs = rsqrtf(q * (1.0f / CC) + EPSV);
#pragma unroll
    for (int i = 0; i < 12; i++) {
        int c = lane + 32 * i;
        outp[base + c] = __float2half((v[i] - mu) * rs * gam[c] + bet[c]);
    }
}

// ---------------- DCNv4 sampling: 192 thr/token, warp = 2 groups ---------
// lane 0-15 -> group 2w (channels 2*sl, 2*sl+1 via half2), lane 16-31 -> 2w+1
__global__ __launch_bounds__(192) void dcn_kernel(
    const __half* __restrict__ vo,
    __half* __restrict__ outp)
{
    __shared__ float s_om[OMC];
    const int n = blockIdx.x;
    const int tid = threadIdx.x;
    for (int i = tid; i < OMC; i += 192)
        s_om[i] = __half2float(vo[(size_t)n * VOC + CC + i]);
    __syncthreads();

    const int w = tid >> 5, lane = tid & 31;
    const int g = w * 2 + (lane >> 4);
    const int ch = (lane & 15) * 2;
    const int b = n / HWW;
    const int hw = n - b * HWW;
    const int ii = hw / WW;
    const int jj = hw - ii * WW;

    const float* omb = s_om + g * 27;
    const __half* vb = vo + (size_t)b * HWW * VOC + g * GCH + ch;

    float accx = 0.f, accy = 0.f;
#pragma unroll
    for (int k = 0; k < KK2; k++) {
        float dx = omb[2 * k];
        float dy = omb[2 * k + 1];
        float mk = omb[18 + k];
        float px = (float)jj + (float)(k % 3 - 1) + dx;
        float py = (float)ii + (float)(k / 3 - 1) + dy;
        float x0f = floorf(px), y0f = floorf(py);
        float tx = px - x0f, ty = py - y0f;
        int x0 = (int)x0f, y0 = (int)y0f;
        int x1 = x0 + 1,   y1 = y0 + 1;
        bool vx0 = (x0 >= 0) & (x0 < WW);
        bool vx1 = (x1 >= 0) & (x1 < WW);
        bool vy0 = (y0 >= 0) & (y0 < HH);
        bool vy1 = (y1 >= 0) & (y1 < HH);
        int row0 = y0 * (WW * VOC), row1 = row0 + WW * VOC;
        float2 z = make_float2(0.f, 0.f);
        float2 v00 = (vy0 && vx0) ? __half22float2(*(const __half2*)(vb + row0 + x0 * VOC)) : z;
        float2 v01 = (vy0 && vx1) ? __half22float2(*(const __half2*)(vb + row0 + x1 * VOC)) : z;
        float2 v10 = (vy1 && vx0) ? __half22float2(*(const __half2*)(vb + row1 + x0 * VOC)) : z;
        float2 v11 = (vy1 && vx1) ? __half22float2(*(const __half2*)(vb + row1 + x1 * VOC)) : z;
        float w00 = (1.f - tx) * (1.f - ty) * mk;
        float w01 = tx * (1.f - ty) * mk;
        float w10 = (1.f - tx) * ty * mk;
        float w11 = tx * ty * mk;
        accx += v00.x * w00 + v01.x * w01 + v10.x * w10 + v11.x * w11;
        accy += v00.y * w00 + v01.y * w01 + v10.y * w10 + v11.y * w11;
    }
    *reinterpret_cast<__half2*>(outp + (size_t)n * CC + g * GCH + ch) =
        __floats2half2_rn(accx, accy);
}

// ---------------- final transpose ----------------
__global__ void transpose_out(const float* __restrict__ fin,
                              float* __restrict__ outp)
{
    __shared__ float s[32][33];
    int b   = blockIdx.z;
    int hw0 = blockIdx.x * 32;
    int c0  = blockIdx.y * 32;
    int tx = threadIdx.x, ty = threadIdx.y;
#pragma unroll
    for (int r = 0; r < 4; r++) {
        int hw = hw0 + ty + 8 * r;
        s[ty + 8 * r][tx] = fin[(size_t)(b * HWW + hw) * CC + c0 + tx];
    }
    __syncthreads();
#pragma unroll
    for (int r = 0; r < 4; r++) {
        int c = c0 + ty + 8 * r;
        outp[(size_t)(b * CC + c) * HWW + hw0 + tx] = s[tx][ty + 8 * r];
    }
}

// --------------------------------------------------------------------------
extern "C" void kernel_launch(void* const* d_in, const int* in_sizes, int n_in,
                              void* d_out, int out_size)
{
    const float* x       = (const float*)d_in[0];
    const float* ln1_g   = (const float*)d_in[1];
    const float* ln1_b   = (const float*)d_in[2];
    const float* vproj_w = (const float*)d_in[3];
    const float* vproj_b = (const float*)d_in[4];
    const float* om_w    = (const float*)d_in[5];
    const float* om_b    = (const float*)d_in[6];
    const float* oproj_w = (const float*)d_in[7];
    const float* oproj_b = (const float*)d_in[8];
    const float* ln2_g   = (const float*)d_in[9];
    const float* ln2_b   = (const float*)d_in[10];
    const float* fc1_w   = (const float*)d_in[11];
    const float* fc1_b   = (const float*)d_in[12];
    const float* fc2_w   = (const float*)d_in[13];
    const float* fc2_b   = (const float*)d_in[14];
    float* outp = (float*)d_out;

    float *xp, *res, *fin, *bvm;
    __half *tn, *vo, *dcn, *ln2o, *hid, *wvm, *wo, *w1, *w2;
    cudaGetSymbolAddress((void**)&xp,  g_xp);
    cudaGetSymbolAddress((void**)&tn,  g_tn);
    cudaGetSymbolAddress((void**)&vo,  g_vo);
    cudaGetSymbolAddress((void**)&dcn, g_dcn);
    cudaGetSymbolAddress((void**)&res, g_res);
    cudaGetSymbolAddress((void**)&ln2o, g_ln2);
    cudaGetSymbolAddress((void**)&hid, g_hid);
    cudaGetSymbolAddress((void**)&fin, g_fin);
    cudaGetSymbolAddress((void**)&wvm, g_wvm);
    cudaGetSymbolAddress((void**)&bvm, g_bvm);
    cudaGetSymbolAddress((void**)&wo,  g_wo);
    cudaGetSymbolAddress((void**)&w1,  g_w1);
    cudaGetSymbolAddress((void**)&w2,  g_w2);

    static int attr_done = 0;
    if (!attr_done) {
        cudaFuncSetAttribute(gemm_mma<0, 1>, cudaFuncAttributeMaxDynamicSharedMemorySize, GEMM_SMEM_BYTES);
        cudaFuncSetAttribute(gemm_mma<1, 1>, cudaFuncAttributeMaxDynamicSharedMemorySize, GEMM_SMEM_BYTES);
        cudaFuncSetAttribute(gemm_mma<2, 0>, cudaFuncAttributeMaxDynamicSharedMemorySize, GEMM_SMEM_BYTES);
        attr_done = 1;
    }

    dim3 tb(32, 8);
    // 0. all weight transposes + bias combine, one launch
    transpose_all<<<1573, tb>>>(vproj_w, om_w, oproj_w, fc1_w, fc2_w,
                                vproj_b, om_b, wvm, wo, w1, w2, bvm);
    // 1. transpose + LN1
    ln1_kernel<<<NTOK / 8, 256>>>(x, ln1_g, ln1_b, xp, tn);
    // 2. vo = tn @ [vproj|om] + b   (fp16 out, N=708 of 768-padded)
    gemm_mma<0, 1><<<dim3(NTOK / 128, 6), 256, GEMM_SMEM_BYTES>>>(tn, wvm, bvm, nullptr, vo, VOC, CC);
    // 3. DCN sampling (combined vo in, fp16 out)
    dcn_kernel<<<NTOK, 192>>>(vo, dcn);
    // 4. res = xp + dcn @ oproj_w + b  (fp32 out)
    gemm_mma<2, 0><<<dim3(NTOK / 128, 3), 256, GEMM_SMEM_BYTES>>>(dcn, wo, oproj_b, xp, res, CC, CC);
    // 5. LN2 (fp16 out)
    ln2_kernel<<<NTOK / 8, 256>>>(res, ln2_g, ln2_b, ln2o);
    // 6. hid = gelu(ln2o @ fc1_w + b)  (fp16 out)
    gemm_mma<1, 1><<<dim3(NTOK / 128, HID / 128), 256, GEMM_SMEM_BYTES>>>(ln2o, w1, fc1_b, nullptr, hid, HID, CC);
    // 7. fin = res + hid @ fc2_w + b   (fp32 out)
    gemm_mma<2, 0><<<dim3(NTOK / 128, 3), 256, GEMM_SMEM_BYTES>>>(hid, w2, fc2_b, res, fin, CC, HID);
    // 8. transpose back
    transpose_out<<<dim3(HWW / 32, CC / 32, BB), tb>>>(fin, outp);
}

// round 14
// speedup vs baseline: 1.6488x; 1.0484x over previous
#include <cuda_runtime.h>
#include <cuda_fp16.h>
#include <math.h>
#include <stdint.h>

#define BB   4
#define CC   384
#define HH   56
#define WW   56
#define HWW  3136
#define NTOK 12544
#define GG   12
#define GCH  32
#define KK2  9
#define OMC  324
#define HID  1536
#define EPSV 1e-5f
#define VOC  708          // combined val(384) + om(324) row width

// ---------------- scratch (device globals; no allocation) ----------------
__device__ float  g_xp [NTOK * CC];
__device__ __half g_tn [NTOK * CC];
__device__ __half g_vo [NTOK * VOC];     // val | om combined, fp16
__device__ __half g_dcn[NTOK * CC];
__device__ float  g_res[NTOK * CC];
__device__ __half g_ln2[NTOK * CC];
__device__ __half g_hid[NTOK * HID];
__device__ float  g_fin[NTOK * CC];
// transposed weights [N,K] row-major, fp16 (zero-init where never written)
__device__ __half g_wvm[768 * CC];       // vproj^T rows 0..383, om^T rows 384..707
__device__ float  g_bvm[768];            // combined bias
__device__ __half g_wo [CC * CC];
__device__ __half g_w1 [HID * CC];
__device__ __half g_w2 [CC * HID];

// ===================== helpers =====================
__device__ __forceinline__ uint32_t smem_u32(const void* p) {
    uint32_t a;
    asm("{ .reg .u64 t; cvta.to.shared.u64 t, %1; cvt.u32.u64 %0, t; }"
        : "=r"(a) : "l"(p));
    return a;
}
#define CP16(dst, src) \
    asm volatile("cp.async.ca.shared.global [%0], [%1], 16;" \
                 :: "r"(dst), "l"(src))
#define CP_COMMIT() asm volatile("cp.async.commit_group;")
#define CP_WAIT1()  asm volatile("cp.async.wait_group 1;")
#define CP_WAIT0()  asm volatile("cp.async.wait_group 0;")

#define MMA_F16(d, a, b) \
    asm volatile("mma.sync.aligned.m16n8k16.row.col.f32.f16.f16.f32 " \
        "{%0,%1,%2,%3}, {%4,%5,%6,%7}, {%8,%9}, {%0,%1,%2,%3};" \
        : "+f"((d)[0]), "+f"((d)[1]), "+f"((d)[2]), "+f"((d)[3]) \
        : "r"((a)[0]), "r"((a)[1]), "r"((a)[2]), "r"((a)[3]), \
          "r"((b)[0]), "r"((b)[1]))

#define LDSM4(r0, r1, r2, r3, addr) \
    asm volatile("ldmatrix.sync.aligned.m8n8.x4.shared.b16 {%0,%1,%2,%3}, [%4];" \
        : "=r"(r0), "=r"(r1), "=r"(r2), "=r"(r3) : "r"(addr))

// ===================== mma.sync fp16 GEMM (fp32 accum) =====================
#define TSTRH 40
#define T_HALFS (128 * TSTRH)
#define GEMM_SMEM_BYTES ((6 * T_HALFS) * 2)         // 61440 B

template <int EPI, int OUTH>
__global__ __launch_bounds__(256, 2) void gemm_mma(
    const __half* __restrict__ A, const __half* __restrict__ Wt,
    const float* __restrict__ bias, const float* __restrict__ Add,
    void* __restrict__ OutV, int Nn, int K)
{
    extern __shared__ __half dynh[];
    __half* Asb = dynh;
    __half* Bsb = dynh + 3 * T_HALFS;
    float*  OutF = (float*)OutV;
    __half* OutH = (__half*)OutV;

    const int tid  = threadIdx.x;
    const int lane = tid & 31, warp = tid >> 5;
    const int wm = (warp >> 2) * 64, wn = (warp & 3) * 32;
    const int g4 = lane >> 2, tg = lane & 3;
    const int m0 = blockIdx.x * 128, n0 = blockIdx.y * 128;

    const int lrow = lane & 15;
    const int lkof = (lane >> 4) * 8;
    const int bnof = (lane >> 4) * 8 + (lane & 7);
    const int bkof = ((lane >> 3) & 1) * 8;

    const int r = tid & 127;
    const int q = tid >> 7;

    float acc[4][4][4];
#pragma unroll
    for (int a = 0; a < 4; a++)
#pragma unroll
        for (int b = 0; b < 4; b++)
#pragma unroll
            for (int c = 0; c < 4; c++) acc[a][b][c] = 0.f;

    const int nkc = K >> 5;
    const __half* srcA = A  + (size_t)(m0 + r) * K + q * 8;
    const __half* srcB = Wt + (size_t)(n0 + r) * K + q * 8;

#define ISSUE(kc, bufi) do {                                                  \
        int _k0 = (kc) << 5;                                                  \
        __half* _As = Asb + (bufi) * T_HALFS + r * TSTRH + q * 8;             \
        __half* _Bs = Bsb + (bufi) * T_HALFS + r * TSTRH + q * 8;             \
        CP16(smem_u32(_As),      srcA + _k0);                                 \
        CP16(smem_u32(_As + 16), srcA + _k0 + 16);                            \
        CP16(smem_u32(_Bs),      srcB + _k0);                                 \
        CP16(smem_u32(_Bs + 16), srcB + _k0 + 16);                            \
        CP_COMMIT();                                                          \
    } while (0)

    ISSUE(0, 0);
    ISSUE(1, 1);

    int buf = 0;
    for (int kc = 0; kc < nkc; kc++) {
        if (kc + 2 < nkc) CP_WAIT1(); else CP_WAIT0();
        __syncthreads();
        if (kc + 2 < nkc) {
            int nb = kc + 2 - ((kc + 2) / 3) * 3;
            ISSUE(kc + 2, nb);
        }
        const __half* As = Asb + buf * T_HALFS;
        const __half* Bs = Bsb + buf * T_HALFS;

#pragma unroll
        for (int s = 0; s < 2; s++) {
            uint32_t af[4][4], bf[4][2];
#pragma unroll
            for (int mt = 0; mt < 4; mt++) {
                uint32_t ad = smem_u32(As + (wm + mt * 16 + lrow) * TSTRH + s * 16 + lkof);
                LDSM4(af[mt][0], af[mt][1], af[mt][2], af[mt][3], ad);
            }
#pragma unroll
            for (int p = 0; p < 2; p++) {
                uint32_t ad = smem_u32(Bs + (wn + p * 16 + bnof) * TSTRH + s * 16 + bkof);
                LDSM4(bf[2 * p][0], bf[2 * p][1], bf[2 * p + 1][0], bf[2 * p + 1][1], ad);
            }
#pragma unroll
            for (int mt = 0; mt < 4; mt++)
#pragma unroll
                for (int nt = 0; nt < 4; nt++)
                    MMA_F16(acc[mt][nt], af[mt], bf[nt]);
        }
        buf++; if (buf == 3) buf = 0;
    }
#undef ISSUE

#pragma unroll
    for (int mt = 0; mt < 4; mt++) {
        int row = m0 + wm + mt * 16 + g4;
#pragma unroll
        for (int nt = 0; nt < 4; nt++) {
            int col = n0 + wn + nt * 8 + tg * 2;
            if (col < Nn) {
                float b0 = __ldg(&bias[col]), b1 = __ldg(&bias[col + 1]);
                float v0 = acc[mt][nt][0] + b0;
                float v1 = acc[mt][nt][1] + b1;
                float v2 = acc[mt][nt][2] + b0;
                float v3 = acc[mt][nt][3] + b1;
                if (EPI == 1) {
                    v0 = 0.5f * v0 * (1.f + erff(v0 * 0.70710678118654752f));
                    v1 = 0.5f * v1 * (1.f + erff(v1 * 0.70710678118654752f));
                    v2 = 0.5f * v2 * (1.f + erff(v2 * 0.70710678118654752f));
                    v3 = 0.5f * v3 * (1.f + erff(v3 * 0.70710678118654752f));
                }
                if (EPI == 2) {
                    v0 += Add[(size_t)row * Nn + col];
                    v1 += Add[(size_t)row * Nn + col + 1];
                    v2 += Add[(size_t)(row + 8) * Nn + col];
                    v3 += Add[(size_t)(row + 8) * Nn + col + 1];
                }
                if (OUTH) {
                    *reinterpret_cast<__half2*>(OutH + (size_t)row * Nn + col)       = __floats2half2_rn(v0, v1);
                    *reinterpret_cast<__half2*>(OutH + (size_t)(row + 8) * Nn + col) = __floats2half2_rn(v2, v3);
                } else {
                    *reinterpret_cast<float2*>(OutF + (size_t)row * Nn + col)       = make_float2(v0, v1);
                    *reinterpret_cast<float2*>(OutF + (size_t)(row + 8) * Nn + col) = make_float2(v2, v3);
                }
            }
        }
    }
}

// ---------------- one-shot weight prep: all transposes + bias ------------
__global__ void transpose_all(
    const float* __restrict__ vproj_w, const float* __restrict__ om_w,
    const float* __restrict__ oproj_w, const float* __restrict__ fc1_w,
    const float* __restrict__ fc2_w,
    const float* __restrict__ vproj_b, const float* __restrict__ om_b,
    __half* __restrict__ wvm, __half* __restrict__ wo,
    __half* __restrict__ w1, __half* __restrict__ w2,
    float* __restrict__ bvm)
{
    __shared__ float s[32][33];
    int t = blockIdx.x;
    int tx = threadIdx.x, ty = threadIdx.y;
    int tid = ty * 32 + tx;

    if (t == 1572) {
        for (int i = tid; i < 768; i += 256)
            bvm[i] = (i < CC) ? vproj_b[i] : ((i < VOC) ? om_b[i - CC] : 0.f);
        return;
    }

    const float* src; __half* dst;
    int Kdim, Ndim, ntiles_n, rowoff, dstK;
    if (t < 144)       { src = vproj_w; dst = wvm; Kdim = CC;  Ndim = CC;  ntiles_n = 12; rowoff = 0;   dstK = CC;  }
    else if (t < 276)  { t -= 144;  src = om_w;   dst = wvm; Kdim = CC;  Ndim = OMC; ntiles_n = 11; rowoff = CC;  dstK = CC;  }
    else if (t < 420)  { t -= 276;  src = oproj_w; dst = wo;  Kdim = CC;  Ndim = CC;  ntiles_n = 12; rowoff = 0;   dstK = CC;  }
    else if (t < 996)  { t -= 420;  src = fc1_w;  dst = w1;  Kdim = CC;  Ndim = HID; ntiles_n = 48; rowoff = 0;   dstK = CC;  }
    else               { t -= 996;  src = fc2_w;  dst = w2;  Kdim = HID; Ndim = CC;  ntiles_n = 12; rowoff = 0;   dstK = HID; }

    int n0 = (t % ntiles_n) * 32;
    int k0 = (t / ntiles_n) * 32;

#pragma unroll
    for (int r = 0; r < 4; r++) {
        int k = k0 + ty + 8 * r, n = n0 + tx;
        s[ty + 8 * r][tx] = (k < Kdim && n < Ndim) ? src[(size_t)k * Ndim + n] : 0.f;
    }
    __syncthreads();
#pragma unroll
    for (int r = 0; r < 4; r++) {
        int n = n0 + ty + 8 * r, k = k0 + tx;
        if (n < Ndim && k < Kdim)
            dst[(size_t)(n + rowoff) * dstK + k] = __float2half(s[tx][ty + 8 * r]);
    }
}

// ---------------- LN1: transpose x + layernorm (tn -> fp16) ----------------
__global__ void ln1_kernel(const float* __restrict__ x,
                           const float* __restrict__ gam,
                           const float* __restrict__ bet,
                           float* __restrict__ xp, __half* __restrict__ tn)
{
    int warp = (blockIdx.x * blockDim.x + threadIdx.x) >> 5;
    if (warp >= NTOK) return;
    int lane = threadIdx.x & 31;
    int b  = warp / HWW;
    int hw = warp - b * HWW;
    const float* xb = x + (size_t)b * CC * HWW + hw;

    float v[12];
#pragma unroll
    for (int i = 0; i < 12; i++) v[i] = xb[(size_t)(lane + 32 * i) * HWW];
    float s = 0.f;
#pragma unroll
    for (int i = 0; i < 12; i++) s += v[i];
#pragma unroll
    for (int o = 16; o; o >>= 1) s += __shfl_xor_sync(0xffffffffu, s, o);
    float mu = s * (1.0f / CC);
    float q = 0.f;
#pragma unroll
    for (int i = 0; i < 12; i++) { float d = v[i] - mu; q += d * d; }
#pragma unroll
    for (int o = 16; o; o >>= 1) q += __shfl_xor_sync(0xffffffffu, q, o);
    float rs = rsqrtf(q * (1.0f / CC) + EPSV);
    size_t base = (size_t)warp * CC;
#pragma unroll
    for (int i = 0; i < 12; i++) {
        int c = lane + 32 * i;
        xp[base + c] = v[i];
        tn[base + c] = __float2half((v[i] - mu) * rs * gam[c] + bet[c]);
    }
}

// ---------------- LN2 (out -> fp16) ----------------
__global__ void ln2_kernel(const float* __restrict__ res,
                           const float* __restrict__ gam,
                           const float* __restrict__ bet,
                           __half* __restrict__ outp)
{
    int warp = (blockIdx.x * blockDim.x + threadIdx.x) >> 5;
    if (warp >= NTOK) return;
    int lane = threadIdx.x & 31;
    size_t base = (size_t)warp * CC;
    float v[12];
#pragma unroll
    for (int i = 0; i < 12; i++) v[i] = res[base + lane + 32 * i];
    float s = 0.f;
#pragma unroll
    for (int i = 0; i < 12; i++) s += v[i];
#pragma unroll
    for (int o = 16; o; o >>= 1) s += __shfl_xor_sync(0xffffffffu, s, o);
    float mu = s * (1.0f / CC);
    float q = 0.f;
#pragma unroll
    for (int i = 0; i < 12; i++) { float d = v[i] - mu; q += d * d; }
#pragma unroll
    for (int o = 16; o; o >>= 1) q += __shfl_xor_sync(0xffffffffu, q, o);
    float rs = rsqrtf(q * (1.0f / CC) + EPSV);
#pragma unroll
    for (int i = 0; i < 12; i++) {
        int c = lane + 32 * i;
        outp[base + c] = __float2half((v[i] - mu) * rs * gam[c] + bet[c]);
    }
}

// ---------------- DCNv4 sampling: 2 tokens/block, 96 thr/token -----------
// warp = 4 groups (8 lanes each); lane = 4 channels via uint2 (4x half)
__global__ __launch_bounds__(192) void dcn_kernel(
    const __half* __restrict__ vo,
    __half* __restrict__ outp)
{
    __shared__ float s_om[2][OMC];
    const int n0 = blockIdx.x * 2;
    const int tid = threadIdx.x;
    for (int i = tid; i < 2 * OMC; i += 192) {
        int t = i / OMC, c = i - t * OMC;
        s_om[t][c] = __half2float(vo[(size_t)(n0 + t) * VOC + CC + c]);
    }
    __syncthreads();

    const int sub = tid / 96, tt = tid - sub * 96;
    const int n = n0 + sub;
    const int w = tt >> 5, lane = tt & 31;
    const int g = w * 4 + (lane >> 3);
    const int ch = (lane & 7) * 4;
    const int b = n / HWW;
    const int hw = n - b * HWW;
    const int ii = hw / WW;
    const int jj = hw - ii * WW;

    const float* omb = s_om[sub] + g * 27;
    const __half* vb = vo + (size_t)b * HWW * VOC + g * GCH + ch;

    float a0 = 0.f, a1 = 0.f, a2 = 0.f, a3 = 0.f;
#pragma unroll
    for (int k = 0; k < KK2; k++) {
        float dx = omb[2 * k];
        float dy = omb[2 * k + 1];
        float mk = omb[18 + k];
        float px = (float)jj + (float)(k % 3 - 1) + dx;
        float py = (float)ii + (float)(k / 3 - 1) + dy;
        float x0f = floorf(px), y0f = floorf(py);
        float tx = px - x0f, ty = py - y0f;
        int x0 = (int)x0f, y0 = (int)y0f;
        int x1 = x0 + 1,   y1 = y0 + 1;
        bool vx0 = (x0 >= 0) & (x0 < WW);
        bool vx1 = (x1 >= 0) & (x1 < WW);
        bool vy0 = (y0 >= 0) & (y0 < HH);
        bool vy1 = (y1 >= 0) & (y1 < HH);
        int row0 = y0 * (WW * VOC), row1 = row0 + WW * VOC;

        float w00 = (1.f - tx) * (1.f - ty) * mk;
        float w01 = tx * (1.f - ty) * mk;
        float w10 = (1.f - tx) * ty * mk;
        float w11 = tx * ty * mk;

#define GATH(cond, off, wgt) do {                                             \
        if (cond) {                                                           \
            uint2 u = __ldg(reinterpret_cast<const uint2*>(vb + (off)));      \
            float2 f0 = __half22float2(*reinterpret_cast<__half2*>(&u.x));    \
            float2 f1 = __half22float2(*reinterpret_cast<__half2*>(&u.y));    \
            a0 += f0.x * (wgt); a1 += f0.y * (wgt);                           \
            a2 += f1.x * (wgt); a3 += f1.y * (wgt);                           \
        }                                                                     \
    } while (0)
        GATH(vy0 && vx0, row0 + x0 * VOC, w00);
        GATH(vy0 && vx1, row0 + x1 * VOC, w01);
        GATH(vy1 && vx0, row1 + x0 * VOC, w10);
        GATH(vy1 && vx1, row1 + x1 * VOC, w11);
#undef GATH
    }
    __half* op = outp + (size_t)n * CC + g * GCH + ch;
    *reinterpret_cast<__half2*>(op)     = __floats2half2_rn(a0, a1);
    *reinterpret_cast<__half2*>(op + 2) = __floats2half2_rn(a2, a3);
}

// ---------------- final transpose ----------------
__global__ void transpose_out(const float* __restrict__ fin,
                              float* __restrict__ outp)
{
    __shared__ float s[32][33];
    int b   = blockIdx.z;
    int hw0 = blockIdx.x * 32;
    int c0  = blockIdx.y * 32;
    int tx = threadIdx.x, ty = threadIdx.y;
#pragma unroll
    for (int r = 0; r < 4; r++) {
        int hw = hw0 + ty + 8 * r;
        s[ty + 8 * r][tx] = fin[(size_t)(b * HWW + hw) * CC + c0 + tx];
    }
    __syncthreads();
#pragma unroll
    for (int r = 0; r < 4; r++) {
        int c = c0 + ty + 8 * r;
        outp[(size_t)(b * CC + c) * HWW + hw0 + tx] = s[tx][ty + 8 * r];
    }
}

// --------------------------------------------------------------------------
extern "C" void kernel_launch(void* const* d_in, const int* in_sizes, int n_in,
                              void* d_out, int out_size)
{
    const float* x       = (const float*)d_in[0];
    const float* ln1_g   = (const float*)d_in[1];
    const float* ln1_b   = (const float*)d_in[2];
    const float* vproj_w = (const float*)d_in[3];
    const float* vproj_b = (const float*)d_in[4];
    const float* om_w    = (const float*)d_in[5];
    const float* om_b    = (const float*)d_in[6];
    const float* oproj_w = (const float*)d_in[7];
    const float* oproj_b = (const float*)d_in[8];
    const float* ln2_g   = (const float*)d_in[9];
    const float* ln2_b   = (const float*)d_in[10];
    const float* fc1_w   = (const float*)d_in[11];
    const float* fc1_b   = (const float*)d_in[12];
    const float* fc2_w   = (const float*)d_in[13];
    const float* fc2_b   = (const float*)d_in[14];
    float* outp = (float*)d_out;

    float *xp, *res, *fin, *bvm;
    __half *tn, *vo, *dcn, *ln2o, *hid, *wvm, *wo, *w1, *w2;
    cudaGetSymbolAddress((void**)&xp,  g_xp);
    cudaGetSymbolAddress((void**)&tn,  g_tn);
    cudaGetSymbolAddress((void**)&vo,  g_vo);
    cudaGetSymbolAddress((void**)&dcn, g_dcn);
    cudaGetSymbolAddress((void**)&res, g_res);
    cudaGetSymbolAddress((void**)&ln2o, g_ln2);
    cudaGetSymbolAddress((void**)&hid, g_hid);
    cudaGetSymbolAddress((void**)&fin, g_fin);
    cudaGetSymbolAddress((void**)&wvm, g_wvm);
    cudaGetSymbolAddress((void**)&bvm, g_bvm);
    cudaGetSymbolAddress((void**)&wo,  g_wo);
    cudaGetSymbolAddress((void**)&w1,  g_w1);
    cudaGetSymbolAddress((void**)&w2,  g_w2);

    static int attr_done = 0;
    if (!attr_done) {
        cudaFuncSetAttribute(gemm_mma<0, 1>, cudaFuncAttributeMaxDynamicSharedMemorySize, GEMM_SMEM_BYTES);
        cudaFuncSetAttribute(gemm_mma<1, 1>, cudaFuncAttributeMaxDynamicSharedMemorySize, GEMM_SMEM_BYTES);
        cudaFuncSetAttribute(gemm_mma<2, 0>, cudaFuncAttributeMaxDynamicSharedMemorySize, GEMM_SMEM_BYTES);
        attr_done = 1;
    }

    dim3 tb(32, 8);
    // 0. all weight transposes + bias combine, one launch
    transpose_all<<<1573, tb>>>(vproj_w, om_w, oproj_w, fc1_w, fc2_w,
                                vproj_b, om_b, wvm, wo, w1, w2, bvm);
    // 1. transpose + LN1
    ln1_kernel<<<NTOK / 8, 256>>>(x, ln1_g, ln1_b, xp, tn);
    // 2. vo = tn @ [vproj|om] + b   (fp16 out, N=708 of 768-padded)
    gemm_mma<0, 1><<<dim3(NTOK / 128, 6), 256, GEMM_SMEM_BYTES>>>(tn, wvm, bvm, nullptr, vo, VOC, CC);
    // 3. DCN sampling (2 tokens/block)
    dcn_kernel<<<NTOK / 2, 192>>>(vo, dcn);
    // 4. res = xp + dcn @ oproj_w + b  (fp32 out)
    gemm_mma<2, 0><<<dim3(NTOK / 128, 3), 256, GEMM_SMEM_BYTES>>>(dcn, wo, oproj_b, xp, res, CC, CC);
    // 5. LN2 (fp16 out)
    ln2_kernel<<<NTOK / 8, 256>>>(res, ln2_g, ln2_b, ln2o);
    // 6. hid = gelu(ln2o @ fc1_w + b)  (fp16 out)
    gemm_mma<1, 1><<<dim3(NTOK / 128, HID / 128), 256, GEMM_SMEM_BYTES>>>(ln2o, w1, fc1_b, nullptr, hid, HID, CC);
    // 7. fin = res + hid @ fc2_w + b   (fp32 out)
    gemm_mma<2, 0><<<dim3(NTOK / 128, 3), 256, GEMM_SMEM_BYTES>>>(hid, w2, fc2_b, res, fin, CC, HID);
    // 8. transpose back
    transpose_out<<<dim3(HWW / 32, CC / 32, BB), tb>>>(fin, outp);
}

// round 15
// speedup vs baseline: 1.6778x; 1.0176x over previous
#include <cuda_runtime.h>
#include <cuda_fp16.h>
#include <math.h>
#include <stdint.h>

#define BB   4
#define CC   384
#define HH   56
#define WW   56
#define HWW  3136
#define NTOK 12544
#define GG   12
#define GCH  32
#define KK2  9
#define OMC  324
#define HID  1536
#define EPSV 1e-5f
#define VOC  708          // valid width: val(384) + om(324)
#define VOCP 712          // padded row stride (16B-aligned rows)

// ---------------- scratch (device globals; no allocation) ----------------
__device__ float  g_xp [NTOK * CC];
__device__ __half g_tn [NTOK * CC];
__device__ __half g_vo [NTOK * VOCP];    // val | om combined, fp16, padded stride
__device__ __half g_dcn[NTOK * CC];
__device__ float  g_res[NTOK * CC];
__device__ __half g_ln2[NTOK * CC];
__device__ __half g_hid[NTOK * HID];
__device__ float  g_fin[NTOK * CC];
// transposed weights [N,K] row-major, fp16 (zero-init where never written)
__device__ __half g_wvm[768 * CC];       // vproj^T rows 0..383, om^T rows 384..707
__device__ float  g_bvm[768];            // combined bias
__device__ __half g_wo [CC * CC];
__device__ __half g_w1 [HID * CC];
__device__ __half g_w2 [CC * HID];

// ===================== helpers =====================
__device__ __forceinline__ uint32_t smem_u32(const void* p) {
    uint32_t a;
    asm("{ .reg .u64 t; cvta.to.shared.u64 t, %1; cvt.u32.u64 %0, t; }"
        : "=r"(a) : "l"(p));
    return a;
}
#define CP16(dst, src) \
    asm volatile("cp.async.ca.shared.global [%0], [%1], 16;" \
                 :: "r"(dst), "l"(src))
#define CP_COMMIT() asm volatile("cp.async.commit_group;")
#define CP_WAIT1()  asm volatile("cp.async.wait_group 1;")
#define CP_WAIT0()  asm volatile("cp.async.wait_group 0;")

#define MMA_F16(d, a, b) \
    asm volatile("mma.sync.aligned.m16n8k16.row.col.f32.f16.f16.f32 " \
        "{%0,%1,%2,%3}, {%4,%5,%6,%7}, {%8,%9}, {%0,%1,%2,%3};" \
        : "+f"((d)[0]), "+f"((d)[1]), "+f"((d)[2]), "+f"((d)[3]) \
        : "r"((a)[0]), "r"((a)[1]), "r"((a)[2]), "r"((a)[3]), \
          "r"((b)[0]), "r"((b)[1]))

#define LDSM4(r0, r1, r2, r3, addr) \
    asm volatile("ldmatrix.sync.aligned.m8n8.x4.shared.b16 {%0,%1,%2,%3}, [%4];" \
        : "=r"(r0), "=r"(r1), "=r"(r2), "=r"(r3) : "r"(addr))

// ===================== mma.sync fp16 GEMM (fp32 accum) =====================
#define TSTRH 40
#define T_HALFS (128 * TSTRH)
#define GEMM_SMEM_BYTES ((6 * T_HALFS) * 2)         // 61440 B

template <int EPI, int OUTH>
__global__ __launch_bounds__(256, 2) void gemm_mma(
    const __half* __restrict__ A, const __half* __restrict__ Wt,
    const float* __restrict__ bias, const float* __restrict__ Add,
    void* __restrict__ OutV, int Nn, int ldo, int K)
{
    extern __shared__ __half dynh[];
    __half* Asb = dynh;
    __half* Bsb = dynh + 3 * T_HALFS;
    float*  OutF = (float*)OutV;
    __half* OutH = (__half*)OutV;

    const int tid  = threadIdx.x;
    const int lane = tid & 31, warp = tid >> 5;
    const int wm = (warp >> 2) * 64, wn = (warp & 3) * 32;
    const int g4 = lane >> 2, tg = lane & 3;
    const int m0 = blockIdx.x * 128, n0 = blockIdx.y * 128;

    const int lrow = lane & 15;
    const int lkof = (lane >> 4) * 8;
    const int bnof = (lane >> 4) * 8 + (lane & 7);
    const int bkof = ((lane >> 3) & 1) * 8;

    const int r = tid & 127;
    const int q = tid >> 7;

    float acc[4][4][4];
#pragma unroll
    for (int a = 0; a < 4; a++)
#pragma unroll
        for (int b = 0; b < 4; b++)
#pragma unroll
            for (int c = 0; c < 4; c++) acc[a][b][c] = 0.f;

    const int nkc = K >> 5;
    const __half* srcA = A  + (size_t)(m0 + r) * K + q * 8;
    const __half* srcB = Wt + (size_t)(n0 + r) * K + q * 8;

#define ISSUE(kc, bufi) do {                                                  \
        int _k0 = (kc) << 5;                                                  \
        __half* _As = Asb + (bufi) * T_HALFS + r * TSTRH + q * 8;             \
        __half* _Bs = Bsb + (bufi) * T_HALFS + r * TSTRH + q * 8;             \
        CP16(smem_u32(_As),      srcA + _k0);                                 \
        CP16(smem_u32(_As + 16), srcA + _k0 + 16);                            \
        CP16(smem_u32(_Bs),      srcB + _k0);                                 \
        CP16(smem_u32(_Bs + 16), srcB + _k0 + 16);                            \
        CP_COMMIT();                                                          \
    } while (0)

    ISSUE(0, 0);
    ISSUE(1, 1);

    int buf = 0;
    for (int kc = 0; kc < nkc; kc++) {
        if (kc + 2 < nkc) CP_WAIT1(); else CP_WAIT0();
        __syncthreads();
        if (kc + 2 < nkc) {
            int nb = kc + 2 - ((kc + 2) / 3) * 3;
            ISSUE(kc + 2, nb);
        }
        const __half* As = Asb + buf * T_HALFS;
        const __half* Bs = Bsb + buf * T_HALFS;

#pragma unroll
        for (int s = 0; s < 2; s++) {
            uint32_t af[4][4], bf[4][2];
#pragma unroll
            for (int mt = 0; mt < 4; mt++) {
                uint32_t ad = smem_u32(As + (wm + mt * 16 + lrow) * TSTRH + s * 16 + lkof);
                LDSM4(af[mt][0], af[mt][1], af[mt][2], af[mt][3], ad);
            }
#pragma unroll
            for (int p = 0; p < 2; p++) {
                uint32_t ad = smem_u32(Bs + (wn + p * 16 + bnof) * TSTRH + s * 16 + bkof);
                LDSM4(bf[2 * p][0], bf[2 * p][1], bf[2 * p + 1][0], bf[2 * p + 1][1], ad);
            }
#pragma unroll
            for (int mt = 0; mt < 4; mt++)
#pragma unroll
                for (int nt = 0; nt < 4; nt++)
                    MMA_F16(acc[mt][nt], af[mt], bf[nt]);
        }
        buf++; if (buf == 3) buf = 0;
    }
#undef ISSUE

#pragma unroll
    for (int mt = 0; mt < 4; mt++) {
        int row = m0 + wm + mt * 16 + g4;
#pragma unroll
        for (int nt = 0; nt < 4; nt++) {
            int col = n0 + wn + nt * 8 + tg * 2;
            if (col < Nn) {
                float b0 = __ldg(&bias[col]), b1 = __ldg(&bias[col + 1]);
                float v0 = acc[mt][nt][0] + b0;
                float v1 = acc[mt][nt][1] + b1;
                float v2 = acc[mt][nt][2] + b0;
                float v3 = acc[mt][nt][3] + b1;
                if (EPI == 1) {
                    v0 = 0.5f * v0 * (1.f + erff(v0 * 0.70710678118654752f));
                    v1 = 0.5f * v1 * (1.f + erff(v1 * 0.70710678118654752f));
                    v2 = 0.5f * v2 * (1.f + erff(v2 * 0.70710678118654752f));
                    v3 = 0.5f * v3 * (1.f + erff(v3 * 0.70710678118654752f));
                }
                if (EPI == 2) {
                    v0 += Add[(size_t)row * ldo + col];
                    v1 += Add[(size_t)row * ldo + col + 1];
                    v2 += Add[(size_t)(row + 8) * ldo + col];
                    v3 += Add[(size_t)(row + 8) * ldo + col + 1];
                }
                if (OUTH) {
                    *reinterpret_cast<__half2*>(OutH + (size_t)row * ldo + col)       = __floats2half2_rn(v0, v1);
                    *reinterpret_cast<__half2*>(OutH + (size_t)(row + 8) * ldo + col) = __floats2half2_rn(v2, v3);
                } else {
                    *reinterpret_cast<float2*>(OutF + (size_t)row * ldo + col)       = make_float2(v0, v1);
                    *reinterpret_cast<float2*>(OutF + (size_t)(row + 8) * ldo + col) = make_float2(v2, v3);
                }
            }
        }
    }
}

// ---------------- one-shot weight prep: all transposes + bias ------------
__global__ void transpose_all(
    const float* __restrict__ vproj_w, const float* __restrict__ om_w,
    const float* __restrict__ oproj_w, const float* __restrict__ fc1_w,
    const float* __restrict__ fc2_w,
    const float* __restrict__ vproj_b, const float* __restrict__ om_b,
    __half* __restrict__ wvm, __half* __restrict__ wo,
    __half* __restrict__ w1, __half* __restrict__ w2,
    float* __restrict__ bvm)
{
    __shared__ float s[32][33];
    int t = blockIdx.x;
    int tx = threadIdx.x, ty = threadIdx.y;
    int tid = ty * 32 + tx;

    if (t == 1572) {
        for (int i = tid; i < 768; i += 256)
            bvm[i] = (i < CC) ? vproj_b[i] : ((i < VOC) ? om_b[i - CC] : 0.f);
        return;
    }

    const float* src; __half* dst;
    int Kdim, Ndim, ntiles_n, rowoff, dstK;
    if (t < 144)       { src = vproj_w; dst = wvm; Kdim = CC;  Ndim = CC;  ntiles_n = 12; rowoff = 0;   dstK = CC;  }
    else if (t < 276)  { t -= 144;  src = om_w;   dst = wvm; Kdim = CC;  Ndim = OMC; ntiles_n = 11; rowoff = CC;  dstK = CC;  }
    else if (t < 420)  { t -= 276;  src = oproj_w; dst = wo;  Kdim = CC;  Ndim = CC;  ntiles_n = 12; rowoff = 0;   dstK = CC;  }
    else if (t < 996)  { t -= 420;  src = fc1_w;  dst = w1;  Kdim = CC;  Ndim = HID; ntiles_n = 48; rowoff = 0;   dstK = CC;  }
    else               { t -= 996;  src = fc2_w;  dst = w2;  Kdim = HID; Ndim = CC;  ntiles_n = 12; rowoff = 0;   dstK = HID; }

    int n0 = (t % ntiles_n) * 32;
    int k0 = (t / ntiles_n) * 32;

#pragma unroll
    for (int r = 0; r < 4; r++) {
        int k = k0 + ty + 8 * r, n = n0 + tx;
        s[ty + 8 * r][tx] = (k < Kdim && n < Ndim) ? src[(size_t)k * Ndim + n] : 0.f;
    }
    __syncthreads();
#pragma unroll
    for (int r = 0; r < 4; r++) {
        int n = n0 + ty + 8 * r, k = k0 + tx;
        if (n < Ndim && k < Kdim)
            dst[(size_t)(n + rowoff) * dstK + k] = __float2half(s[tx][ty + 8 * r]);
    }
}

// ---------------- LN1: transpose x + layernorm (tn -> fp16) ----------------
__global__ void ln1_kernel(const float* __restrict__ x,
                           const float* __restrict__ gam,
                           const float* __restrict__ bet,
                           float* __restrict__ xp, __half* __restrict__ tn)
{
    int warp = (blockIdx.x * blockDim.x + threadIdx.x) >> 5;
    if (warp >= NTOK) return;
    int lane = threadIdx.x & 31;
    int b  = warp / HWW;
    int hw = warp - b * HWW;
    const float* xb = x + (size_t)b * CC * HWW + hw;

    float v[12];
#pragma unroll
    for (int i = 0; i < 12; i++) v[i] = xb[(size_t)(lane + 32 * i) * HWW];
    float s = 0.f;
#pragma unroll
    for (int i = 0; i < 12; i++) s += v[i];
#pragma unroll
    for (int o = 16; o; o >>= 1) s += __shfl_xor_sync(0xffffffffu, s, o);
    float mu = s * (1.0f / CC);
    float q = 0.f;
#pragma unroll
    for (int i = 0; i < 12; i++) { float d = v[i] - mu; q += d * d; }
#pragma unroll
    for (int o = 16; o; o >>= 1) q += __shfl_xor_sync(0xffffffffu, q, o);
    float rs = rsqrtf(q * (1.0f / CC) + EPSV);
    size_t base = (size_t)warp * CC;
#pragma unroll
    for (int i = 0; i < 12; i++) {
        int c = lane + 32 * i;
        xp[base + c] = v[i];
        tn[base + c] = __float2half((v[i] - mu) * rs * gam[c] + bet[c]);
    }
}

// ---------------- LN2 (out -> fp16) ----------------
__global__ void ln2_kernel(const float* __restrict__ res,
                           const float* __restrict__ gam,
                           const float* __restrict__ bet,
                           __half* __restrict__ outp)
{
    int warp = (blockIdx.x * blockDim.x + threadIdx.x) >> 5;
    if (warp >= NTOK) return;
    int lane = threadIdx.x & 31;
    size_t base = (size_t)warp * CC;
    float v[12];
#pragma unroll
    for (int i = 0; i < 12; i++) v[i] = res[base + lane + 32 * i];
    float s = 0.f;
#pragma unroll
    for (int i = 0; i < 12; i++) s += v[i];
#pragma unroll
    for (int o = 16; o; o >>= 1) s += __shfl_xor_sync(0xffffffffu, s, o);
    float mu = s * (1.0f / CC);
    float q = 0.f;
#pragma unroll
    for (int i = 0; i < 12; i++) { float d = v[i] - mu; q += d * d; }
#pragma unroll
    for (int o = 16; o; o >>= 1) q += __shfl_xor_sync(0xffffffffu, q, o);
    float rs = rsqrtf(q * (1.0f / CC) + EPSV);
#pragma unroll
    for (int i = 0; i < 12; i++) {
        int c = lane + 32 * i;
        outp[base + c] = __float2half((v[i] - mu) * rs * gam[c] + bet[c]);
    }
}

// ---------------- DCNv4 sampling: 4 tokens/block, 48 thr/token -----------
// group = tt>>2 (4 lanes per group), lane = 8 channels via uint4 (16B)
__global__ __launch_bounds__(192) void dcn_kernel(
    const __half* __restrict__ vo,
    __half* __restrict__ outp)
{
    __shared__ float s_om[4][OMC];
    const int n0 = blockIdx.x * 4;
    const int tid = threadIdx.x;
    for (int i = tid; i < 4 * OMC; i += 192) {
        int t = i / OMC, c = i - t * OMC;
        s_om[t][c] = __half2float(vo[(size_t)(n0 + t) * VOCP + CC + c]);
    }
    __syncthreads();

    const int sub = tid / 48, tt = tid - sub * 48;
    const int n = n0 + sub;
    const int g = tt >> 2;
    const int ch = (tt & 3) * 8;
    const int b = n / HWW;
    const int hw = n - b * HWW;
    const int ii = hw / WW;
    const int jj = hw - ii * WW;

    const float* omb = s_om[sub] + g * 27;
    const __half* vb = vo + (size_t)b * HWW * VOCP + g * GCH + ch;

    float a0 = 0.f, a1 = 0.f, a2 = 0.f, a3 = 0.f;
    float a4 = 0.f, a5 = 0.f, a6 = 0.f, a7 = 0.f;
#pragma unroll
    for (int k = 0; k < KK2; k++) {
        float dx = omb[2 * k];
        float dy = omb[2 * k + 1];
        float mk = omb[18 + k];
        float px = (float)jj + (float)(k % 3 - 1) + dx;
        float py = (float)ii + (float)(k / 3 - 1) + dy;
        float x0f = floorf(px), y0f = floorf(py);
        float tx = px - x0f, ty = py - y0f;
        int x0 = (int)x0f, y0 = (int)y0f;
        int x1 = x0 + 1,   y1 = y0 + 1;
        bool vx0 = (x0 >= 0) & (x0 < WW);
        bool vx1 = (x1 >= 0) & (x1 < WW);
        bool vy0 = (y0 >= 0) & (y0 < HH);
        bool vy1 = (y1 >= 0) & (y1 < HH);
        int row0 = y0 * (WW * VOCP), row1 = row0 + WW * VOCP;

        float w00 = (1.f - tx) * (1.f - ty) * mk;
        float w01 = tx * (1.f - ty) * mk;
        float w10 = (1.f - tx) * ty * mk;
        float w11 = tx * ty * mk;

#define GATH(cond, off, wgt) do {                                             \
        if (cond) {                                                           \
            uint4 u = __ldg(reinterpret_cast<const uint4*>(vb + (off)));      \
            float2 f0 = __half22float2(*reinterpret_cast<__half2*>(&u.x));    \
            float2 f1 = __half22float2(*reinterpret_cast<__half2*>(&u.y));    \
            float2 f2 = __half22float2(*reinterpret_cast<__half2*>(&u.z));    \
            float2 f3 = __half22float2(*reinterpret_cast<__half2*>(&u.w));    \
            a0 += f0.x * (wgt); a1 += f0.y * (wgt);                           \
            a2 += f1.x * (wgt); a3 += f1.y * (wgt);                           \
            a4 += f2.x * (wgt); a5 += f2.y * (wgt);                           \
            a6 += f3.x * (wgt); a7 += f3.y * (wgt);                           \
        }                                                                     \
    } while (0)
        GATH(vy0 && vx0, row0 + x0 * VOCP, w00);
        GATH(vy0 && vx1, row0 + x1 * VOCP, w01);
        GATH(vy1 && vx0, row1 + x0 * VOCP, w10);
        GATH(vy1 && vx1, row1 + x1 * VOCP, w11);
#undef GATH
    }
    uint4 out;
    *reinterpret_cast<__half2*>(&out.x) = __floats2half2_rn(a0, a1);
    *reinterpret_cast<__half2*>(&out.y) = __floats2half2_rn(a2, a3);
    *reinterpret_cast<__half2*>(&out.z) = __floats2half2_rn(a4, a5);
    *reinterpret_cast<__half2*>(&out.w) = __floats2half2_rn(a6, a7);
    *reinterpret_cast<uint4*>(outp + (size_t)n * CC + g * GCH + ch) = out;
}

// ---------------- final transpose ----------------
__global__ void transpose_out(const float* __restrict__ fin,
                              float* __restrict__ outp)
{
    __shared__ float s[32][33];
    int b   = blockIdx.z;
    int hw0 = blockIdx.x * 32;
    int c0  = blockIdx.y * 32;
    int tx = threadIdx.x, ty = threadIdx.y;
#pragma unroll
    for (int r = 0; r < 4; r++) {
        int hw = hw0 + ty + 8 * r;
        s[ty + 8 * r][tx] = fin[(size_t)(b * HWW + hw) * CC + c0 + tx];
    }
    __syncthreads();
#pragma unroll
    for (int r = 0; r < 4; r++) {
        int c = c0 + ty + 8 * r;
        outp[(size_t)(b * CC + c) * HWW + hw0 + tx] = s[tx][ty + 8 * r];
    }
}

// --------------------------------------------------------------------------
extern "C" void kernel_launch(void* const* d_in, const int* in_sizes, int n_in,
                              void* d_out, int out_size)
{
    const float* x       = (const float*)d_in[0];
    const float* ln1_g   = (const float*)d_in[1];
    const float* ln1_b   = (const float*)d_in[2];
    const float* vproj_w = (const float*)d_in[3];
    const float* vproj_b = (const float*)d_in[4];
    const float* om_w    = (const float*)d_in[5];
    const float* om_b    = (const float*)d_in[6];
    const float* oproj_w = (const float*)d_in[7];
    const float* oproj_b = (const float*)d_in[8];
    const float* ln2_g   = (const float*)d_in[9];
    const float* ln2_b   = (const float*)d_in[10];
    const float* fc1_w   = (const float*)d_in[11];
    const float* fc1_b   = (const float*)d_in[12];
    const float* fc2_w   = (const float*)d_in[13];
    const float* fc2_b   = (const float*)d_in[14];
    float* outp = (float*)d_out;

    float *xp, *res, *fin, *bvm;
    __half *tn, *vo, *dcn, *ln2o, *hid, *wvm, *wo, *w1, *w2;
    cudaGetSymbolAddress((void**)&xp,  g_xp);
    cudaGetSymbolAddress((void**)&tn,  g_tn);
    cudaGetSymbolAddress((void**)&vo,  g_vo);
    cudaGetSymbolAddress((void**)&dcn, g_dcn);
    cudaGetSymbolAddress((void**)&res, g_res);
    cudaGetSymbolAddress((void**)&ln2o, g_ln2);
    cudaGetSymbolAddress((void**)&hid, g_hid);
    cudaGetSymbolAddress((void**)&fin, g_fin);
    cudaGetSymbolAddress((void**)&wvm, g_wvm);
    cudaGetSymbolAddress((void**)&bvm, g_bvm);
    cudaGetSymbolAddress((void**)&wo,  g_wo);
    cudaGetSymbolAddress((void**)&w1,  g_w1);
    cudaGetSymbolAddress((void**)&w2,  g_w2);

    static int attr_done = 0;
    if (!attr_done) {
        cudaFuncSetAttribute(gemm_mma<0, 1>, cudaFuncAttributeMaxDynamicSharedMemorySize, GEMM_SMEM_BYTES);
        cudaFuncSetAttribute(gemm_mma<1, 1>, cudaFuncAttributeMaxDynamicSharedMemorySize, GEMM_SMEM_BYTES);
        cudaFuncSetAttribute(gemm_mma<2, 0>, cudaFuncAttributeMaxDynamicSharedMemorySize, GEMM_SMEM_BYTES);
        attr_done = 1;
    }

    dim3 tb(32, 8);
    // 0. all weight transposes + bias combine, one launch
    transpose_all<<<1573, tb>>>(vproj_w, om_w, oproj_w, fc1_w, fc2_w,
                                vproj_b, om_b, wvm, wo, w1, w2, bvm);
    // 1. transpose + LN1
    ln1_kernel<<<NTOK / 8, 256>>>(x, ln1_g, ln1_b, xp, tn);
    // 2. vo = tn @ [vproj|om] + b   (fp16 out, stride VOCP)
    gemm_mma<0, 1><<<dim3(NTOK / 128, 6), 256, GEMM_SMEM_BYTES>>>(tn, wvm, bvm, nullptr, vo, VOC, VOCP, CC);
    // 3. DCN sampling (4 tokens/block)
    dcn_kernel<<<NTOK / 4, 192>>>(vo, dcn);
    // 4. res = xp + dcn @ oproj_w + b  (fp32 out)
    gemm_mma<2, 0><<<dim3(NTOK / 128, 3), 256, GEMM_SMEM_BYTES>>>(dcn, wo, oproj_b, xp, res, CC, CC, CC);
    // 5. LN2 (fp16 out)
    ln2_kernel<<<NTOK / 8, 256>>>(res, ln2_g, ln2_b, ln2o);
    // 6. hid = gelu(ln2o @ fc1_w + b)  (fp16 out)
    gemm_mma<1, 1><<<dim3(NTOK / 128, HID / 128), 256, GEMM_SMEM_BYTES>>>(ln2o, w1, fc1_b, nullptr, hid, HID, HID, CC);
    // 7. fin = res + hid @ fc2_w + b   (fp32 out)
    gemm_mma<2, 0><<<dim3(NTOK / 128, 3), 256, GEMM_SMEM_BYTES>>>(hid, w2, fc2_b, res, fin, CC, CC, HID);
    // 8. transpose back
    transpose_out<<<dim3(HWW / 32, CC / 32, BB), tb>>>(fin, outp);
}

// round 16
// speedup vs baseline: 1.6999x; 1.0131x over previous
#include <cuda_runtime.h>
#include <cuda_fp16.h>
#include <math.h>
#include <stdint.h>

#define BB   4
#define CC   384
#define HH   56
#define WW   56
#define HWW  3136
#define NTOK 12544
#define GG   12
#define GCH  32
#define KK2  9
#define OMC  324
#define HID  1536
#define EPSV 1e-5f
#define VOC  708          // valid width: val(384) + om(324)
#define VOCP 712          // padded row stride (16B-aligned rows)

// ---------------- scratch (device globals; no allocation) ----------------
__device__ float  g_xp [NTOK * CC];
__device__ __half g_tn [NTOK * CC];
__device__ __half g_vo [NTOK * VOCP];    // val | om combined, fp16, padded stride
__device__ __half g_dcn[NTOK * CC];
__device__ float  g_res[NTOK * CC];
__device__ __half g_ln2[NTOK * CC];
__device__ __half g_hid[NTOK * HID];
// transposed weights [N,K] row-major, fp16 (zero-init where never written)
__device__ __half g_wvm[768 * CC];       // vproj^T rows 0..383, om^T rows 384..707
__device__ float  g_bvm[768];            // combined bias
__device__ __half g_wo [CC * CC];
__device__ __half g_w1 [HID * CC];
__device__ __half g_w2 [CC * HID];

// ===================== helpers =====================
__device__ __forceinline__ uint32_t smem_u32(const void* p) {
    uint32_t a;
    asm("{ .reg .u64 t; cvta.to.shared.u64 t, %1; cvt.u32.u64 %0, t; }"
        : "=r"(a) : "l"(p));
    return a;
}
#define CP16(dst, src) \
    asm volatile("cp.async.ca.shared.global [%0], [%1], 16;" \
                 :: "r"(dst), "l"(src))
#define CP_COMMIT() asm volatile("cp.async.commit_group;")
#define CP_WAIT1()  asm volatile("cp.async.wait_group 1;")
#define CP_WAIT0()  asm volatile("cp.async.wait_group 0;")

#define MMA_F16(d, a, b) \
    asm volatile("mma.sync.aligned.m16n8k16.row.col.f32.f16.f16.f32 " \
        "{%0,%1,%2,%3}, {%4,%5,%6,%7}, {%8,%9}, {%0,%1,%2,%3};" \
        : "+f"((d)[0]), "+f"((d)[1]), "+f"((d)[2]), "+f"((d)[3]) \
        : "r"((a)[0]), "r"((a)[1]), "r"((a)[2]), "r"((a)[3]), \
          "r"((b)[0]), "r"((b)[1]))

#define LDSM4(r0, r1, r2, r3, addr) \
    asm volatile("ldmatrix.sync.aligned.m8n8.x4.shared.b16 {%0,%1,%2,%3}, [%4];" \
        : "=r"(r0), "=r"(r1), "=r"(r2), "=r"(r3) : "r"(addr))

// ===================== mma.sync fp16 GEMM (fp32 accum) =====================
// EPI: 0=+bias ; 1=+bias+GELU ; 2=+bias+Add
// OUTH: fp16 output.  OUTT: fp32 output scattered to (B,C,H,W).
#define TSTRH 40
#define T_HALFS (128 * TSTRH)
#define GEMM_SMEM_BYTES ((6 * T_HALFS) * 2)         // 61440 B

template <int EPI, int OUTH, int OUTT>
__global__ __launch_bounds__(256, 2) void gemm_mma(
    const __half* __restrict__ A, const __half* __restrict__ Wt,
    const float* __restrict__ bias, const float* __restrict__ Add,
    void* __restrict__ OutV, int Nn, int ldo, int K)
{
    extern __shared__ __half dynh[];
    __half* Asb = dynh;
    __half* Bsb = dynh + 3 * T_HALFS;
    float*  OutF = (float*)OutV;
    __half* OutH = (__half*)OutV;

    const int tid  = threadIdx.x;
    const int lane = tid & 31, warp = tid >> 5;
    const int wm = (warp >> 2) * 64, wn = (warp & 3) * 32;
    const int g4 = lane >> 2, tg = lane & 3;
    const int m0 = blockIdx.x * 128, n0 = blockIdx.y * 128;

    const int lrow = lane & 15;
    const int lkof = (lane >> 4) * 8;
    const int bnof = (lane >> 4) * 8 + (lane & 7);
    const int bkof = ((lane >> 3) & 1) * 8;

    const int r = tid & 127;
    const int q = tid >> 7;

    float acc[4][4][4];
#pragma unroll
    for (int a = 0; a < 4; a++)
#pragma unroll
        for (int b = 0; b < 4; b++)
#pragma unroll
            for (int c = 0; c < 4; c++) acc[a][b][c] = 0.f;

    const int nkc = K >> 5;
    const __half* srcA = A  + (size_t)(m0 + r) * K + q * 8;
    const __half* srcB = Wt + (size_t)(n0 + r) * K + q * 8;

#define ISSUE(kc, bufi) do {                                                  \
        int _k0 = (kc) << 5;                                                  \
        __half* _As = Asb + (bufi) * T_HALFS + r * TSTRH + q * 8;             \
        __half* _Bs = Bsb + (bufi) * T_HALFS + r * TSTRH + q * 8;             \
        CP16(smem_u32(_As),      srcA + _k0);                                 \
        CP16(smem_u32(_As + 16), srcA + _k0 + 16);                            \
        CP16(smem_u32(_Bs),      srcB + _k0);                                 \
        CP16(smem_u32(_Bs + 16), srcB + _k0 + 16);                            \
        CP_COMMIT();                                                          \
    } while (0)

    ISSUE(0, 0);
    ISSUE(1, 1);

    int buf = 0;
    for (int kc = 0; kc < nkc; kc++) {
        if (kc + 2 < nkc) CP_WAIT1(); else CP_WAIT0();
        __syncthreads();
        if (kc + 2 < nkc) {
            int nb = kc + 2 - ((kc + 2) / 3) * 3;
            ISSUE(kc + 2, nb);
        }
        const __half* As = Asb + buf * T_HALFS;
        const __half* Bs = Bsb + buf * T_HALFS;

#pragma unroll
        for (int s = 0; s < 2; s++) {
            uint32_t af[4][4], bf[4][2];
#pragma unroll
            for (int mt = 0; mt < 4; mt++) {
                uint32_t ad = smem_u32(As + (wm + mt * 16 + lrow) * TSTRH + s * 16 + lkof);
                LDSM4(af[mt][0], af[mt][1], af[mt][2], af[mt][3], ad);
            }
#pragma unroll
            for (int p = 0; p < 2; p++) {
                uint32_t ad = smem_u32(Bs + (wn + p * 16 + bnof) * TSTRH + s * 16 + bkof);
                LDSM4(bf[2 * p][0], bf[2 * p][1], bf[2 * p + 1][0], bf[2 * p + 1][1], ad);
            }
#pragma unroll
            for (int mt = 0; mt < 4; mt++)
#pragma unroll
                for (int nt = 0; nt < 4; nt++)
                    MMA_F16(acc[mt][nt], af[mt], bf[nt]);
        }
        buf++; if (buf == 3) buf = 0;
    }
#undef ISSUE

#pragma unroll
    for (int mt = 0; mt < 4; mt++) {
        int row = m0 + wm + mt * 16 + g4;
        int bA = 0, hwA = 0, bB = 0, hwB = 0;
        if (OUTT) {
            bA = row / HWW;        hwA = row - bA * HWW;
            bB = (row + 8) / HWW;  hwB = (row + 8) - bB * HWW;
        }
#pragma unroll
        for (int nt = 0; nt < 4; nt++) {
            int col = n0 + wn + nt * 8 + tg * 2;
            if (col < Nn) {
                float b0 = __ldg(&bias[col]), b1 = __ldg(&bias[col + 1]);
                float v0 = acc[mt][nt][0] + b0;
                float v1 = acc[mt][nt][1] + b1;
                float v2 = acc[mt][nt][2] + b0;
                float v3 = acc[mt][nt][3] + b1;
                if (EPI == 1) {
                    v0 = 0.5f * v0 * (1.f + erff(v0 * 0.70710678118654752f));
                    v1 = 0.5f * v1 * (1.f + erff(v1 * 0.70710678118654752f));
                    v2 = 0.5f * v2 * (1.f + erff(v2 * 0.70710678118654752f));
                    v3 = 0.5f * v3 * (1.f + erff(v3 * 0.70710678118654752f));
                }
                if (EPI == 2) {
                    v0 += Add[(size_t)row * ldo + col];
                    v1 += Add[(size_t)row * ldo + col + 1];
                    v2 += Add[(size_t)(row + 8) * ldo + col];
                    v3 += Add[(size_t)(row + 8) * ldo + col + 1];
                }
                if (OUTT) {
                    float* oA = OutF + (size_t)bA * CC * HWW + hwA;
                    float* oB = OutF + (size_t)bB * CC * HWW + hwB;
                    oA[(size_t)col * HWW]       = v0;
                    oA[(size_t)(col + 1) * HWW] = v1;
                    oB[(size_t)col * HWW]       = v2;
                    oB[(size_t)(col + 1) * HWW] = v3;
                } else if (OUTH) {
                    *reinterpret_cast<__half2*>(OutH + (size_t)row * ldo + col)       = __floats2half2_rn(v0, v1);
                    *reinterpret_cast<__half2*>(OutH + (size_t)(row + 8) * ldo + col) = __floats2half2_rn(v2, v3);
                } else {
                    *reinterpret_cast<float2*>(OutF + (size_t)row * ldo + col)       = make_float2(v0, v1);
                    *reinterpret_cast<float2*>(OutF + (size_t)(row + 8) * ldo + col) = make_float2(v2, v3);
                }
            }
        }
    }
}

// ---------------- one-shot weight prep: all transposes + bias ------------
__global__ void transpose_all(
    const float* __restrict__ vproj_w, const float* __restrict__ om_w,
    const float* __restrict__ oproj_w, const float* __restrict__ fc1_w,
    const float* __restrict__ fc2_w,
    const float* __restrict__ vproj_b, const float* __restrict__ om_b,
    __half* __restrict__ wvm, __half* __restrict__ wo,
    __half* __restrict__ w1, __half* __restrict__ w2,
    float* __restrict__ bvm)
{
    __shared__ float s[32][33];
    int t = blockIdx.x;
    int tx = threadIdx.x, ty = threadIdx.y;
    int tid = ty * 32 + tx;

    if (t == 1572) {
        for (int i = tid; i < 768; i += 256)
            bvm[i] = (i < CC) ? vproj_b[i] : ((i < VOC) ? om_b[i - CC] : 0.f);
        return;
    }

    const float* src; __half* dst;
    int Kdim, Ndim, ntiles_n, rowoff, dstK;
    if (t < 144)       { src = vproj_w; dst = wvm; Kdim = CC;  Ndim = CC;  ntiles_n = 12; rowoff = 0;   dstK = CC;  }
    else if (t < 276)  { t -= 144;  src = om_w;   dst = wvm; Kdim = CC;  Ndim = OMC; ntiles_n = 11; rowoff = CC;  dstK = CC;  }
    else if (t < 420)  { t -= 276;  src = oproj_w; dst = wo;  Kdim = CC;  Ndim = CC;  ntiles_n = 12; rowoff = 0;   dstK = CC;  }
    else if (t < 996)  { t -= 420;  src = fc1_w;  dst = w1;  Kdim = CC;  Ndim = HID; ntiles_n = 48; rowoff = 0;   dstK = CC;  }
    else               { t -= 996;  src = fc2_w;  dst = w2;  Kdim = HID; Ndim = CC;  ntiles_n = 12; rowoff = 0;   dstK = HID; }

    int n0 = (t % ntiles_n) * 32;
    int k0 = (t / ntiles_n) * 32;

#pragma unroll
    for (int r = 0; r < 4; r++) {
        int k = k0 + ty + 8 * r, n = n0 + tx;
        s[ty + 8 * r][tx] = (k < Kdim && n < Ndim) ? src[(size_t)k * Ndim + n] : 0.f;
    }
    __syncthreads();
#pragma unroll
    for (int r = 0; r < 4; r++) {
        int n = n0 + ty + 8 * r, k = k0 + tx;
        if (n < Ndim && k < Kdim)
            dst[(size_t)(n + rowoff) * dstK + k] = __float2half(s[tx][ty + 8 * r]);
    }
}

// ---------------- LN1: transpose x + layernorm (tn -> fp16) ----------------
__global__ void ln1_kernel(const float* __restrict__ x,
                           const float* __restrict__ gam,
                           const float* __restrict__ bet,
                           float* __restrict__ xp, __half* __restrict__ tn)
{
    int warp = (blockIdx.x * blockDim.x + threadIdx.x) >> 5;
    if (warp >= NTOK) return;
    int lane = threadIdx.x & 31;
    int b  = warp / HWW;
    int hw = warp - b * HWW;
    const float* xb = x + (size_t)b * CC * HWW + hw;

    float v[12];
#pragma unroll
    for (int i = 0; i < 12; i++) v[i] = xb[(size_t)(lane + 32 * i) * HWW];
    float s = 0.f;
#pragma unroll
    for (int i = 0; i < 12; i++) s += v[i];
#pragma unroll
    for (int o = 16; o; o >>= 1) s += __shfl_xor_sync(0xffffffffu, s, o);
    float mu = s * (1.0f / CC);
    float q = 0.f;
#pragma unroll
    for (int i = 0; i < 12; i++) { float d = v[i] - mu; q += d * d; }
#pragma unroll
    for (int o = 16; o; o >>= 1) q += __shfl_xor_sync(0xffffffffu, q, o);
    float rs = rsqrtf(q * (1.0f / CC) + EPSV);
    size_t base = (size_t)warp * CC;
#pragma unroll
    for (int i = 0; i < 12; i++) {
        int c = lane + 32 * i;
        xp[base + c] = v[i];
        tn[base + c] = __float2half((v[i] - mu) * rs * gam[c] + bet[c]);
    }
}

// ---------------- LN2 (out -> fp16) ----------------
__global__ void ln2_kernel(const float* __restrict__ res,
                           const float* __restrict__ gam,
                           const float* __restrict__ bet,
                           __half* __restrict__ outp)
{
    int warp = (blockIdx.x * blockDim.x + threadIdx.x) >> 5;
    if (warp >= NTOK) return;
    int lane = threadIdx.x & 31;
    size_t base = (size_t)warp * CC;
    float v[12];
#pragma unroll
    for (int i = 0; i < 12; i++) v[i] = res[base + lane + 32 * i];
    float s = 0.f;
#pragma unroll
    for (int i = 0; i < 12; i++) s += v[i];
#pragma unroll
    for (int o = 16; o; o >>= 1) s += __shfl_xor_sync(0xffffffffu, s, o);
    float mu = s * (1.0f / CC);
    float q = 0.f;
#pragma unroll
    for (int i = 0; i < 12; i++) { float d = v[i] - mu; q += d * d; }
#pragma unroll
    for (int o = 16; o; o >>= 1) q += __shfl_xor_sync(0xffffffffu, q, o);
    float rs = rsqrtf(q * (1.0f / CC) + EPSV);
#pragma unroll
    for (int i = 0; i < 12; i++) {
        int c = lane + 32 * i;
        outp[base + c] = __float2half((v[i] - mu) * rs * gam[c] + bet[c]);
    }
}

// ---------------- DCNv4 sampling: 4 tokens/block, 48 thr/token -----------
__global__ __launch_bounds__(192) void dcn_kernel(
    const __half* __restrict__ vo,
    __half* __restrict__ outp)
{
    __shared__ float s_om[4][OMC];
    const int n0 = blockIdx.x * 4;
    const int tid = threadIdx.x;
    for (int i = tid; i < 4 * OMC; i += 192) {
        int t = i / OMC, c = i - t * OMC;
        s_om[t][c] = __half2float(vo[(size_t)(n0 + t) * VOCP + CC + c]);
    }
    __syncthreads();

    const int sub = tid / 48, tt = tid - sub * 48;
    const int n = n0 + sub;
    const int g = tt >> 2;
    const int ch = (tt & 3) * 8;
    const int b = n / HWW;
    const int hw = n - b * HWW;
    const int ii = hw / WW;
    const int jj = hw - ii * WW;

    const float* omb = s_om[sub] + g * 27;
    const __half* vb = vo + (size_t)b * HWW * VOCP + g * GCH + ch;

    float a0 = 0.f, a1 = 0.f, a2 = 0.f, a3 = 0.f;
    float a4 = 0.f, a5 = 0.f, a6 = 0.f, a7 = 0.f;
#pragma unroll
    for (int k = 0; k < KK2; k++) {
        float dx = omb[2 * k];
        float dy = omb[2 * k + 1];
        float mk = omb[18 + k];
        float px = (float)jj + (float)(k % 3 - 1) + dx;
        float py = (float)ii + (float)(k / 3 - 1) + dy;
        float x0f = floorf(px), y0f = floorf(py);
        float tx = px - x0f, ty = py - y0f;
        int x0 = (int)x0f, y0 = (int)y0f;
        int x1 = x0 + 1,   y1 = y0 + 1;
        bool vx0 = (x0 >= 0) & (x0 < WW);
        bool vx1 = (x1 >= 0) & (x1 < WW);
        bool vy0 = (y0 >= 0) & (y0 < HH);
        bool vy1 = (y1 >= 0) & (y1 < HH);
        int row0 = y0 * (WW * VOCP), row1 = row0 + WW * VOCP;

        float w00 = (1.f - tx) * (1.f - ty) * mk;
        float w01 = tx * (1.f - ty) * mk;
        float w10 = (1.f - tx) * ty * mk;
        float w11 = tx * ty * mk;

#define GATH(cond, off, wgt) do {                                             \
        if (cond) {                                                           \
            uint4 u = __ldg(reinterpret_cast<const uint4*>(vb + (off)));      \
            float2 f0 = __half22float2(*reinterpret_cast<__half2*>(&u.x));    \
            float2 f1 = __half22float2(*reinterpret_cast<__half2*>(&u.y));    \
            float2 f2 = __half22float2(*reinterpret_cast<__half2*>(&u.z));    \
            float2 f3 = __half22float2(*reinterpret_cast<__half2*>(&u.w));    \
            a0 += f0.x * (wgt); a1 += f0.y * (wgt);                           \
            a2 += f1.x * (wgt); a3 += f1.y * (wgt);                           \
            a4 += f2.x * (wgt); a5 += f2.y * (wgt);                           \
            a6 += f3.x * (wgt); a7 += f3.y * (wgt);                           \
        }                                                                     \
    } while (0)
        GATH(vy0 && vx0, row0 + x0 * VOCP, w00);
        GATH(vy0 && vx1, row0 + x1 * VOCP, w01);
        GATH(vy1 && vx0, row1 + x0 * VOCP, w10);
        GATH(vy1 && vx1, row1 + x1 * VOCP, w11);
#undef GATH
    }
    uint4 out;
    *reinterpret_cast<__half2*>(&out.x) = __floats2half2_rn(a0, a1);
    *reinterpret_cast<__half2*>(&out.y) = __floats2half2_rn(a2, a3);
    *reinterpret_cast<__half2*>(&out.z) = __floats2half2_rn(a4, a5);
    *reinterpret_cast<__half2*>(&out.w) = __floats2half2_rn(a6, a7);
    *reinterpret_cast<uint4*>(outp + (size_t)n * CC + g * GCH + ch) = out;
}

// --------------------------------------------------------------------------
extern "C" void kernel_launch(void* const* d_in, const int* in_sizes, int n_in,
                              void* d_out, int out_size)
{
    const float* x       = (const float*)d_in[0];
    const float* ln1_g   = (const float*)d_in[1];
    const float* ln1_b   = (const float*)d_in[2];
    const float* vproj_w = (const float*)d_in[3];
    const float* vproj_b = (const float*)d_in[4];
    const float* om_w    = (const float*)d_in[5];
    const float* om_b    = (const float*)d_in[6];
    const float* oproj_w = (const float*)d_in[7];
    const float* oproj_b = (const float*)d_in[8];
    const float* ln2_g   = (const float*)d_in[9];
    const float* ln2_b   = (const float*)d_in[10];
    const float* fc1_w   = (const float*)d_in[11];
    const float* fc1_b   = (const float*)d_in[12];
    const float* fc2_w   = (const float*)d_in[13];
    const float* fc2_b   = (const float*)d_in[14];
    float* outp = (float*)d_out;

    float *xp, *res, *bvm;
    __half *tn, *vo, *dcn, *ln2o, *hid, *wvm, *wo, *w1, *w2;
    cudaGetSymbolAddress((void**)&xp,  g_xp);
    cudaGetSymbolAddress((void**)&tn,  g_tn);
    cudaGetSymbolAddress((void**)&vo,  g_vo);
    cudaGetSymbolAddress((void**)&dcn, g_dcn);
    cudaGetSymbolAddress((void**)&res, g_res);
    cudaGetSymbolAddress((void**)&ln2o, g_ln2);
    cudaGetSymbolAddress((void**)&hid, g_hid);
    cudaGetSymbolAddress((void**)&wvm, g_wvm);
    cudaGetSymbolAddress((void**)&bvm, g_bvm);
    cudaGetSymbolAddress((void**)&wo,  g_wo);
    cudaGetSymbolAddress((void**)&w1,  g_w1);
    cudaGetSymbolAddress((void**)&w2,  g_w2);

    static int attr_done = 0;
    if (!attr_done) {
        cudaFuncSetAttribute(gemm_mma<0, 1, 0>, cudaFuncAttributeMaxDynamicSharedMemorySize, GEMM_SMEM_BYTES);
        cudaFuncSetAttribute(gemm_mma<1, 1, 0>, cudaFuncAttributeMaxDynamicSharedMemorySize, GEMM_SMEM_BYTES);
        cudaFuncSetAttribute(gemm_mma<2, 0, 0>, cudaFuncAttributeMaxDynamicSharedMemorySize, GEMM_SMEM_BYTES);
        cudaFuncSetAttribute(gemm_mma<2, 0, 1>, cudaFuncAttributeMaxDynamicSharedMemorySize, GEMM_SMEM_BYTES);
        attr_done = 1;
    }

    dim3 tb(32, 8);
    // 0. all weight transposes + bias combine, one launch
    transpose_all<<<1573, tb>>>(vproj_w, om_w, oproj_w, fc1_w, fc2_w,
                                vproj_b, om_b, wvm, wo, w1, w2, bvm);
    // 1. transpose + LN1
    ln1_kernel<<<NTOK / 8, 256>>>(x, ln1_g, ln1_b, xp, tn);
    // 2. vo = tn @ [vproj|om] + b   (fp16 out, stride VOCP)
    gemm_mma<0, 1, 0><<<dim3(NTOK / 128, 6), 256, GEMM_SMEM_BYTES>>>(tn, wvm, bvm, nullptr, vo, VOC, VOCP, CC);
    // 3. DCN sampling (4 tokens/block)
    dcn_kernel<<<NTOK / 4, 192>>>(vo, dcn);
    // 4. res = xp + dcn @ oproj_w + b  (fp32 out)
    gemm_mma<2, 0, 0><<<dim3(NTOK / 128, 3), 256, GEMM_SMEM_BYTES>>>(dcn, wo, oproj_b, xp, res, CC, CC, CC);
    // 5. LN2 (fp16 out)
    ln2_kernel<<<NTOK / 8, 256>>>(res, ln2_g, ln2_b, ln2o);
    // 6. hid = gelu(ln2o @ fc1_w + b)  (fp16 out)
    gemm_mma<1, 1, 0><<<dim3(NTOK / 128, HID / 128), 256, GEMM_SMEM_BYTES>>>(ln2o, w1, fc1_b, nullptr, hid, HID, HID, CC);
    // 7. out(B,C,H,W) = transpose(res + hid @ fc2_w + b)  — fused epilogue
    gemm_mma<2, 0, 1><<<dim3(NTOK / 128, 3), 256, GEMM_SMEM_BYTES>>>(hid, w2, fc2_b, res, outp, CC, CC, HID);
}

// round 17
// speedup vs baseline: 1.7713x; 1.0420x over previous
#include <cuda_runtime.h>
#include <cuda_fp16.h>
#include <math.h>
#include <stdint.h>

#define BB   4
#define CC   384
#define HH   56
#define WW   56
#define HWW  3136
#define NTOK 12544
#define GG   12
#define GCH  32
#define KK2  9
#define OMC  324
#define HID  1536
#define EPSV 1e-5f
#define VOC  708          // valid width: val(384) + om(324)
#define VOCP 712          // padded row stride (16B-aligned rows)

// ---------------- scratch (device globals; no allocation) ----------------
__device__ float  g_xp [NTOK * CC];
__device__ __half g_tn [NTOK * CC];
__device__ __half g_vo [NTOK * VOCP];    // val | om combined, fp16, padded stride
__device__ __half g_dcn[NTOK * CC];
__device__ float  g_res[NTOK * CC];
__device__ __half g_ln2[NTOK * CC];
__device__ __half g_hid[NTOK * HID];
// transposed weights [N,K] row-major, fp16 (zero-init where never written)
__device__ __half g_wvm[768 * CC];       // vproj^T rows 0..383, om^T rows 384..707
__device__ float  g_bvm[768];            // combined bias
__device__ __half g_wo [CC * CC];
__device__ __half g_w1 [HID * CC];
__device__ __half g_w2 [CC * HID];

// ===================== helpers =====================
__device__ __forceinline__ uint32_t smem_u32(const void* p) {
    uint32_t a;
    asm("{ .reg .u64 t; cvta.to.shared.u64 t, %1; cvt.u32.u64 %0, t; }"
        : "=r"(a) : "l"(p));
    return a;
}
#define CP16(dst, src) \
    asm volatile("cp.async.ca.shared.global [%0], [%1], 16;" \
                 :: "r"(dst), "l"(src))
#define CP_COMMIT() asm volatile("cp.async.commit_group;")
#define CP_WAIT1()  asm volatile("cp.async.wait_group 1;")
#define CP_WAIT0()  asm volatile("cp.async.wait_group 0;")

#define MMA_F16(d, a, b) \
    asm volatile("mma.sync.aligned.m16n8k16.row.col.f32.f16.f16.f32 " \
        "{%0,%1,%2,%3}, {%4,%5,%6,%7}, {%8,%9}, {%0,%1,%2,%3};" \
        : "+f"((d)[0]), "+f"((d)[1]), "+f"((d)[2]), "+f"((d)[3]) \
        : "r"((a)[0]), "r"((a)[1]), "r"((a)[2]), "r"((a)[3]), \
          "r"((b)[0]), "r"((b)[1]))

#define LDSM4(r0, r1, r2, r3, addr) \
    asm volatile("ldmatrix.sync.aligned.m8n8.x4.shared.b16 {%0,%1,%2,%3}, [%4];" \
        : "=r"(r0), "=r"(r1), "=r"(r2), "=r"(r3) : "r"(addr))

// ===================== mma.sync fp16 GEMM (fp32 accum) =====================
// EPI: 0=+bias ; 1=+bias+GELU ; 2=+bias+Add
// OUTH: fp16 output.  OUTT: fp32 output scattered to (B,C,H,W).
#define TSTRH 40
#define T_HALFS (128 * TSTRH)
#define GEMM_SMEM_BYTES ((6 * T_HALFS) * 2)         // 61440 B

template <int EPI, int OUTH, int OUTT>
__global__ __launch_bounds__(256, 2) void gemm_mma(
    const __half* __restrict__ A, const __half* __restrict__ Wt,
    const float* __restrict__ bias, const float* __restrict__ Add,
    void* __restrict__ OutV, int Nn, int ldo, int K)
{
    extern __shared__ __half dynh[];
    __half* Asb = dynh;
    __half* Bsb = dynh + 3 * T_HALFS;
    float*  OutF = (float*)OutV;
    __half* OutH = (__half*)OutV;

    const int tid  = threadIdx.x;
    const int lane = tid & 31, warp = tid >> 5;
    const int wm = (warp >> 2) * 64, wn = (warp & 3) * 32;
    const int g4 = lane >> 2, tg = lane & 3;
    const int m0 = blockIdx.x * 128, n0 = blockIdx.y * 128;

    const int lrow = lane & 15;
    const int lkof = (lane >> 4) * 8;
    const int bnof = (lane >> 4) * 8 + (lane & 7);
    const int bkof = ((lane >> 3) & 1) * 8;

    const int r = tid & 127;
    const int q = tid >> 7;

    float acc[4][4][4];
#pragma unroll
    for (int a = 0; a < 4; a++)
#pragma unroll
        for (int b = 0; b < 4; b++)
#pragma unroll
            for (int c = 0; c < 4; c++) acc[a][b][c] = 0.f;

    const int nkc = K >> 5;
    const __half* srcA = A  + (size_t)(m0 + r) * K + q * 8;
    const __half* srcB = Wt + (size_t)(n0 + r) * K + q * 8;

#define ISSUE(kc, bufi) do {                                                  \
        int _k0 = (kc) << 5;                                                  \
        __half* _As = Asb + (bufi) * T_HALFS + r * TSTRH + q * 8;             \
        __half* _Bs = Bsb + (bufi) * T_HALFS + r * TSTRH + q * 8;             \
        CP16(smem_u32(_As),      srcA + _k0);                                 \
        CP16(smem_u32(_As + 16), srcA + _k0 + 16);                            \
        CP16(smem_u32(_Bs),      srcB + _k0);                                 \
        CP16(smem_u32(_Bs + 16), srcB + _k0 + 16);                            \
        CP_COMMIT();                                                          \
    } while (0)

    ISSUE(0, 0);
    ISSUE(1, 1);

    int buf = 0;
    for (int kc = 0; kc < nkc; kc++) {
        if (kc + 2 < nkc) CP_WAIT1(); else CP_WAIT0();
        __syncthreads();
        if (kc + 2 < nkc) {
            int nb = kc + 2 - ((kc + 2) / 3) * 3;
            ISSUE(kc + 2, nb);
        }
        const __half* As = Asb + buf * T_HALFS;
        const __half* Bs = Bsb + buf * T_HALFS;

#pragma unroll
        for (int s = 0; s < 2; s++) {
            uint32_t af[4][4], bf[4][2];
#pragma unroll
            for (int mt = 0; mt < 4; mt++) {
                uint32_t ad = smem_u32(As + (wm + mt * 16 + lrow) * TSTRH + s * 16 + lkof);
                LDSM4(af[mt][0], af[mt][1], af[mt][2], af[mt][3], ad);
            }
#pragma unroll
            for (int p = 0; p < 2; p++) {
                uint32_t ad = smem_u32(Bs + (wn + p * 16 + bnof) * TSTRH + s * 16 + bkof);
                LDSM4(bf[2 * p][0], bf[2 * p][1], bf[2 * p + 1][0], bf[2 * p + 1][1], ad);
            }
#pragma unroll
            for (int mt = 0; mt < 4; mt++)
#pragma unroll
                for (int nt = 0; nt < 4; nt++)
                    MMA_F16(acc[mt][nt], af[mt], bf[nt]);
        }
        buf++; if (buf == 3) buf = 0;
    }
#undef ISSUE

#pragma unroll
    for (int mt = 0; mt < 4; mt++) {
        int row = m0 + wm + mt * 16 + g4;
        int bA = 0, hwA = 0, bB = 0, hwB = 0;
        if (OUTT) {
            bA = row / HWW;        hwA = row - bA * HWW;
            bB = (row + 8) / HWW;  hwB = (row + 8) - bB * HWW;
        }
#pragma unroll
        for (int nt = 0; nt < 4; nt++) {
            int col = n0 + wn + nt * 8 + tg * 2;
            if (col < Nn) {
                float b0 = __ldg(&bias[col]), b1 = __ldg(&bias[col + 1]);
                float v0 = acc[mt][nt][0] + b0;
                float v1 = acc[mt][nt][1] + b1;
                float v2 = acc[mt][nt][2] + b0;
                float v3 = acc[mt][nt][3] + b1;
                if (EPI == 1) {
                    v0 = 0.5f * v0 * (1.f + erff(v0 * 0.70710678118654752f));
                    v1 = 0.5f * v1 * (1.f + erff(v1 * 0.70710678118654752f));
                    v2 = 0.5f * v2 * (1.f + erff(v2 * 0.70710678118654752f));
                    v3 = 0.5f * v3 * (1.f + erff(v3 * 0.70710678118654752f));
                }
                if (EPI == 2) {
                    v0 += Add[(size_t)row * ldo + col];
                    v1 += Add[(size_t)row * ldo + col + 1];
                    v2 += Add[(size_t)(row + 8) * ldo + col];
                    v3 += Add[(size_t)(row + 8) * ldo + col + 1];
                }
                if (OUTT) {
                    float* oA = OutF + (size_t)bA * CC * HWW + hwA;
                    float* oB = OutF + (size_t)bB * CC * HWW + hwB;
                    oA[(size_t)col * HWW]       = v0;
                    oA[(size_t)(col + 1) * HWW] = v1;
                    oB[(size_t)col * HWW]       = v2;
                    oB[(size_t)(col + 1) * HWW] = v3;
                } else if (OUTH) {
                    *reinterpret_cast<__half2*>(OutH + (size_t)row * ldo + col)       = __floats2half2_rn(v0, v1);
                    *reinterpret_cast<__half2*>(OutH + (size_t)(row + 8) * ldo + col) = __floats2half2_rn(v2, v3);
                } else {
                    *reinterpret_cast<float2*>(OutF + (size_t)row * ldo + col)       = make_float2(v0, v1);
                    *reinterpret_cast<float2*>(OutF + (size_t)(row + 8) * ldo + col) = make_float2(v2, v3);
                }
            }
        }
    }
}

// ---------------- one-shot weight prep: all transposes + bias ------------
__global__ void transpose_all(
    const float* __restrict__ vproj_w, const float* __restrict__ om_w,
    const float* __restrict__ oproj_w, const float* __restrict__ fc1_w,
    const float* __restrict__ fc2_w,
    const float* __restrict__ vproj_b, const float* __restrict__ om_b,
    __half* __restrict__ wvm, __half* __restrict__ wo,
    __half* __restrict__ w1, __half* __restrict__ w2,
    float* __restrict__ bvm)
{
    __shared__ float s[32][33];
    int t = blockIdx.x;
    int tx = threadIdx.x, ty = threadIdx.y;
    int tid = ty * 32 + tx;

    if (t == 1572) {
        for (int i = tid; i < 768; i += 256)
            bvm[i] = (i < CC) ? vproj_b[i] : ((i < VOC) ? om_b[i - CC] : 0.f);
        return;
    }

    const float* src; __half* dst;
    int Kdim, Ndim, ntiles_n, rowoff, dstK;
    if (t < 144)       { src = vproj_w; dst = wvm; Kdim = CC;  Ndim = CC;  ntiles_n = 12; rowoff = 0;   dstK = CC;  }
    else if (t < 276)  { t -= 144;  src = om_w;   dst = wvm; Kdim = CC;  Ndim = OMC; ntiles_n = 11; rowoff = CC;  dstK = CC;  }
    else if (t < 420)  { t -= 276;  src = oproj_w; dst = wo;  Kdim = CC;  Ndim = CC;  ntiles_n = 12; rowoff = 0;   dstK = CC;  }
    else if (t < 996)  { t -= 420;  src = fc1_w;  dst = w1;  Kdim = CC;  Ndim = HID; ntiles_n = 48; rowoff = 0;   dstK = CC;  }
    else               { t -= 996;  src = fc2_w;  dst = w2;  Kdim = HID; Ndim = CC;  ntiles_n = 12; rowoff = 0;   dstK = HID; }

    int n0 = (t % ntiles_n) * 32;
    int k0 = (t / ntiles_n) * 32;

#pragma unroll
    for (int r = 0; r < 4; r++) {
        int k = k0 + ty + 8 * r, n = n0 + tx;
        s[ty + 8 * r][tx] = (k < Kdim && n < Ndim) ? src[(size_t)k * Ndim + n] : 0.f;
    }
    __syncthreads();
#pragma unroll
    for (int r = 0; r < 4; r++) {
        int n = n0 + ty + 8 * r, k = k0 + tx;
        if (n < Ndim && k < Kdim)
            dst[(size_t)(n + rowoff) * dstK + k] = __float2half(s[tx][ty + 8 * r]);
    }
}

// ---------------- LN1: tiled transpose + layernorm (tn -> fp16) -----------
// block = (b, 16 tokens); stage 384x16 tile in smem with coalesced reads.
__global__ __launch_bounds__(256) void ln1_kernel(
    const float* __restrict__ x,
    const float* __restrict__ gam,
    const float* __restrict__ bet,
    float* __restrict__ xp, __half* __restrict__ tn)
{
    __shared__ float s[CC][17];
    const int b   = blockIdx.y;
    const int hw0 = blockIdx.x * 16;
    const int tid = threadIdx.x;
    const int tx = tid & 15, ty = tid >> 4;   // ty 0..15

    const float* xb = x + (size_t)b * CC * HWW + hw0 + tx;
#pragma unroll
    for (int j = 0; j < 24; j++) {
        int c = ty + 16 * j;
        s[c][tx] = xb[(size_t)c * HWW];
    }
    __syncthreads();

    const int w = tid >> 5, lane = tid & 31;
#pragma unroll
    for (int ti = 0; ti < 2; ti++) {
        int t = w * 2 + ti;
        float v[12];
#pragma unroll
        for (int i = 0; i < 12; i++) v[i] = s[lane + 32 * i][t];
        float sm = 0.f;
#pragma unroll
        for (int i = 0; i < 12; i++) sm += v[i];
#pragma unroll
        for (int o = 16; o; o >>= 1) sm += __shfl_xor_sync(0xffffffffu, sm, o);
        float mu = sm * (1.0f / CC);
        float q = 0.f;
#pragma unroll
        for (int i = 0; i < 12; i++) { float d = v[i] - mu; q += d * d; }
#pragma unroll
        for (int o = 16; o; o >>= 1) q += __shfl_xor_sync(0xffffffffu, q, o);
        float rs = rsqrtf(q * (1.0f / CC) + EPSV);

        size_t base = ((size_t)b * HWW + hw0 + t) * CC;
#pragma unroll
        for (int i = 0; i < 12; i++) {
            int c = lane + 32 * i;
            xp[base + c] = v[i];
            tn[base + c] = __float2half((v[i] - mu) * rs * gam[c] + bet[c]);
        }
    }
}

// ---------------- LN2 (out -> fp16) ----------------
__global__ void ln2_kernel(const float* __restrict__ res,
                           const float* __restrict__ gam,
                           const float* __restrict__ bet,
                           __half* __restrict__ outp)
{
    int warp = (blockIdx.x * blockDim.x + threadIdx.x) >> 5;
    if (warp >= NTOK) return;
    int lane = threadIdx.x & 31;
    size_t base = (size_t)warp * CC;
    float v[12];
#pragma unroll
    for (int i = 0; i < 12; i++) v[i] = res[base + lane + 32 * i];
    float s = 0.f;
#pragma unroll
    for (int i = 0; i < 12; i++) s += v[i];
#pragma unroll
    for (int o = 16; o; o >>= 1) s += __shfl_xor_sync(0xffffffffu, s, o);
    float mu = s * (1.0f / CC);
    float q = 0.f;
#pragma unroll
    for (int i = 0; i < 12; i++) { float d = v[i] - mu; q += d * d; }
#pragma unroll
    for (int o = 16; o; o >>= 1) q += __shfl_xor_sync(0xffffffffu, q, o);
    float rs = rsqrtf(q * (1.0f / CC) + EPSV);
#pragma unroll
    for (int i = 0; i < 12; i++) {
        int c = lane + 32 * i;
        outp[base + c] = __float2half((v[i] - mu) * rs * gam[c] + bet[c]);
    }
}

// ---------------- DCNv4 sampling: 4 tokens/block, 48 thr/token -----------
__global__ __launch_bounds__(192) void dcn_kernel(
    const __half* __restrict__ vo,
    __half* __restrict__ outp)
{
    __shared__ float s_om[4][OMC];
    const int n0 = blockIdx.x * 4;
    const int tid = threadIdx.x;
    for (int i = tid; i < 4 * OMC; i += 192) {
        int t = i / OMC, c = i - t * OMC;
        s_om[t][c] = __half2float(vo[(size_t)(n0 + t) * VOCP + CC + c]);
    }
    __syncthreads();

    const int sub = tid / 48, tt = tid - sub * 48;
    const int n = n0 + sub;
    const int g = tt >> 2;
    const int ch = (tt & 3) * 8;
    const int b = n / HWW;
    const int hw = n - b * HWW;
    const int ii = hw / WW;
    const int jj = hw - ii * WW;

    const float* omb = s_om[sub] + g * 27;
    const __half* vb = vo + (size_t)b * HWW * VOCP + g * GCH + ch;

    float a0 = 0.f, a1 = 0.f, a2 = 0.f, a3 = 0.f;
    float a4 = 0.f, a5 = 0.f, a6 = 0.f, a7 = 0.f;
#pragma unroll
    for (int k = 0; k < KK2; k++) {
        float dx = omb[2 * k];
        float dy = omb[2 * k + 1];
        float mk = omb[18 + k];
        float px = (float)jj + (float)(k % 3 - 1) + dx;
        float py = (float)ii + (float)(k / 3 - 1) + dy;
        float x0f = floorf(px), y0f = floorf(py);
        float tx = px - x0f, ty = py - y0f;
        int x0 = (int)x0f, y0 = (int)y0f;
        int x1 = x0 + 1,   y1 = y0 + 1;
        bool vx0 = (x0 >= 0) & (x0 < WW);
        bool vx1 = (x1 >= 0) & (x1 < WW);
        bool vy0 = (y0 >= 0) & (y0 < HH);
        bool vy1 = (y1 >= 0) & (y1 < HH);
        int row0 = y0 * (WW * VOCP), row1 = row0 + WW * VOCP;

        float w00 = (1.f - tx) * (1.f - ty) * mk;
        float w01 = tx * (1.f - ty) * mk;
        float w10 = (1.f - tx) * ty * mk;
        float w11 = tx * ty * mk;

#define GATH(cond, off, wgt) do {                                             \
        if (cond) {                                                           \
            uint4 u = __ldg(reinterpret_cast<const uint4*>(vb + (off)));      \
            float2 f0 = __half22float2(*reinterpret_cast<__half2*>(&u.x));    \
            float2 f1 = __half22float2(*reinterpret_cast<__half2*>(&u.y));    \
            float2 f2 = __half22float2(*reinterpret_cast<__half2*>(&u.z));    \
            float2 f3 = __half22float2(*reinterpret_cast<__half2*>(&u.w));    \
            a0 += f0.x * (wgt); a1 += f0.y * (wgt);                           \
            a2 += f1.x * (wgt); a3 += f1.y * (wgt);                           \
            a4 += f2.x * (wgt); a5 += f2.y * (wgt);                           \
            a6 += f3.x * (wgt); a7 += f3.y * (wgt);                           \
        }                                                                     \
    } while (0)
        GATH(vy0 && vx0, row0 + x0 * VOCP, w00);
        GATH(vy0 && vx1, row0 + x1 * VOCP, w01);
        GATH(vy1 && vx0, row1 + x0 * VOCP, w10);
        GATH(vy1 && vx1, row1 + x1 * VOCP, w11);
#undef GATH
    }
    uint4 out;
    *reinterpret_cast<__half2*>(&out.x) = __floats2half2_rn(a0, a1);
    *reinterpret_cast<__half2*>(&out.y) = __floats2half2_rn(a2, a3);
    *reinterpret_cast<__half2*>(&out.z) = __floats2half2_rn(a4, a5);
    *reinterpret_cast<__half2*>(&out.w) = __floats2half2_rn(a6, a7);
    *reinterpret_cast<uint4*>(outp + (size_t)n * CC + g * GCH + ch) = out;
}

// --------------------------------------------------------------------------
extern "C" void kernel_launch(void* const* d_in, const int* in_sizes, int n_in,
                              void* d_out, int out_size)
{
    const float* x       = (const float*)d_in[0];
    const float* ln1_g   = (const float*)d_in[1];
    const float* ln1_b   = (const float*)d_in[2];
    const float* vproj_w = (const float*)d_in[3];
    const float* vproj_b = (const float*)d_in[4];
    const float* om_w    = (const float*)d_in[5];
    const float* om_b    = (const float*)d_in[6];
    const float* oproj_w = (const float*)d_in[7];
    const float* oproj_b = (const float*)d_in[8];
    const float* ln2_g   = (const float*)d_in[9];
    const float* ln2_b   = (const float*)d_in[10];
    const float* fc1_w   = (const float*)d_in[11];
    const float* fc1_b   = (const float*)d_in[12];
    const float* fc2_w   = (const float*)d_in[13];
    const float* fc2_b   = (const float*)d_in[14];
    float* outp = (float*)d_out;

    float *xp, *res, *bvm;
    __half *tn, *vo, *dcn, *ln2o, *hid, *wvm, *wo, *w1, *w2;
    cudaGetSymbolAddress((void**)&xp,  g_xp);
    cudaGetSymbolAddress((void**)&tn,  g_tn);
    cudaGetSymbolAddress((void**)&vo,  g_vo);
    cudaGetSymbolAddress((void**)&dcn, g_dcn);
    cudaGetSymbolAddress((void**)&res, g_res);
    cudaGetSymbolAddress((void**)&ln2o, g_ln2);
    cudaGetSymbolAddress((void**)&hid, g_hid);
    cudaGetSymbolAddress((void**)&wvm, g_wvm);
    cudaGetSymbolAddress((void**)&bvm, g_bvm);
    cudaGetSymbolAddress((void**)&wo,  g_wo);
    cudaGetSymbolAddress((void**)&w1,  g_w1);
    cudaGetSymbolAddress((void**)&w2,  g_w2);

    static int attr_done = 0;
    if (!attr_done) {
        cudaFuncSetAttribute(gemm_mma<0, 1, 0>, cudaFuncAttributeMaxDynamicSharedMemorySize, GEMM_SMEM_BYTES);
        cudaFuncSetAttribute(gemm_mma<1, 1, 0>, cudaFuncAttributeMaxDynamicSharedMemorySize, GEMM_SMEM_BYTES);
        cudaFuncSetAttribute(gemm_mma<2, 0, 0>, cudaFuncAttributeMaxDynamicSharedMemorySize, GEMM_SMEM_BYTES);
        cudaFuncSetAttribute(gemm_mma<2, 0, 1>, cudaFuncAttributeMaxDynamicSharedMemorySize, GEMM_SMEM_BYTES);
        attr_done = 1;
    }

    dim3 tb(32, 8);
    // 0. all weight transposes + bias combine, one launch
    transpose_all<<<1573, tb>>>(vproj_w, om_w, oproj_w, fc1_w, fc2_w,
                                vproj_b, om_b, wvm, wo, w1, w2, bvm);
    // 1. tiled transpose + LN1
    ln1_kernel<<<dim3(HWW / 16, BB), 256>>>(x, ln1_g, ln1_b, xp, tn);
    // 2. vo = tn @ [vproj|om] + b   (fp16 out, stride VOCP)
    gemm_mma<0, 1, 0><<<dim3(NTOK / 128, 6), 256, GEMM_SMEM_BYTES>>>(tn, wvm, bvm, nullptr, vo, VOC, VOCP, CC);
    // 3. DCN sampling (4 tokens/block)
    dcn_kernel<<<NTOK / 4, 192>>>(vo, dcn);
    // 4. res = xp + dcn @ oproj_w + b  (fp32 out)
    gemm_mma<2, 0, 0><<<dim3(NTOK / 128, 3), 256, GEMM_SMEM_BYTES>>>(dcn, wo, oproj_b, xp, res, CC, CC, CC);
    // 5. LN2 (fp16 out)
    ln2_kernel<<<NTOK / 8, 256>>>(res, ln2_g, ln2_b, ln2o);
    // 6. hid = gelu(ln2o @ fc1_w + b)  (fp16 out)
    gemm_mma<1, 1, 0><<<dim3(NTOK / 128, HID / 128), 256, GEMM_SMEM_BYTES>>>(ln2o, w1, fc1_b, nullptr, hid, HID, HID, CC);
    // 7. out(B,C,H,W) = transpose(res + hid @ fc2_w + b)  — fused epilogue
    gemm_mma<2, 0, 1><<<dim3(NTOK / 128, 3), 256, GEMM_SMEM_BYTES>>>(hid, w2, fc2_b, res, outp, CC, CC, HID);
}